// round 3
// baseline (speedup 1.0000x reference)
#include <cuda_runtime.h>
#include <cuda_fp16.h>
#include <cstdint>

// Problem constants
#define BB   64
#define NN   100
#define DD   2048
#define NRH  16
#define PP   (BB*NN)        // 6400

// ---------------------------------------------------------------------------
// Scratch (__device__ globals; no allocations allowed)
// ---------------------------------------------------------------------------
__device__ __half g_Ah[PP * 2048];               // 26.2 MB  A in fp16
__device__ __half g_Wh[2048 * 2048];             // 8.4 MB   W^T fused [n][k] (Wk|Wq)
__device__ float  g_K [PP * 1024];               // 26.2 MB
__device__ float  g_Q [PP * 1024];               // 26.2 MB
__device__ float  g_GW[BB * NRH * NN * NN];      // 41 MB gate weights (NOT log)

__device__ __forceinline__ uint32_t smem_u32(const void* p) {
    uint32_t a;
    asm("{ .reg .u64 t; cvta.to.shared.u64 t, %1; cvt.u32.u64 %0, t; }" : "=r"(a) : "l"(p));
    return a;
}

#define CP_ASYNC16(dst, src) \
    asm volatile("cp.async.cg.shared.global [%0], [%1], 16;" :: "r"(dst), "l"(src) : "memory")
#define CP_COMMIT() asm volatile("cp.async.commit_group;" ::: "memory")
#define CP_WAIT1()  asm volatile("cp.async.wait_group 1;" ::: "memory")
#define CP_WAIT0()  asm volatile("cp.async.wait_group 0;" ::: "memory")

#define LDSM_X4(r0, r1, r2, r3, addr) \
    asm volatile("ldmatrix.sync.aligned.m8n8.x4.shared.b16 {%0,%1,%2,%3}, [%4];" \
        : "=r"(r0), "=r"(r1), "=r"(r2), "=r"(r3) : "r"(addr))

__device__ __forceinline__ void mma_fp16(float& c0, float& c1, float& c2, float& c3,
                                         uint32_t a0, uint32_t a1, uint32_t a2, uint32_t a3,
                                         uint32_t b0, uint32_t b1)
{
    asm volatile(
        "mma.sync.aligned.m16n8k16.row.col.f32.f16.f16.f32 "
        "{%0,%1,%2,%3}, {%4,%5,%6,%7}, {%8,%9}, {%0,%1,%2,%3};"
        : "+f"(c0), "+f"(c1), "+f"(c2), "+f"(c3)
        : "r"(a0), "r"(a1), "r"(a2), "r"(a3), "r"(b0), "r"(b1));
}

// ---------------------------------------------------------------------------
// Prep A: fp32 -> fp16
// ---------------------------------------------------------------------------
__global__ __launch_bounds__(256)
void prepA_kernel(const float* __restrict__ A)
{
    int id = blockIdx.x * 256 + threadIdx.x;       // one float4 each
    float4 v = *(const float4*)(A + id * 4);
    __half h[4] = {__float2half_rn(v.x), __float2half_rn(v.y),
                   __float2half_rn(v.z), __float2half_rn(v.w)};
    *(uint2*)(g_Ah + id * 4) = *(uint2*)h;
}

// ---------------------------------------------------------------------------
// Prep W: Wh[n][k] = fp16(Wsrc[k][n']);  n<1024 -> Wk else Wq.  32x32 tiles.
// ---------------------------------------------------------------------------
__global__ __launch_bounds__(256)
void prepW_kernel(const float* __restrict__ Wk, const float* __restrict__ Wq)
{
    __shared__ float t[32][33];
    const int k0 = blockIdx.x * 32, n0 = blockIdx.y * 32;
    const float* src = (n0 < 1024) ? Wk : Wq;
    const int nc0 = (n0 < 1024) ? n0 : n0 - 1024;
    const int tx = threadIdx.x & 31, ty = threadIdx.x >> 5;
    for (int r = ty; r < 32; r += 8)
        t[r][tx] = src[(k0 + r) * 1024 + nc0 + tx];
    __syncthreads();
    for (int r = ty; r < 32; r += 8)
        g_Wh[(size_t)(n0 + r) * 2048 + k0 + tx] = __float2half_rn(t[tx][r]);
}

// ---------------------------------------------------------------------------
// fp16 GEMM: C[6400 x 2048] = Ah @ Wh^T (+bias)  ->  g_K | g_Q
// Tiles BM=128 BN=128 BK=32; 3-stage cp.async; 8 warps (2m x 4n), warp 64x32.
// smem rows padded to 40 halves (80B): conflict-free LDSM, 16B-aligned cp.async
// ---------------------------------------------------------------------------
#define ROWH 40
#define ROWB 80
#define TILE_HALVES (128 * ROWH)                   // 5120 per operand
#define STAGE_HALVES (2 * TILE_HALVES)             // 10240 (20480 B)
#define NSTAGE 3
#define NITER  64                                  // 2048 / 32
#define GEMM_SMEM (NSTAGE * STAGE_HALVES * 2)      // 61440 B

__global__ __launch_bounds__(256, 1)
void gemm_kernel(const float* __restrict__ bk, const float* __restrict__ bq)
{
    extern __shared__ __align__(16) __half sm[];

    const int tid  = threadIdx.x;
    const int wid  = tid >> 5, lane = tid & 31;
    const int wm   = wid & 1,  wn   = wid >> 1;       // 2 x 4 warp grid
    const int g    = lane >> 2, t4  = lane & 3;
    const int mbase = blockIdx.y * 128;
    const int nbase = blockIdx.x * 128;

    const uint32_t sbase = smem_u32(sm);

    // per-thread load coords: A/B tile = 128 rows x 4 x 16B chunks, 2 per thread
    const int ra0 = tid >> 2,        ca0 = (tid & 3);         // chunks 0..255
    const int ra1 = (tid + 256) >> 2, ca1 = (tid & 3);        // chunks 256..511
    const __half* gA = g_Ah + (size_t)(mbase + 0) * 2048;
    const __half* gB = g_Wh + (size_t)(nbase + 0) * 2048;

    auto load_stage = [&](int it, int s) {
        const int k0 = it * 32;
        const uint32_t sA = sbase + s * STAGE_HALVES * 2;
        const uint32_t sB = sA + TILE_HALVES * 2;
        CP_ASYNC16(sA + ra0 * ROWB + ca0 * 16,
                   (const char*)(gA + (size_t)ra0 * 2048 + k0 + ca0 * 8));
        CP_ASYNC16(sA + ra1 * ROWB + ca1 * 16,
                   (const char*)(gA + (size_t)ra1 * 2048 + k0 + ca1 * 8));
        CP_ASYNC16(sB + ra0 * ROWB + ca0 * 16,
                   (const char*)(gB + (size_t)ra0 * 2048 + k0 + ca0 * 8));
        CP_ASYNC16(sB + ra1 * ROWB + ca1 * 16,
                   (const char*)(gB + (size_t)ra1 * 2048 + k0 + ca1 * 8));
        CP_COMMIT();
    };

    float c[4][4][4];
    #pragma unroll
    for (int i = 0; i < 4; i++)
        #pragma unroll
        for (int j = 0; j < 4; j++)
            #pragma unroll
            for (int k = 0; k < 4; k++) c[i][j][k] = 0.f;

    load_stage(0, 0);
    load_stage(1, 1);

    // LDSM lane addressing (see fragment layout analysis):
    // A: row = frag_m0 + (lane&15), byte = ks*32 + (lane>>4)*16
    const int arow = (lane & 15);
    const int abyt = (lane >> 4) << 4;
    // B: row = frag_n0 + (lane&7) + ((lane>>4)<<3), byte = ks*32 + ((lane>>3)&1)*16
    const int brow = (lane & 7) + ((lane >> 4) << 3);
    const int bbyt = ((lane >> 3) & 1) << 4;

    for (int it = 0; it < NITER; ++it) {
        const int s = it % NSTAGE;
        if (it == NITER - 1) { CP_WAIT0(); } else { CP_WAIT1(); }
        __syncthreads();

        const uint32_t sA = sbase + s * STAGE_HALVES * 2;
        const uint32_t sB = sA + TILE_HALVES * 2;

        #pragma unroll
        for (int ks = 0; ks < 2; ks++) {
            uint32_t af[4][4], bfr[2][4];
            #pragma unroll
            for (int fm = 0; fm < 4; fm++) {
                uint32_t ad = sA + (wm * 64 + fm * 16 + arow) * ROWB + ks * 32 + abyt;
                LDSM_X4(af[fm][0], af[fm][1], af[fm][2], af[fm][3], ad);
            }
            #pragma unroll
            for (int f2 = 0; f2 < 2; f2++) {
                uint32_t bd = sB + (wn * 32 + f2 * 16 + brow) * ROWB + ks * 32 + bbyt;
                LDSM_X4(bfr[f2][0], bfr[f2][1], bfr[f2][2], bfr[f2][3], bd);
            }
            #pragma unroll
            for (int fm = 0; fm < 4; fm++)
                #pragma unroll
                for (int fn = 0; fn < 4; fn++) {
                    uint32_t b0 = bfr[fn >> 1][(fn & 1) * 2 + 0];
                    uint32_t b1 = bfr[fn >> 1][(fn & 1) * 2 + 1];
                    mma_fp16(c[fm][fn][0], c[fm][fn][1], c[fm][fn][2], c[fm][fn][3],
                             af[fm][0], af[fm][1], af[fm][2], af[fm][3], b0, b1);
                }
        }

        __syncthreads();
        if (it + 2 < NITER) load_stage(it + 2, (it + 2) % NSTAGE);
    }

    // epilogue: +bias, write to g_K (cols<1024) or g_Q
    const bool side = (nbase >= 1024);
    const float* bsrc = side ? bq : bk;
    float* outp = side ? g_Q : g_K;
    const int colb = side ? (nbase - 1024) : nbase;

    #pragma unroll
    for (int fm = 0; fm < 4; fm++) {
        int row = mbase + wm * 64 + fm * 16 + g;
        #pragma unroll
        for (int fn = 0; fn < 4; fn++) {
            int col = colb + wn * 32 + fn * 8 + t4 * 2;
            float b0 = bsrc[col], b1 = bsrc[col + 1];
            *(float2*)(outp + (size_t)row * 1024 + col) =
                make_float2(c[fm][fn][0] + b0, c[fm][fn][1] + b1);
            *(float2*)(outp + (size_t)(row + 8) * 1024 + col) =
                make_float2(c[fm][fn][2] + b0, c[fm][fn][3] + b1);
        }
    }
}

// ---------------------------------------------------------------------------
// Gate: gw[b][h][i][j] = max(g_row . Wg[:,h] + bg[h], 1e-6)   (no log!)
// ---------------------------------------------------------------------------
__global__ __launch_bounds__(128)
void gate_kernel(const float* __restrict__ gf,
                 const float* __restrict__ Wg, const float* __restrict__ bg)
{
    __shared__ float sW[64 * 16];
    __shared__ float sb[16];
    __shared__ float sg[128 * 65];

    const int tid = threadIdx.x;
    for (int i = tid; i < 1024; i += 128) sW[i] = Wg[i];
    if (tid < 16) sb[tid] = bg[tid];

    const int base = blockIdx.x * 128;
    for (int v = tid; v < 2048; v += 128) {
        int r = v >> 4, cc = (v & 15) << 2;
        float4 x = *(const float4*)(gf + (base + r) * 64 + cc);
        sg[r*65+cc] = x.x; sg[r*65+cc+1] = x.y; sg[r*65+cc+2] = x.z; sg[r*65+cc+3] = x.w;
    }
    __syncthreads();

    float acc[16];
    #pragma unroll
    for (int r = 0; r < 16; r++) acc[r] = sb[r];
    #pragma unroll 4
    for (int k = 0; k < 64; k++) {
        float gv = sg[tid * 65 + k];
        #pragma unroll
        for (int r = 0; r < 16; r++) acc[r] += gv * sW[k * 16 + r];
    }

    const int row = base + tid;
    const int b   = row / 10000;
    const int rem = row - b * 10000;
    float* op = g_GW + b * 160000 + rem;
    #pragma unroll
    for (int r = 0; r < 16; r++)
        op[r * 10000] = fmaxf(acc[r], 1e-6f);
}

// ---------------------------------------------------------------------------
// Attention per (b,h): S=K.Q^T/8; e=gw*exp(S-colmax); out=V^T e /colsum *ws+bs
// ---------------------------------------------------------------------------
#define ATTN_SMEM_FLOATS (6500 + 6500 + 10100 + 128 + 10000 + 13200)

__global__ __launch_bounds__(256)
void attn_kernel(const float* __restrict__ a,
                 const float* __restrict__ wsp, const float* __restrict__ bsp,
                 float* __restrict__ out)
{
    extern __shared__ float smf[];
    float* sK   = smf;              // 100*65
    float* sQ   = sK + 6500;        // 100*65
    float* sS   = sQ + 6500;        // 100*101
    float* sInv = sS + 10100;       // 128
    float* sGW  = sInv + 128;       // 100*100
    float* sV   = sGW + 10000;      // 100*132

    const int h = blockIdx.x, b = blockIdx.y;
    const int tid = threadIdx.x;

    // V load first (independent of K/Q)
    for (int v = tid; v < 3200; v += 256) {
        int i = v >> 5, cc = (v & 31) << 2;
        *(float4*)(sV + i * 132 + cc) =
            *(const float4*)(a + (size_t)(b * 100 + i) * 2048 + h * 128 + cc);
    }

    const float* Kg = g_K + (size_t)(b * 100) * 1024 + h * 64;
    const float* Qg = g_Q + (size_t)(b * 100) * 1024 + h * 64;
    for (int v = tid; v < 1600; v += 256) {
        int i = v >> 4, cc = (v & 15) << 2;
        float4 kv = *(const float4*)(Kg + (size_t)i * 1024 + cc);
        float4 qv = *(const float4*)(Qg + (size_t)i * 1024 + cc);
        sK[i*65+cc] = kv.x; sK[i*65+cc+1] = kv.y; sK[i*65+cc+2] = kv.z; sK[i*65+cc+3] = kv.w;
        sQ[i*65+cc] = qv.x; sQ[i*65+cc+1] = qv.y; sQ[i*65+cc+2] = qv.z; sQ[i*65+cc+3] = qv.w;
    }
    __syncthreads();

    // S tiles 4x4; stage gw into smem
    const float* GW = g_GW + (size_t)(b * 16 + h) * 10000;
    for (int tt = tid; tt < 625; tt += 256) {
        int i0 = (tt % 25) << 2;
        int j0 = (tt / 25) << 2;
        float acc[4][4] = {};
        #pragma unroll 4
        for (int d = 0; d < 64; d++) {
            float kv[4], qv[4];
            #pragma unroll
            for (int ii = 0; ii < 4; ii++) kv[ii] = sK[(i0 + ii) * 65 + d];
            #pragma unroll
            for (int jj = 0; jj < 4; jj++) qv[jj] = sQ[(j0 + jj) * 65 + d];
            #pragma unroll
            for (int ii = 0; ii < 4; ii++)
                #pragma unroll
                for (int jj = 0; jj < 4; jj++) acc[ii][jj] += kv[ii] * qv[jj];
        }
        #pragma unroll
        for (int ii = 0; ii < 4; ii++)
            #pragma unroll
            for (int jj = 0; jj < 4; jj++) {
                sS [(i0 + ii) * 101 + j0 + jj] = acc[ii][jj] * 0.125f;
                sGW[(i0 + ii) * 100 + j0 + jj] = GW[(i0 + ii) * 100 + j0 + jj];
            }
    }
    __syncthreads();

    // column softmax over i (thread j): e = gw * exp(s - m); keep 1/sum
    if (tid < 100) {
        float m = -1e30f;
        for (int i = 0; i < 100; i++) m = fmaxf(m, sS[i * 101 + tid]);
        float s = 0.f;
        for (int i = 0; i < 100; i++) {
            float e = sGW[i * 100 + tid] * __expf(sS[i * 101 + tid] - m);
            sS[i * 101 + tid] = e;
            s += e;
        }
        sInv[tid] = 1.f / s;
    }
    __syncthreads();

    // PV: out[j][d] = inv[j] * sum_i e[i][j] * V[i][d]; tiles 4j x 8d
    const float wsc = *wsp;
    const float bsc = *bsp;
    for (int tt = tid; tt < 400; tt += 256) {
        int d0 = (tt & 15) << 3;
        int j0 = (tt >> 4) << 2;
        float acc[4][8] = {};
        for (int i = 0; i < 100; i++) {
            float4 v0 = *(const float4*)(sV + i * 132 + d0);
            float4 v1 = *(const float4*)(sV + i * 132 + d0 + 4);
            float vv[8] = {v0.x, v0.y, v0.z, v0.w, v1.x, v1.y, v1.z, v1.w};
            float p[4];
            #pragma unroll
            for (int jj = 0; jj < 4; jj++) p[jj] = sS[i * 101 + j0 + jj];
            #pragma unroll
            for (int jj = 0; jj < 4; jj++)
                #pragma unroll
                for (int dd = 0; dd < 8; dd++) acc[jj][dd] += p[jj] * vv[dd];
        }
        #pragma unroll
        for (int jj = 0; jj < 4; jj++) {
            float sc = sInv[j0 + jj] * wsc;
            float* op = out + (size_t)(b * 100 + j0 + jj) * 2048 + h * 128 + d0;
            #pragma unroll
            for (int dd = 0; dd < 8; dd++) op[dd] = acc[jj][dd] * sc + bsc;
        }
    }
}

// ---------------------------------------------------------------------------
// Launch. Inputs: a_features, g_features, split, rel_pair_counts,
// W_g, b_g, W_K, b_K, W_Q, b_Q, w_s, b_s
// ---------------------------------------------------------------------------
extern "C" void kernel_launch(void* const* d_in, const int* in_sizes, int n_in,
                              void* d_out, int out_size)
{
    (void)in_sizes; (void)n_in; (void)out_size;
    const float* a  = (const float*)d_in[0];
    const float* gf = (const float*)d_in[1];
    const float* Wg = (const float*)d_in[4];
    const float* bg = (const float*)d_in[5];
    const float* Wk = (const float*)d_in[6];
    const float* bk = (const float*)d_in[7];
    const float* Wq = (const float*)d_in[8];
    const float* bq = (const float*)d_in[9];
    const float* ws = (const float*)d_in[10];
    const float* bs = (const float*)d_in[11];
    float* out = (float*)d_out;

    cudaFuncSetAttribute(gemm_kernel, cudaFuncAttributeMaxDynamicSharedMemorySize, GEMM_SMEM);
    cudaFuncSetAttribute(attn_kernel, cudaFuncAttributeMaxDynamicSharedMemorySize,
                         ATTN_SMEM_FLOATS * (int)sizeof(float));

    prepA_kernel<<<PP * 2048 / 1024, 256>>>(a);
    prepW_kernel<<<dim3(64, 64), 256>>>(Wk, Wq);
    gate_kernel<<<5000, 128>>>(gf, Wg, bg);
    gemm_kernel<<<dim3(16, 50), 256, GEMM_SMEM>>>(bk, bq);
    attn_kernel<<<dim3(16, 64), 256, ATTN_SMEM_FLOATS * sizeof(float)>>>(a, ws, bs, out);
}

// round 4
// speedup vs baseline: 1.6933x; 1.6933x over previous
#include <cuda_runtime.h>
#include <cuda_fp16.h>
#include <cstdint>

// Problem constants
#define BB   64
#define NN   100
#define DD   2048
#define NRH  16
#define PP   (BB*NN)        // 6400

// ---------------------------------------------------------------------------
// Scratch (__device__ globals; no allocations allowed)
// ---------------------------------------------------------------------------
__device__ __half g_Ah[PP * 2048];               // 26.2 MB  A in fp16
__device__ __half g_Wh[2048 * 2048];             // 8.4 MB   W^T fused [n][k] (Wk|Wq)
__device__ float  g_K [PP * 1024];               // 26.2 MB
__device__ float  g_Q [PP * 1024];               // 26.2 MB
__device__ float  g_GW[BB * NRH * NN * NN];      // 41 MB gate weights (NOT log)

__device__ __forceinline__ uint32_t smem_u32(const void* p) {
    uint32_t a;
    asm("{ .reg .u64 t; cvta.to.shared.u64 t, %1; cvt.u32.u64 %0, t; }" : "=r"(a) : "l"(p));
    return a;
}

#define CP_ASYNC16(dst, src) \
    asm volatile("cp.async.cg.shared.global [%0], [%1], 16;" :: "r"(dst), "l"(src) : "memory")
#define CP_COMMIT() asm volatile("cp.async.commit_group;" ::: "memory")
#define CP_WAIT1()  asm volatile("cp.async.wait_group 1;" ::: "memory")
#define CP_WAIT0()  asm volatile("cp.async.wait_group 0;" ::: "memory")

#define LDSM_X4(r0, r1, r2, r3, addr) \
    asm volatile("ldmatrix.sync.aligned.m8n8.x4.shared.b16 {%0,%1,%2,%3}, [%4];" \
        : "=r"(r0), "=r"(r1), "=r"(r2), "=r"(r3) : "r"(addr))

__device__ __forceinline__ void mma_fp16(float& c0, float& c1, float& c2, float& c3,
                                         uint32_t a0, uint32_t a1, uint32_t a2, uint32_t a3,
                                         uint32_t b0, uint32_t b1)
{
    asm volatile(
        "mma.sync.aligned.m16n8k16.row.col.f32.f16.f16.f32 "
        "{%0,%1,%2,%3}, {%4,%5,%6,%7}, {%8,%9}, {%0,%1,%2,%3};"
        : "+f"(c0), "+f"(c1), "+f"(c2), "+f"(c3)
        : "r"(a0), "r"(a1), "r"(a2), "r"(a3), "r"(b0), "r"(b1));
}

// ---------------------------------------------------------------------------
// Prep A: fp32 -> fp16
// ---------------------------------------------------------------------------
__global__ __launch_bounds__(256)
void prepA_kernel(const float* __restrict__ A)
{
    int id = blockIdx.x * 256 + threadIdx.x;       // one float4 each
    float4 v = *(const float4*)(A + id * 4);
    __half h[4] = {__float2half_rn(v.x), __float2half_rn(v.y),
                   __float2half_rn(v.z), __float2half_rn(v.w)};
    *(uint2*)(g_Ah + id * 4) = *(uint2*)h;
}

// ---------------------------------------------------------------------------
// Prep W: Wh[n][k] = fp16(Wsrc[k][n']);  n<1024 -> Wk else Wq.  32x32 tiles.
// ---------------------------------------------------------------------------
__global__ __launch_bounds__(256)
void prepW_kernel(const float* __restrict__ Wk, const float* __restrict__ Wq)
{
    __shared__ float t[32][33];
    const int k0 = blockIdx.x * 32, n0 = blockIdx.y * 32;
    const float* src = (n0 < 1024) ? Wk : Wq;
    const int nc0 = (n0 < 1024) ? n0 : n0 - 1024;
    const int tx = threadIdx.x & 31, ty = threadIdx.x >> 5;
    for (int r = ty; r < 32; r += 8)
        t[r][tx] = src[(k0 + r) * 1024 + nc0 + tx];
    __syncthreads();
    for (int r = ty; r < 32; r += 8)
        g_Wh[(size_t)(n0 + r) * 2048 + k0 + tx] = __float2half_rn(t[tx][r]);
}

// ---------------------------------------------------------------------------
// fp16 GEMM: C[6400 x 2048] = Ah @ Wh^T (+bias)  ->  g_K | g_Q
// Tiles BM=128 BN=128 BK=32; 3-stage cp.async; 8 warps (2m x 4n), warp 64x32.
// 2 CTAs/SM (launch_bounds 256,2). ONE barrier per K-iter; loads overlap mma.
// ---------------------------------------------------------------------------
#define ROWH 40
#define ROWB 80
#define TILE_HALVES (128 * ROWH)                   // 5120 per operand
#define STAGE_HALVES (2 * TILE_HALVES)             // 10240 (20480 B)
#define NSTAGE 3
#define NITER  64                                  // 2048 / 32
#define GEMM_SMEM (NSTAGE * STAGE_HALVES * 2)      // 61440 B

__global__ __launch_bounds__(256, 2)
void gemm_kernel(const float* __restrict__ bk, const float* __restrict__ bq)
{
    extern __shared__ __align__(16) __half sm[];

    const int tid  = threadIdx.x;
    const int wid  = tid >> 5, lane = tid & 31;
    const int wm   = wid & 1,  wn   = wid >> 1;       // 2 x 4 warp grid
    const int g    = lane >> 2, t4  = lane & 3;
    const int mbase = blockIdx.y * 128;
    const int nbase = blockIdx.x * 128;

    const uint32_t sbase = smem_u32(sm);

    // per-thread load coords: each tile = 128 rows x 4 x 16B chunks, 2 per thread
    const int ra0 = tid >> 2,         ca0 = (tid & 3);
    const int ra1 = (tid + 256) >> 2, ca1 = (tid & 3);
    const __half* gA = g_Ah + (size_t)mbase * 2048;
    const __half* gB = g_Wh + (size_t)nbase * 2048;

    auto load_stage = [&](int it, int s) {
        const int k0 = it * 32;
        const uint32_t sA = sbase + s * STAGE_HALVES * 2;
        const uint32_t sB = sA + TILE_HALVES * 2;
        CP_ASYNC16(sA + ra0 * ROWB + ca0 * 16,
                   (const char*)(gA + (size_t)ra0 * 2048 + k0 + ca0 * 8));
        CP_ASYNC16(sA + ra1 * ROWB + ca1 * 16,
                   (const char*)(gA + (size_t)ra1 * 2048 + k0 + ca1 * 8));
        CP_ASYNC16(sB + ra0 * ROWB + ca0 * 16,
                   (const char*)(gB + (size_t)ra0 * 2048 + k0 + ca0 * 8));
        CP_ASYNC16(sB + ra1 * ROWB + ca1 * 16,
                   (const char*)(gB + (size_t)ra1 * 2048 + k0 + ca1 * 8));
        CP_COMMIT();
    };

    float c[4][4][4];
    #pragma unroll
    for (int i = 0; i < 4; i++)
        #pragma unroll
        for (int j = 0; j < 4; j++)
            #pragma unroll
            for (int k = 0; k < 4; k++) c[i][j][k] = 0.f;

    load_stage(0, 0);
    load_stage(1, 1);

    // LDSM lane addressing
    const int arow = (lane & 15);
    const int abyt = (lane >> 4) << 4;
    const int brow = (lane & 7) + ((lane >> 4) << 3);
    const int bbyt = ((lane >> 3) & 1) << 4;

    for (int it = 0; it < NITER; ++it) {
        const int s = it % NSTAGE;
        if (it < NITER - 1) { CP_WAIT1(); } else { CP_WAIT0(); }
        __syncthreads();
        // buffer (it+2)%3 was last read in iter it-1; the barrier above proves
        // all warps are past it -> safe to refill now, overlapping the mma below.
        if (it + 2 < NITER) load_stage(it + 2, (it + 2) % NSTAGE);

        const uint32_t sA = sbase + s * STAGE_HALVES * 2;
        const uint32_t sB = sA + TILE_HALVES * 2;

        #pragma unroll
        for (int ks = 0; ks < 2; ks++) {
            uint32_t af[4][4], bfr[2][4];
            #pragma unroll
            for (int fm = 0; fm < 4; fm++) {
                uint32_t ad = sA + (wm * 64 + fm * 16 + arow) * ROWB + ks * 32 + abyt;
                LDSM_X4(af[fm][0], af[fm][1], af[fm][2], af[fm][3], ad);
            }
            #pragma unroll
            for (int f2 = 0; f2 < 2; f2++) {
                uint32_t bd = sB + (wn * 32 + f2 * 16 + brow) * ROWB + ks * 32 + bbyt;
                LDSM_X4(bfr[f2][0], bfr[f2][1], bfr[f2][2], bfr[f2][3], bd);
            }
            #pragma unroll
            for (int fm = 0; fm < 4; fm++)
                #pragma unroll
                for (int fn = 0; fn < 4; fn++) {
                    uint32_t b0 = bfr[fn >> 1][(fn & 1) * 2 + 0];
                    uint32_t b1 = bfr[fn >> 1][(fn & 1) * 2 + 1];
                    mma_fp16(c[fm][fn][0], c[fm][fn][1], c[fm][fn][2], c[fm][fn][3],
                             af[fm][0], af[fm][1], af[fm][2], af[fm][3], b0, b1);
                }
        }
    }

    // epilogue: +bias, write to g_K (cols<1024) or g_Q
    const bool side = (nbase >= 1024);
    const float* bsrc = side ? bq : bk;
    float* outp = side ? g_Q : g_K;
    const int colb = side ? (nbase - 1024) : nbase;

    #pragma unroll
    for (int fm = 0; fm < 4; fm++) {
        int row = mbase + wm * 64 + fm * 16 + g;
        #pragma unroll
        for (int fn = 0; fn < 4; fn++) {
            int col = colb + wn * 32 + fn * 8 + t4 * 2;
            float b0 = bsrc[col], b1 = bsrc[col + 1];
            *(float2*)(outp + (size_t)row * 1024 + col) =
                make_float2(c[fm][fn][0] + b0, c[fm][fn][1] + b1);
            *(float2*)(outp + (size_t)(row + 8) * 1024 + col) =
                make_float2(c[fm][fn][2] + b0, c[fm][fn][3] + b1);
        }
    }
}

// ---------------------------------------------------------------------------
// Gate: gw[b][h][i][j] = max(g_row . Wg[:,h] + bg[h], 1e-6)   (no log!)
// ---------------------------------------------------------------------------
__global__ __launch_bounds__(128)
void gate_kernel(const float* __restrict__ gf,
                 const float* __restrict__ Wg, const float* __restrict__ bg)
{
    __shared__ float sW[64 * 16];
    __shared__ float sb[16];
    __shared__ float sg[128 * 65];

    const int tid = threadIdx.x;
    for (int i = tid; i < 1024; i += 128) sW[i] = Wg[i];
    if (tid < 16) sb[tid] = bg[tid];

    const int base = blockIdx.x * 128;
    for (int v = tid; v < 2048; v += 128) {
        int r = v >> 4, cc = (v & 15) << 2;
        float4 x = *(const float4*)(gf + (base + r) * 64 + cc);
        sg[r*65+cc] = x.x; sg[r*65+cc+1] = x.y; sg[r*65+cc+2] = x.z; sg[r*65+cc+3] = x.w;
    }
    __syncthreads();

    float acc[16];
    #pragma unroll
    for (int r = 0; r < 16; r++) acc[r] = sb[r];
    #pragma unroll 4
    for (int k = 0; k < 64; k++) {
        float gv = sg[tid * 65 + k];
        #pragma unroll
        for (int r = 0; r < 16; r++) acc[r] += gv * sW[k * 16 + r];
    }

    const int row = base + tid;
    const int b   = row / 10000;
    const int rem = row - b * 10000;
    float* op = g_GW + b * 160000 + rem;
    #pragma unroll
    for (int r = 0; r < 16; r++)
        op[r * 10000] = fmaxf(acc[r], 1e-6f);
}

// ---------------------------------------------------------------------------
// Attention per (b,h): S=K.Q^T/8; e=gw*exp(S-colmax); out=V^T e /colsum *ws+bs
// 512 threads. Warp-parallel column softmax.
// ---------------------------------------------------------------------------
#define ATTN_SMEM_FLOATS (6500 + 6500 + 10100 + 128 + 10100 + 13200)

__global__ __launch_bounds__(512)
void attn_kernel(const float* __restrict__ a,
                 const float* __restrict__ wsp, const float* __restrict__ bsp,
                 float* __restrict__ out)
{
    extern __shared__ float smf[];
    float* sK   = smf;              // 100*65
    float* sQ   = sK + 6500;        // 100*65
    float* sS   = sQ + 6500;        // 100*101
    float* sInv = sS + 10100;       // 128
    float* sGW  = sInv + 128;       // 100*101 (padded stride)
    float* sV   = sGW + 10100;      // 100*132

    const int h = blockIdx.x, b = blockIdx.y;
    const int tid = threadIdx.x;
    const int wrp = tid >> 5, lane = tid & 31;

    // V load first (independent of K/Q)
    for (int v = tid; v < 3200; v += 512) {
        int i = v >> 5, cc = (v & 31) << 2;
        *(float4*)(sV + i * 132 + cc) =
            *(const float4*)(a + (size_t)(b * 100 + i) * 2048 + h * 128 + cc);
    }

    // gw stage (coalesced scalar; smem stride 101)
    const float* GW = g_GW + (size_t)(b * 16 + h) * 10000;
    for (int v = tid; v < 10000; v += 512) {
        int i = v / 100, j = v - i * 100;
        sGW[i * 101 + j] = GW[v];
    }

    const float* Kg = g_K + (size_t)(b * 100) * 1024 + h * 64;
    const float* Qg = g_Q + (size_t)(b * 100) * 1024 + h * 64;
    for (int v = tid; v < 1600; v += 512) {
        int i = v >> 4, cc = (v & 15) << 2;
        float4 kv = *(const float4*)(Kg + (size_t)i * 1024 + cc);
        float4 qv = *(const float4*)(Qg + (size_t)i * 1024 + cc);
        sK[i*65+cc] = kv.x; sK[i*65+cc+1] = kv.y; sK[i*65+cc+2] = kv.z; sK[i*65+cc+3] = kv.w;
        sQ[i*65+cc] = qv.x; sQ[i*65+cc+1] = qv.y; sQ[i*65+cc+2] = qv.z; sQ[i*65+cc+3] = qv.w;
    }
    __syncthreads();

    // S tiles 4x4
    for (int tt = tid; tt < 625; tt += 512) {
        int i0 = (tt % 25) << 2;
        int j0 = (tt / 25) << 2;
        float acc[4][4] = {};
        #pragma unroll 4
        for (int d = 0; d < 64; d++) {
            float kv[4], qv[4];
            #pragma unroll
            for (int ii = 0; ii < 4; ii++) kv[ii] = sK[(i0 + ii) * 65 + d];
            #pragma unroll
            for (int jj = 0; jj < 4; jj++) qv[jj] = sQ[(j0 + jj) * 65 + d];
            #pragma unroll
            for (int ii = 0; ii < 4; ii++)
                #pragma unroll
                for (int jj = 0; jj < 4; jj++) acc[ii][jj] += kv[ii] * qv[jj];
        }
        #pragma unroll
        for (int ii = 0; ii < 4; ii++)
            #pragma unroll
            for (int jj = 0; jj < 4; jj++)
                sS[(i0 + ii) * 101 + j0 + jj] = acc[ii][jj] * 0.125f;
    }
    __syncthreads();

    // warp-per-column softmax over i: e = gw * exp(s - m); keep 1/sum
    for (int j = wrp; j < 100; j += 16) {
        float m = -1e30f;
        for (int i = lane; i < 100; i += 32) m = fmaxf(m, sS[i * 101 + j]);
        #pragma unroll
        for (int o = 16; o; o >>= 1) m = fmaxf(m, __shfl_xor_sync(~0u, m, o));
        float s = 0.f;
        for (int i = lane; i < 100; i += 32) {
            float e = sGW[i * 101 + j] * __expf(sS[i * 101 + j] - m);
            sS[i * 101 + j] = e;
            s += e;
        }
        #pragma unroll
        for (int o = 16; o; o >>= 1) s += __shfl_xor_sync(~0u, s, o);
        if (lane == 0) sInv[j] = 1.f / s;
    }
    __syncthreads();

    // PV: out[j][d] = inv[j] * sum_i e[i][j] * V[i][d]; tiles 4j x 8d
    const float wsc = *wsp;
    const float bsc = *bsp;
    for (int tt = tid; tt < 400; tt += 512) {
        int d0 = (tt & 15) << 3;
        int j0 = (tt >> 4) << 2;
        float acc[4][8] = {};
        for (int i = 0; i < 100; i++) {
            float4 v0 = *(const float4*)(sV + i * 132 + d0);
            float4 v1 = *(const float4*)(sV + i * 132 + d0 + 4);
            float vv[8] = {v0.x, v0.y, v0.z, v0.w, v1.x, v1.y, v1.z, v1.w};
            float p[4];
            #pragma unroll
            for (int jj = 0; jj < 4; jj++) p[jj] = sS[i * 101 + j0 + jj];
            #pragma unroll
            for (int jj = 0; jj < 4; jj++)
                #pragma unroll
                for (int dd = 0; dd < 8; dd++) acc[jj][dd] += p[jj] * vv[dd];
        }
        #pragma unroll
        for (int jj = 0; jj < 4; jj++) {
            float sc = sInv[j0 + jj] * wsc;
            float* op = out + (size_t)(b * 100 + j0 + jj) * 2048 + h * 128 + d0;
            #pragma unroll
            for (int dd = 0; dd < 8; dd++) op[dd] = acc[jj][dd] * sc + bsc;
        }
    }
}

// ---------------------------------------------------------------------------
// Launch. Inputs: a_features, g_features, split, rel_pair_counts,
// W_g, b_g, W_K, b_K, W_Q, b_Q, w_s, b_s
// ---------------------------------------------------------------------------
extern "C" void kernel_launch(void* const* d_in, const int* in_sizes, int n_in,
                              void* d_out, int out_size)
{
    (void)in_sizes; (void)n_in; (void)out_size;
    const float* a  = (const float*)d_in[0];
    const float* gf = (const float*)d_in[1];
    const float* Wg = (const float*)d_in[4];
    const float* bg = (const float*)d_in[5];
    const float* Wk = (const float*)d_in[6];
    const float* bk = (const float*)d_in[7];
    const float* Wq = (const float*)d_in[8];
    const float* bq = (const float*)d_in[9];
    const float* ws = (const float*)d_in[10];
    const float* bs = (const float*)d_in[11];
    float* out = (float*)d_out;

    cudaFuncSetAttribute(gemm_kernel, cudaFuncAttributeMaxDynamicSharedMemorySize, GEMM_SMEM);
    cudaFuncSetAttribute(attn_kernel, cudaFuncAttributeMaxDynamicSharedMemorySize,
                         ATTN_SMEM_FLOATS * (int)sizeof(float));

    prepA_kernel<<<PP * 2048 / 1024, 256>>>(a);
    prepW_kernel<<<dim3(64, 64), 256>>>(Wk, Wq);
    gate_kernel<<<5000, 128>>>(gf, Wg, bg);
    gemm_kernel<<<dim3(16, 50), 256, GEMM_SMEM>>>(bk, bq);
    attn_kernel<<<dim3(16, 64), 512, ATTN_SMEM_FLOATS * sizeof(float)>>>(a, ws, bs, out);
}

// round 6
// speedup vs baseline: 2.1782x; 1.2864x over previous
#include <cuda_runtime.h>
#include <cuda_fp16.h>
#include <cstdint>

// Problem constants
#define BB   64
#define NN   100
#define DD   2048
#define NRH  16
#define PP   (BB*NN)        // 6400

#define GW_SCALE 1024.0f    // uniform gate scale; cancels exactly in softmax ratio

// ---------------------------------------------------------------------------
// Scratch (__device__ globals; no allocations allowed)
// ---------------------------------------------------------------------------
__device__ __half g_Ah[PP * 2048];               // 26.2 MB  A in fp16
__device__ __half g_Wh[2048 * 2048];             // 8.4 MB   W^T fused [n][k] (Wk|Wq)
__device__ __half g_Kh[PP * 1024];               // 13.1 MB  K fp16
__device__ __half g_Qh[PP * 1024];               // 13.1 MB  Q fp16
__device__ __half g_GW[BB * NRH * NN * NN];      // 20.5 MB  gw * 1024, fp16

__device__ __forceinline__ uint32_t smem_u32(const void* p) {
    uint32_t a;
    asm("{ .reg .u64 t; cvta.to.shared.u64 t, %1; cvt.u32.u64 %0, t; }" : "=r"(a) : "l"(p));
    return a;
}

#define CP_ASYNC16(dst, src) \
    asm volatile("cp.async.cg.shared.global [%0], [%1], 16;" :: "r"(dst), "l"(src) : "memory")
#define CP_COMMIT() asm volatile("cp.async.commit_group;" ::: "memory")
#define CP_WAIT1()  asm volatile("cp.async.wait_group 1;" ::: "memory")
#define CP_WAIT0()  asm volatile("cp.async.wait_group 0;" ::: "memory")

#define LDSM_X4(r0, r1, r2, r3, addr) \
    asm volatile("ldmatrix.sync.aligned.m8n8.x4.shared.b16 {%0,%1,%2,%3}, [%4];" \
        : "=r"(r0), "=r"(r1), "=r"(r2), "=r"(r3) : "r"(addr))

__device__ __forceinline__ void mma_fp16(float& c0, float& c1, float& c2, float& c3,
                                         uint32_t a0, uint32_t a1, uint32_t a2, uint32_t a3,
                                         uint32_t b0, uint32_t b1)
{
    asm volatile(
        "mma.sync.aligned.m16n8k16.row.col.f32.f16.f16.f32 "
        "{%0,%1,%2,%3}, {%4,%5,%6,%7}, {%8,%9}, {%0,%1,%2,%3};"
        : "+f"(c0), "+f"(c1), "+f"(c2), "+f"(c3)
        : "r"(a0), "r"(a1), "r"(a2), "r"(a3), "r"(b0), "r"(b1));
}

// ---------------------------------------------------------------------------
// Prep A: fp32 -> fp16
// ---------------------------------------------------------------------------
__global__ __launch_bounds__(256)
void prepA_kernel(const float* __restrict__ A)
{
    int id = blockIdx.x * 256 + threadIdx.x;       // one float4 each
    float4 v = *(const float4*)(A + id * 4);
    __half h[4] = {__float2half_rn(v.x), __float2half_rn(v.y),
                   __float2half_rn(v.z), __float2half_rn(v.w)};
    *(uint2*)(g_Ah + id * 4) = *(uint2*)h;
}

// ---------------------------------------------------------------------------
// Prep W: Wh[n][k] = fp16(Wsrc[k][n']);  n<1024 -> Wk else Wq.  32x32 tiles.
// ---------------------------------------------------------------------------
__global__ __launch_bounds__(256)
void prepW_kernel(const float* __restrict__ Wk, const float* __restrict__ Wq)
{
    __shared__ float t[32][33];
    const int k0 = blockIdx.x * 32, n0 = blockIdx.y * 32;
    const float* src = (n0 < 1024) ? Wk : Wq;
    const int nc0 = (n0 < 1024) ? n0 : n0 - 1024;
    const int tx = threadIdx.x & 31, ty = threadIdx.x >> 5;
    for (int r = ty; r < 32; r += 8)
        t[r][tx] = src[(k0 + r) * 1024 + nc0 + tx];
    __syncthreads();
    for (int r = ty; r < 32; r += 8)
        g_Wh[(size_t)(n0 + r) * 2048 + k0 + tx] = __float2half_rn(t[tx][r]);
}

// ---------------------------------------------------------------------------
// fp16 GEMM: C[6400 x 2048] = Ah @ Wh^T (+bias)  ->  g_Kh | g_Qh (fp16)
// Tiles BM=128 BN=128 BK=32; 3-stage cp.async; 8 warps (2m x 4n), warp 64x32.
// ---------------------------------------------------------------------------
#define ROWH 40
#define ROWB 80
#define TILE_HALVES (128 * ROWH)                   // 5120 per operand
#define STAGE_HALVES (2 * TILE_HALVES)             // 10240 (20480 B)
#define NSTAGE 3
#define NITER  64                                  // 2048 / 32
#define GEMM_SMEM (NSTAGE * STAGE_HALVES * 2)      // 61440 B

__global__ __launch_bounds__(256, 2)
void gemm_kernel(const float* __restrict__ bk, const float* __restrict__ bq)
{
    extern __shared__ __align__(16) __half sm[];

    const int tid  = threadIdx.x;
    const int wid  = tid >> 5, lane = tid & 31;
    const int wm   = wid & 1,  wn   = wid >> 1;       // 2 x 4 warp grid
    const int g    = lane >> 2, t4  = lane & 3;
    const int mbase = blockIdx.y * 128;
    const int nbase = blockIdx.x * 128;

    const uint32_t sbase = smem_u32(sm);

    const int ra0 = tid >> 2,         ca0 = (tid & 3);
    const int ra1 = (tid + 256) >> 2, ca1 = (tid & 3);
    const __half* gA = g_Ah + (size_t)mbase * 2048;
    const __half* gB = g_Wh + (size_t)nbase * 2048;

    auto load_stage = [&](int it, int s) {
        const int k0 = it * 32;
        const uint32_t sA = sbase + s * STAGE_HALVES * 2;
        const uint32_t sB = sA + TILE_HALVES * 2;
        CP_ASYNC16(sA + ra0 * ROWB + ca0 * 16,
                   (const char*)(gA + (size_t)ra0 * 2048 + k0 + ca0 * 8));
        CP_ASYNC16(sA + ra1 * ROWB + ca1 * 16,
                   (const char*)(gA + (size_t)ra1 * 2048 + k0 + ca1 * 8));
        CP_ASYNC16(sB + ra0 * ROWB + ca0 * 16,
                   (const char*)(gB + (size_t)ra0 * 2048 + k0 + ca0 * 8));
        CP_ASYNC16(sB + ra1 * ROWB + ca1 * 16,
                   (const char*)(gB + (size_t)ra1 * 2048 + k0 + ca1 * 8));
        CP_COMMIT();
    };

    float c[4][4][4];
    #pragma unroll
    for (int i = 0; i < 4; i++)
        #pragma unroll
        for (int j = 0; j < 4; j++)
            #pragma unroll
            for (int k = 0; k < 4; k++) c[i][j][k] = 0.f;

    load_stage(0, 0);
    load_stage(1, 1);

    const int arow = (lane & 15);
    const int abyt = (lane >> 4) << 4;
    const int brow = (lane & 7) + ((lane >> 4) << 3);
    const int bbyt = ((lane >> 3) & 1) << 4;

    for (int it = 0; it < NITER; ++it) {
        const int s = it % NSTAGE;
        if (it < NITER - 1) { CP_WAIT1(); } else { CP_WAIT0(); }
        __syncthreads();
        if (it + 2 < NITER) load_stage(it + 2, (it + 2) % NSTAGE);

        const uint32_t sA = sbase + s * STAGE_HALVES * 2;
        const uint32_t sB = sA + TILE_HALVES * 2;

        #pragma unroll
        for (int ks = 0; ks < 2; ks++) {
            uint32_t af[4][4], bfr[2][4];
            #pragma unroll
            for (int fm = 0; fm < 4; fm++) {
                uint32_t ad = sA + (wm * 64 + fm * 16 + arow) * ROWB + ks * 32 + abyt;
                LDSM_X4(af[fm][0], af[fm][1], af[fm][2], af[fm][3], ad);
            }
            #pragma unroll
            for (int f2 = 0; f2 < 2; f2++) {
                uint32_t bd = sB + (wn * 32 + f2 * 16 + brow) * ROWB + ks * 32 + bbyt;
                LDSM_X4(bfr[f2][0], bfr[f2][1], bfr[f2][2], bfr[f2][3], bd);
            }
            #pragma unroll
            for (int fm = 0; fm < 4; fm++)
                #pragma unroll
                for (int fn = 0; fn < 4; fn++) {
                    uint32_t b0 = bfr[fn >> 1][(fn & 1) * 2 + 0];
                    uint32_t b1 = bfr[fn >> 1][(fn & 1) * 2 + 1];
                    mma_fp16(c[fm][fn][0], c[fm][fn][1], c[fm][fn][2], c[fm][fn][3],
                             af[fm][0], af[fm][1], af[fm][2], af[fm][3], b0, b1);
                }
        }
    }

    // epilogue: +bias, write fp16 to g_Kh (cols<1024) or g_Qh
    const bool side = (nbase >= 1024);
    const float* bsrc = side ? bq : bk;
    __half* outh = side ? g_Qh : g_Kh;
    const int colb = side ? (nbase - 1024) : nbase;

    #pragma unroll
    for (int fm = 0; fm < 4; fm++) {
        int row = mbase + wm * 64 + fm * 16 + g;
        #pragma unroll
        for (int fn = 0; fn < 4; fn++) {
            int col = colb + wn * 32 + fn * 8 + t4 * 2;
            float b0 = bsrc[col], b1 = bsrc[col + 1];
            *(__half2*)(outh + (size_t)row * 1024 + col) =
                __floats2half2_rn(c[fm][fn][0] + b0, c[fm][fn][1] + b1);
            *(__half2*)(outh + (size_t)(row + 8) * 1024 + col) =
                __floats2half2_rn(c[fm][fn][2] + b0, c[fm][fn][3] + b1);
        }
    }
}

// ---------------------------------------------------------------------------
// Gate: gw = max(g_row . Wg[:,h] + bg[h], 1e-6); store gw*1024 fp16 (normal
// range: 1.02e-3 .. ~500; uniform scale cancels in softmax ratio).
// ---------------------------------------------------------------------------
__global__ __launch_bounds__(128)
void gate_kernel(const float* __restrict__ gf,
                 const float* __restrict__ Wg, const float* __restrict__ bg)
{
    __shared__ float sW[64 * 16];
    __shared__ float sb[16];
    __shared__ float sg[128 * 65];

    const int tid = threadIdx.x;
    for (int i = tid; i < 1024; i += 128) sW[i] = Wg[i];
    if (tid < 16) sb[tid] = bg[tid];

    const int base = blockIdx.x * 128;
    for (int v = tid; v < 2048; v += 128) {
        int r = v >> 4, cc = (v & 15) << 2;
        float4 x = *(const float4*)(gf + (base + r) * 64 + cc);
        sg[r*65+cc] = x.x; sg[r*65+cc+1] = x.y; sg[r*65+cc+2] = x.z; sg[r*65+cc+3] = x.w;
    }
    __syncthreads();

    float acc[16];
    #pragma unroll
    for (int r = 0; r < 16; r++) acc[r] = sb[r];
    #pragma unroll 4
    for (int k = 0; k < 64; k++) {
        float gv = sg[tid * 65 + k];
        #pragma unroll
        for (int r = 0; r < 16; r++) acc[r] += gv * sW[k * 16 + r];
    }

    const int row = base + tid;
    const int b   = row / 10000;
    const int rem = row - b * 10000;
    __half* op = g_GW + (size_t)b * 160000 + rem;
    #pragma unroll
    for (int r = 0; r < 16; r++)
        op[r * 10000] = __float2half_rn(fmaxf(acc[r], 1e-6f) * GW_SCALE);
}

// ---------------------------------------------------------------------------
// Attention per (b,h), tensor-core version. 512 threads (16 warps, 4x4 grid).
//   Phase 1: S[i][j] = (K·Q^T)/8 via mma (i,j padded to 128), fp32 in smem
//   Softmax: warp-per-column, 3-pass; P^T[j][i] stored fp16 scaled to [0,1]
//            by 1/max_e (exact renorm: epilogue uses max_e/sum)
//   Phase 2: out[j][d] = P^T · V^T via mma; epilogue folds (max_e/sum)*w_s+b_s
// SMEM layout (bytes):
//   sKh  [128][72]h   @0        18432
//   sQh  [128][72]h   @18432    18432
//   sS   [112][105]f  @36864    47040
//   sGWh [100][102]h  @83904    20400
//   sPT  [128][120]h  @104304   30720
//   sVT  [128][120]h  @135024   30720
//   sInv [128]f       @165744   512      total 166256
// ---------------------------------------------------------------------------
#define ATTN_SMEM_BYTES 166256

__global__ __launch_bounds__(512)
void attn_kernel(const float* __restrict__ a,
                 const float* __restrict__ wsp, const float* __restrict__ bsp,
                 float* __restrict__ out)
{
    extern __shared__ __align__(16) char smc[];
    __half* sKh  = (__half*)(smc);
    __half* sQh  = (__half*)(smc + 18432);
    float*  sS   = (float*) (smc + 36864);
    __half* sGWh = (__half*)(smc + 83904);
    __half* sPT  = (__half*)(smc + 104304);
    __half* sVT  = (__half*)(smc + 135024);
    float*  sInv = (float*) (smc + 165744);

    const int h = blockIdx.x, b = blockIdx.y;
    const int tid = threadIdx.x;
    const int wid = tid >> 5, lane = tid & 31;
    const int wm = wid & 3, wn = wid >> 2;            // 4 x 4 warp grid
    const int g = lane >> 2, t4 = lane & 3;

    // ---- loads ----
    const __half* Kg = g_Kh + (size_t)(b * 100) * 1024 + h * 64;
    const __half* Qg = g_Qh + (size_t)(b * 100) * 1024 + h * 64;
    for (int v = tid; v < 800; v += 512) {            // 100 rows x 8 x 16B
        int r = v >> 3, c = v & 7;
        *(uint4*)(sKh + r * 72 + c * 8) = *(const uint4*)(Kg + (size_t)r * 1024 + c * 8);
        *(uint4*)(sQh + r * 72 + c * 8) = *(const uint4*)(Qg + (size_t)r * 1024 + c * 8);
    }
    for (int v = tid; v < 224; v += 512) {            // zero pad rows 100..127
        int r = 100 + (v >> 3), c = v & 7;
        *(uint4*)(sKh + r * 72 + c * 8) = make_uint4(0, 0, 0, 0);
        *(uint4*)(sQh + r * 72 + c * 8) = make_uint4(0, 0, 0, 0);
    }
    const __half* GW = g_GW + (size_t)(b * 16 + h) * 10000;
    for (int v = tid; v < 10000; v += 512) {
        int i = v / 100, j = v - i * 100;
        sGWh[i * 102 + j] = GW[v];
    }
    // V transposed fp16: VT[d][i]
    for (int v = tid; v < 12800; v += 512) {
        int i = v >> 7, d = v & 127;
        sVT[d * 120 + i] =
            __float2half_rn(a[(size_t)(b * 100 + i) * 2048 + h * 128 + d]);
    }
    for (int v = tid; v < 1536; v += 512) {           // zero VT i-pad [100,112)
        int d = v / 12, i = 100 + v % 12;
        sVT[d * 120 + i] = __float2half_rn(0.f);
    }
    __syncthreads();

    const int arow = lane & 15,                abyt = (lane >> 4) << 4;
    const int brow = (lane & 7) + ((lane >> 4) << 3), bbyt = ((lane >> 3) & 1) << 4;

    // ---- Phase 1: S = K.Q^T * 0.125 (warp tile 32m x 32n) ----
    {
        float c1[2][4][4];
        #pragma unroll
        for (int i = 0; i < 2; i++)
            #pragma unroll
            for (int j = 0; j < 4; j++)
                #pragma unroll
                for (int k = 0; k < 4; k++) c1[i][j][k] = 0.f;
        const uint32_t sKb = smem_u32(sKh), sQb = smem_u32(sQh);
        #pragma unroll
        for (int ks = 0; ks < 4; ks++) {
            uint32_t af[2][4], bfr[2][4];
            #pragma unroll
            for (int fm = 0; fm < 2; fm++) {
                uint32_t ad = sKb + (wm * 32 + fm * 16 + arow) * 144 + ks * 32 + abyt;
                LDSM_X4(af[fm][0], af[fm][1], af[fm][2], af[fm][3], ad);
            }
            #pragma unroll
            for (int f2 = 0; f2 < 2; f2++) {
                uint32_t bd = sQb + (wn * 32 + f2 * 16 + brow) * 144 + ks * 32 + bbyt;
                LDSM_X4(bfr[f2][0], bfr[f2][1], bfr[f2][2], bfr[f2][3], bd);
            }
            #pragma unroll
            for (int fm = 0; fm < 2; fm++)
                #pragma unroll
                for (int fn = 0; fn < 4; fn++)
                    mma_fp16(c1[fm][fn][0], c1[fm][fn][1], c1[fm][fn][2], c1[fm][fn][3],
                             af[fm][0], af[fm][1], af[fm][2], af[fm][3],
                             bfr[fn >> 1][(fn & 1) * 2], bfr[fn >> 1][(fn & 1) * 2 + 1]);
        }
        #pragma unroll
        for (int fm = 0; fm < 2; fm++) {
            int i0 = wm * 32 + fm * 16 + g;
            #pragma unroll
            for (int fn = 0; fn < 4; fn++) {
                int j0 = wn * 32 + fn * 8 + t4 * 2;
                if (j0 < 100) {
                    if (i0 < 112) {
                        sS[i0 * 105 + j0]     = c1[fm][fn][0] * 0.125f;
                        sS[i0 * 105 + j0 + 1] = c1[fm][fn][1] * 0.125f;
                    }
                    if (i0 + 8 < 112) {
                        sS[(i0 + 8) * 105 + j0]     = c1[fm][fn][2] * 0.125f;
                        sS[(i0 + 8) * 105 + j0 + 1] = c1[fm][fn][3] * 0.125f;
                    }
                }
            }
        }
    }
    __syncthreads();

    // ---- softmax (warp per column j), 3-pass, fp32 intermediates ----
    for (int j = wid; j < 100; j += 16) {
        // pass 1: max of s
        float m = -1e30f;
        for (int i = lane; i < 100; i += 32) m = fmaxf(m, sS[i * 105 + j]);
        #pragma unroll
        for (int o = 16; o; o >>= 1) m = fmaxf(m, __shfl_xor_sync(~0u, m, o));
        // pass 2: e = gw * exp(s-m) fp32 -> sS; accumulate sum and max_e
        float s = 0.f, mx = 0.f;
        for (int i = lane; i < 100; i += 32) {
            float e = __half2float(sGWh[i * 102 + j]) * __expf(sS[i * 105 + j] - m);
            sS[i * 105 + j] = e;
            s += e;
            mx = fmaxf(mx, e);
        }
        #pragma unroll
        for (int o = 16; o; o >>= 1) {
            s  += __shfl_xor_sync(~0u, s, o);
            mx  = fmaxf(mx, __shfl_xor_sync(~0u, mx, o));
        }
        // pass 3: store p = e/max_e in fp16 (range [0,1], full precision)
        const float inv_mx = 1.f / mx;
        for (int i = lane; i < 100; i += 32)
            sPT[j * 120 + i] = __float2half_rn(sS[i * 105 + j] * inv_mx);
        if (lane < 12) sPT[j * 120 + 100 + lane] = __float2half_rn(0.f);
        if (lane == 0) sInv[j] = mx / s;              // exact renormalization
    }
    // zero P^T pad rows 100..127 (cols 0..112 are read by ldmatrix)
    for (int v = tid; v < 392; v += 512) {
        int r = 100 + v / 14, c = v % 14;
        *(uint4*)((char*)sPT + r * 240 + c * 16) = make_uint4(0, 0, 0, 0);
    }
    __syncthreads();

    // ---- Phase 2: out = P^T · V^T  (m=j, k=i 112, n=d 128; warp 32j x 32d) ----
    {
        float c2[2][4][4];
        #pragma unroll
        for (int i = 0; i < 2; i++)
            #pragma unroll
            for (int j = 0; j < 4; j++)
                #pragma unroll
                for (int k = 0; k < 4; k++) c2[i][j][k] = 0.f;
        const uint32_t sPb = smem_u32(sPT), sVb = smem_u32(sVT);
        #pragma unroll
        for (int ks = 0; ks < 7; ks++) {
            uint32_t af[2][4], bfr[2][4];
            #pragma unroll
            for (int fm = 0; fm < 2; fm++) {
                uint32_t ad = sPb + (wm * 32 + fm * 16 + arow) * 240 + ks * 32 + abyt;
                LDSM_X4(af[fm][0], af[fm][1], af[fm][2], af[fm][3], ad);
            }
            #pragma unroll
            for (int f2 = 0; f2 < 2; f2++) {
                uint32_t bd = sVb + (wn * 32 + f2 * 16 + brow) * 240 + ks * 32 + bbyt;
                LDSM_X4(bfr[f2][0], bfr[f2][1], bfr[f2][2], bfr[f2][3], bd);
            }
            #pragma unroll
            for (int fm = 0; fm < 2; fm++)
                #pragma unroll
                for (int fn = 0; fn < 4; fn++)
                    mma_fp16(c2[fm][fn][0], c2[fm][fn][1], c2[fm][fn][2], c2[fm][fn][3],
                             af[fm][0], af[fm][1], af[fm][2], af[fm][3],
                             bfr[fn >> 1][(fn & 1) * 2], bfr[fn >> 1][(fn & 1) * 2 + 1]);
        }
        const float wsc = *wsp, bsc = *bsp;
        #pragma unroll
        for (int fm = 0; fm < 2; fm++) {
            int j0 = wm * 32 + fm * 16 + g;
            #pragma unroll
            for (int fn = 0; fn < 4; fn++) {
                int d0 = wn * 32 + fn * 8 + t4 * 2;
                if (j0 < 100) {
                    float sc = sInv[j0] * wsc;
                    *(float2*)(out + (size_t)(b * 100 + j0) * 2048 + h * 128 + d0) =
                        make_float2(c2[fm][fn][0] * sc + bsc, c2[fm][fn][1] * sc + bsc);
                }
                if (j0 + 8 < 100) {
                    float sc = sInv[j0 + 8] * wsc;
                    *(float2*)(out + (size_t)(b * 100 + j0 + 8) * 2048 + h * 128 + d0) =
                        make_float2(c2[fm][fn][2] * sc + bsc, c2[fm][fn][3] * sc + bsc);
                }
            }
        }
    }
}

// ---------------------------------------------------------------------------
// Launch. Inputs: a_features, g_features, split, rel_pair_counts,
// W_g, b_g, W_K, b_K, W_Q, b_Q, w_s, b_s
// ---------------------------------------------------------------------------
extern "C" void kernel_launch(void* const* d_in, const int* in_sizes, int n_in,
                              void* d_out, int out_size)
{
    (void)in_sizes; (void)n_in; (void)out_size;
    const float* a  = (const float*)d_in[0];
    const float* gf = (const float*)d_in[1];
    const float* Wg = (const float*)d_in[4];
    const float* bg = (const float*)d_in[5];
    const float* Wk = (const float*)d_in[6];
    const float* bk = (const float*)d_in[7];
    const float* Wq = (const float*)d_in[8];
    const float* bq = (const float*)d_in[9];
    const float* ws = (const float*)d_in[10];
    const float* bs = (const float*)d_in[11];
    float* out = (float*)d_out;

    cudaFuncSetAttribute(gemm_kernel, cudaFuncAttributeMaxDynamicSharedMemorySize, GEMM_SMEM);
    cudaFuncSetAttribute(attn_kernel, cudaFuncAttributeMaxDynamicSharedMemorySize,
                         ATTN_SMEM_BYTES);

    prepA_kernel<<<PP * 2048 / 1024, 256>>>(a);
    prepW_kernel<<<dim3(64, 64), 256>>>(Wk, Wq);
    gate_kernel<<<5000, 128>>>(gf, Wg, bg);
    gemm_kernel<<<dim3(16, 50), 256, GEMM_SMEM>>>(bk, bq);
    attn_kernel<<<dim3(16, 64), 512, ATTN_SMEM_BYTES>>>(a, ws, bs, out);
}

// round 8
// speedup vs baseline: 2.4074x; 1.1052x over previous
#include <cuda_runtime.h>
#include <cuda_fp16.h>
#include <cstdint>

// Problem constants
#define BB   64
#define NN   100
#define DD   2048
#define NRH  16
#define PP   (BB*NN)        // 6400

#define GW_SCALE 1024.0f    // uniform gate scale; cancels exactly in softmax ratio

// ---------------------------------------------------------------------------
// Scratch (__device__ globals; no allocations allowed)
// ---------------------------------------------------------------------------
__device__ __half g_Ah[PP * 2048];               // 26.2 MB  A in fp16
__device__ __half g_Wh[2048 * 2048];             // 8.4 MB   W^T fused [n][k] (Wk|Wq)
__device__ __half g_Kh[PP * 1024];               // 13.1 MB  K fp16
__device__ __half g_Qh[PP * 1024];               // 13.1 MB  Q fp16
__device__ __half g_GW[BB * NRH * NN * NN];      // 20.5 MB  gw * 1024, fp16

__device__ __forceinline__ uint32_t smem_u32(const void* p) {
    uint32_t a;
    asm("{ .reg .u64 t; cvta.to.shared.u64 t, %1; cvt.u32.u64 %0, t; }" : "=r"(a) : "l"(p));
    return a;
}

#define CP_ASYNC16(dst, src) \
    asm volatile("cp.async.cg.shared.global [%0], [%1], 16;" :: "r"(dst), "l"(src) : "memory")
#define CP_COMMIT() asm volatile("cp.async.commit_group;" ::: "memory")
#define CP_WAIT1()  asm volatile("cp.async.wait_group 1;" ::: "memory")
#define CP_WAIT0()  asm volatile("cp.async.wait_group 0;" ::: "memory")

#define LDSM_X4(r0, r1, r2, r3, addr) \
    asm volatile("ldmatrix.sync.aligned.m8n8.x4.shared.b16 {%0,%1,%2,%3}, [%4];" \
        : "=r"(r0), "=r"(r1), "=r"(r2), "=r"(r3) : "r"(addr))

__device__ __forceinline__ void mma_fp16(float& c0, float& c1, float& c2, float& c3,
                                         uint32_t a0, uint32_t a1, uint32_t a2, uint32_t a3,
                                         uint32_t b0, uint32_t b1)
{
    asm volatile(
        "mma.sync.aligned.m16n8k16.row.col.f32.f16.f16.f32 "
        "{%0,%1,%2,%3}, {%4,%5,%6,%7}, {%8,%9}, {%0,%1,%2,%3};"
        : "+f"(c0), "+f"(c1), "+f"(c2), "+f"(c3)
        : "r"(a0), "r"(a1), "r"(a2), "r"(a3), "r"(b0), "r"(b1));
}

// ---------------------------------------------------------------------------
// Prep A: fp32 -> fp16
// ---------------------------------------------------------------------------
__global__ __launch_bounds__(256)
void prepA_kernel(const float* __restrict__ A)
{
    int id = blockIdx.x * 256 + threadIdx.x;       // one float4 each
    float4 v = *(const float4*)(A + id * 4);
    __half h[4] = {__float2half_rn(v.x), __float2half_rn(v.y),
                   __float2half_rn(v.z), __float2half_rn(v.w)};
    *(uint2*)(g_Ah + id * 4) = *(uint2*)h;
}

// ---------------------------------------------------------------------------
// Prep W: Wh[n][k] = fp16(Wsrc[k][n']);  n<1024 -> Wk else Wq.  32x32 tiles.
// ---------------------------------------------------------------------------
__global__ __launch_bounds__(256)
void prepW_kernel(const float* __restrict__ Wk, const float* __restrict__ Wq)
{
    __shared__ float t[32][33];
    const int k0 = blockIdx.x * 32, n0 = blockIdx.y * 32;
    const float* src = (n0 < 1024) ? Wk : Wq;
    const int nc0 = (n0 < 1024) ? n0 : n0 - 1024;
    const int tx = threadIdx.x & 31, ty = threadIdx.x >> 5;
    for (int r = ty; r < 32; r += 8)
        t[r][tx] = src[(k0 + r) * 1024 + nc0 + tx];
    __syncthreads();
    for (int r = ty; r < 32; r += 8)
        g_Wh[(size_t)(n0 + r) * 2048 + k0 + tx] = __float2half_rn(t[tx][r]);
}

// ---------------------------------------------------------------------------
// fp16 GEMM: C[6400 x 2048] = Ah @ Wh^T (+bias)  ->  g_Kh | g_Qh (fp16)
// Tiles BM=128 BN=128 BK=64; 3-stage cp.async; 8 warps (2m x 4n), warp 64x32.
// Rows padded to 72 halves (144B): 16B-aligned cp.async, conflict-free LDSM.
// ---------------------------------------------------------------------------
#define ROWH 72
#define ROWB 144
#define TILE_BYTES2 (128 * ROWB)                   // 18432 per operand
#define STAGE_BYTES2 (2 * TILE_BYTES2)             // 36864
#define NSTAGE 3
#define NITER  32                                  // 2048 / 64
#define GEMM_SMEM (NSTAGE * STAGE_BYTES2)          // 110592 B

__global__ __launch_bounds__(256, 2)
void gemm_kernel(const float* __restrict__ bk, const float* __restrict__ bq)
{
    extern __shared__ __align__(16) __half sm[];

    const int tid  = threadIdx.x;
    const int wid  = tid >> 5, lane = tid & 31;
    const int wm   = wid & 1,  wn   = wid >> 1;       // 2 x 4 warp grid
    const int g    = lane >> 2, t4  = lane & 3;
    const int mbase = blockIdx.y * 128;
    const int nbase = blockIdx.x * 128;

    const uint32_t sbase = smem_u32(sm);
    const __half* gA = g_Ah + (size_t)mbase * 2048;
    const __half* gB = g_Wh + (size_t)nbase * 2048;

    // per stage: each operand 128 rows x 8 chunks(16B); 2048 chunks / 256 thr
    auto load_stage = [&](int it, int s) {
        const int k0 = it * 64;
        const uint32_t sA = sbase + s * STAGE_BYTES2;
        const uint32_t sB = sA + TILE_BYTES2;
        #pragma unroll
        for (int l = 0; l < 4; l++) {
            int q = tid + 256 * l;
            int r = q >> 3, c = q & 7;
            CP_ASYNC16(sA + r * ROWB + c * 16,
                       (const char*)(gA + (size_t)r * 2048 + k0 + c * 8));
            CP_ASYNC16(sB + r * ROWB + c * 16,
                       (const char*)(gB + (size_t)r * 2048 + k0 + c * 8));
        }
        CP_COMMIT();
    };

    float c[4][4][4];
    #pragma unroll
    for (int i = 0; i < 4; i++)
        #pragma unroll
        for (int j = 0; j < 4; j++)
            #pragma unroll
            for (int k = 0; k < 4; k++) c[i][j][k] = 0.f;

    load_stage(0, 0);
    load_stage(1, 1);

    const int arow = (lane & 15);
    const int abyt = (lane >> 4) << 4;
    const int brow = (lane & 7) + ((lane >> 4) << 3);
    const int bbyt = ((lane >> 3) & 1) << 4;

    for (int it = 0; it < NITER; ++it) {
        const int s = it % NSTAGE;
        if (it < NITER - 1) { CP_WAIT1(); } else { CP_WAIT0(); }
        __syncthreads();
        if (it + 2 < NITER) load_stage(it + 2, (it + 2) % NSTAGE);

        const uint32_t sA = sbase + s * STAGE_BYTES2;
        const uint32_t sB = sA + TILE_BYTES2;

        #pragma unroll
        for (int ks = 0; ks < 4; ks++) {
            uint32_t af[4][4], bfr[2][4];
            #pragma unroll
            for (int fm = 0; fm < 4; fm++) {
                uint32_t ad = sA + (wm * 64 + fm * 16 + arow) * ROWB + ks * 32 + abyt;
                LDSM_X4(af[fm][0], af[fm][1], af[fm][2], af[fm][3], ad);
            }
            #pragma unroll
            for (int f2 = 0; f2 < 2; f2++) {
                uint32_t bd = sB + (wn * 32 + f2 * 16 + brow) * ROWB + ks * 32 + bbyt;
                LDSM_X4(bfr[f2][0], bfr[f2][1], bfr[f2][2], bfr[f2][3], bd);
            }
            #pragma unroll
            for (int fm = 0; fm < 4; fm++)
                #pragma unroll
                for (int fn = 0; fn < 4; fn++) {
                    uint32_t b0 = bfr[fn >> 1][(fn & 1) * 2 + 0];
                    uint32_t b1 = bfr[fn >> 1][(fn & 1) * 2 + 1];
                    mma_fp16(c[fm][fn][0], c[fm][fn][1], c[fm][fn][2], c[fm][fn][3],
                             af[fm][0], af[fm][1], af[fm][2], af[fm][3], b0, b1);
                }
        }
    }

    // epilogue: +bias, write fp16 to g_Kh (cols<1024) or g_Qh
    const bool side = (nbase >= 1024);
    const float* bsrc = side ? bq : bk;
    __half* outh = side ? g_Qh : g_Kh;
    const int colb = side ? (nbase - 1024) : nbase;

    #pragma unroll
    for (int fm = 0; fm < 4; fm++) {
        int row = mbase + wm * 64 + fm * 16 + g;
        #pragma unroll
        for (int fn = 0; fn < 4; fn++) {
            int col = colb + wn * 32 + fn * 8 + t4 * 2;
            float b0 = bsrc[col], b1 = bsrc[col + 1];
            *(__half2*)(outh + (size_t)row * 1024 + col) =
                __floats2half2_rn(c[fm][fn][0] + b0, c[fm][fn][1] + b1);
            *(__half2*)(outh + (size_t)(row + 8) * 1024 + col) =
                __floats2half2_rn(c[fm][fn][2] + b0, c[fm][fn][3] + b1);
        }
    }
}

// ---------------------------------------------------------------------------
// Gate via fp16 mma with hi/lo split (~fp32 exact):
//   gw = max(g . Wg[:,h] + bg[h], 1e-6) * GW_SCALE, fp16 out
//   gw ≈ g_hi*W_hi + g_hi*W_lo + g_lo*W_hi  (drops ~2^-22 g_lo*W_lo term)
// Block: 256 threads (8 warps), 256 rows; warp = 32 rows (2 m16 tiles).
// B fragments built directly from gmem Wg (tiny, L1-resident).
// ---------------------------------------------------------------------------
#define GATE_ROWS 256
#define GATE_RH   72
#define ROWB_GATE 144

__global__ __launch_bounds__(256)
void gate_kernel(const float* __restrict__ gf,
                 const float* __restrict__ Wg, const float* __restrict__ bg)
{
    __shared__ __align__(16) __half sGh[GATE_ROWS * GATE_RH];
    __shared__ __align__(16) __half sGl[GATE_ROWS * GATE_RH];

    const int tid = threadIdx.x, lane = tid & 31, wid = tid >> 5;
    const int g = lane >> 2, t4 = lane & 3;
    const int rowbase = blockIdx.x * GATE_ROWS;

    // stage g rows fp32 -> (hi, lo) fp16; 4096 float4 / 256 thr
    for (int v = tid; v < 4096; v += 256) {
        int r = v >> 4, c4 = (v & 15) << 2;
        float4 x = *(const float4*)(gf + (size_t)(rowbase + r) * 64 + c4);
        float xs[4] = {x.x, x.y, x.z, x.w};
        __half hi[4], lo[4];
        #pragma unroll
        for (int e = 0; e < 4; e++) {
            hi[e] = __float2half_rn(xs[e]);
            lo[e] = __float2half_rn(xs[e] - __half2float(hi[e]));
        }
        *(uint2*)(sGh + r * GATE_RH + c4) = *(uint2*)hi;
        *(uint2*)(sGl + r * GATE_RH + c4) = *(uint2*)lo;
    }

    // B fragments (col-major B = Wg^T[n][k]): b0 k=16ks+2t4{,+1}, b1 +8; n = nt*8+g
    uint32_t bh[4][2][2], bl[4][2][2];
    #pragma unroll
    for (int ks = 0; ks < 4; ks++)
        #pragma unroll
        for (int nt = 0; nt < 2; nt++) {
            int n = nt * 8 + g;
            #pragma unroll
            for (int rg = 0; rg < 2; rg++) {
                int k0 = ks * 16 + t4 * 2 + rg * 8;
                float w0 = Wg[k0 * 16 + n], w1 = Wg[(k0 + 1) * 16 + n];
                __half h0 = __float2half_rn(w0), h1 = __float2half_rn(w1);
                __half l0 = __float2half_rn(w0 - __half2float(h0));
                __half l1 = __float2half_rn(w1 - __half2float(h1));
                __half hh[2] = {h0, h1}, ll[2] = {l0, l1};
                bh[ks][nt][rg] = *(uint32_t*)hh;
                bl[ks][nt][rg] = *(uint32_t*)ll;
            }
        }
    __syncthreads();

    const uint32_t sGhb = smem_u32(sGh), sGlb = smem_u32(sGl);
    const int arow = lane & 15, abyt = (lane >> 4) << 4;
    const int wrow = wid * 32;

    #pragma unroll
    for (int mt = 0; mt < 2; mt++) {
        float c[2][4];
        #pragma unroll
        for (int nt = 0; nt < 2; nt++)
            #pragma unroll
            for (int k = 0; k < 4; k++) c[nt][k] = 0.f;

        #pragma unroll
        for (int ks = 0; ks < 4; ks++) {
            uint32_t ah[4], al[4];
            uint32_t base_off = (wrow + mt * 16 + arow) * ROWB_GATE + ks * 32 + abyt;
            LDSM_X4(ah[0], ah[1], ah[2], ah[3], sGhb + base_off);
            LDSM_X4(al[0], al[1], al[2], al[3], sGlb + base_off);
            #pragma unroll
            for (int nt = 0; nt < 2; nt++) {
                mma_fp16(c[nt][0], c[nt][1], c[nt][2], c[nt][3],
                         ah[0], ah[1], ah[2], ah[3], bh[ks][nt][0], bh[ks][nt][1]);
                mma_fp16(c[nt][0], c[nt][1], c[nt][2], c[nt][3],
                         ah[0], ah[1], ah[2], ah[3], bl[ks][nt][0], bl[ks][nt][1]);
                mma_fp16(c[nt][0], c[nt][1], c[nt][2], c[nt][3],
                         al[0], al[1], al[2], al[3], bh[ks][nt][0], bh[ks][nt][1]);
            }
        }

        // epilogue: +bias, clamp, scale, scatter to [b][h][i*100+j]
        #pragma unroll
        for (int nt = 0; nt < 2; nt++) {
            int h0 = nt * 8 + t4 * 2;
            float bb0 = bg[h0], bb1 = bg[h0 + 1];
            #pragma unroll
            for (int p = 0; p < 2; p++) {
                int row = rowbase + wrow + mt * 16 + g + p * 8;
                int bidx = row / 10000;
                int rem  = row - bidx * 10000;
                __half* dst = g_GW + (size_t)bidx * 160000 + rem;
                float v0 = fmaxf(c[nt][p * 2 + 0] + bb0, 1e-6f) * GW_SCALE;
                float v1 = fmaxf(c[nt][p * 2 + 1] + bb1, 1e-6f) * GW_SCALE;
                dst[(size_t)h0 * 10000]       = __float2half_rn(v0);
                dst[(size_t)(h0 + 1) * 10000] = __float2half_rn(v1);
            }
        }
    }
}

// ---------------------------------------------------------------------------
// Attention per (b,h), tensor-core version. 512 threads (16 warps, 4x4 grid).
//   Phase 1: S[i][j] = (K·Q^T)/8 via mma (i,j padded to 128), fp32 in smem
//   Softmax: warp-per-column, 3-pass; P^T[j][i] stored fp16 scaled to [0,1]
//   Phase 2: out[j][d] = P^T · V^T via mma; epilogue folds (max_e/sum)*w_s+b_s
// ---------------------------------------------------------------------------
#define ATTN_SMEM_BYTES 166256

__global__ __launch_bounds__(512)
void attn_kernel(const float* __restrict__ a,
                 const float* __restrict__ wsp, const float* __restrict__ bsp,
                 float* __restrict__ out)
{
    extern __shared__ __align__(16) char smc[];
    __half* sKh  = (__half*)(smc);
    __half* sQh  = (__half*)(smc + 18432);
    float*  sS   = (float*) (smc + 36864);
    __half* sGWh = (__half*)(smc + 83904);
    __half* sPT  = (__half*)(smc + 104304);
    __half* sVT  = (__half*)(smc + 135024);
    float*  sInv = (float*) (smc + 165744);

    const int h = blockIdx.x, b = blockIdx.y;
    const int tid = threadIdx.x;
    const int wid = tid >> 5, lane = tid & 31;
    const int wm = wid & 3, wn = wid >> 2;            // 4 x 4 warp grid
    const int g = lane >> 2, t4 = lane & 3;

    // ---- loads ----
    const __half* Kg = g_Kh + (size_t)(b * 100) * 1024 + h * 64;
    const __half* Qg = g_Qh + (size_t)(b * 100) * 1024 + h * 64;
    for (int v = tid; v < 800; v += 512) {            // 100 rows x 8 x 16B
        int r = v >> 3, c = v & 7;
        *(uint4*)(sKh + r * 72 + c * 8) = *(const uint4*)(Kg + (size_t)r * 1024 + c * 8);
        *(uint4*)(sQh + r * 72 + c * 8) = *(const uint4*)(Qg + (size_t)r * 1024 + c * 8);
    }
    for (int v = tid; v < 224; v += 512) {            // zero pad rows 100..127
        int r = 100 + (v >> 3), c = v & 7;
        *(uint4*)(sKh + r * 72 + c * 8) = make_uint4(0, 0, 0, 0);
        *(uint4*)(sQh + r * 72 + c * 8) = make_uint4(0, 0, 0, 0);
    }
    const __half* GW = g_GW + (size_t)(b * 16 + h) * 10000;
    for (int v = tid; v < 10000; v += 512) {
        int i = v / 100, j = v - i * 100;
        sGWh[i * 102 + j] = GW[v];
    }
    // V transposed fp16: VT[d][i], vectorized read (float4), 4 scalar stores
    for (int v = tid; v < 3200; v += 512) {
        int i = v >> 5, d0 = (v & 31) << 2;
        float4 x = *(const float4*)(a + (size_t)(b * 100 + i) * 2048 + h * 128 + d0);
        sVT[(d0 + 0) * 120 + i] = __float2half_rn(x.x);
        sVT[(d0 + 1) * 120 + i] = __float2half_rn(x.y);
        sVT[(d0 + 2) * 120 + i] = __float2half_rn(x.z);
        sVT[(d0 + 3) * 120 + i] = __float2half_rn(x.w);
    }
    for (int v = tid; v < 1536; v += 512) {           // zero VT i-pad [100,112)
        int d = v / 12, i = 100 + v % 12;
        sVT[d * 120 + i] = __float2half_rn(0.f);
    }
    __syncthreads();

    const int arow = lane & 15,                abyt = (lane >> 4) << 4;
    const int brow = (lane & 7) + ((lane >> 4) << 3), bbyt = ((lane >> 3) & 1) << 4;

    // ---- Phase 1: S = K.Q^T * 0.125 (warp tile 32m x 32n) ----
    {
        float c1[2][4][4];
        #pragma unroll
        for (int i = 0; i < 2; i++)
            #pragma unroll
            for (int j = 0; j < 4; j++)
                #pragma unroll
                for (int k = 0; k < 4; k++) c1[i][j][k] = 0.f;
        const uint32_t sKb = smem_u32(sKh), sQb = smem_u32(sQh);
        #pragma unroll
        for (int ks = 0; ks < 4; ks++) {
            uint32_t af[2][4], bfr[2][4];
            #pragma unroll
            for (int fm = 0; fm < 2; fm++) {
                uint32_t ad = sKb + (wm * 32 + fm * 16 + arow) * 144 + ks * 32 + abyt;
                LDSM_X4(af[fm][0], af[fm][1], af[fm][2], af[fm][3], ad);
            }
            #pragma unroll
            for (int f2 = 0; f2 < 2; f2++) {
                uint32_t bd = sQb + (wn * 32 + f2 * 16 + brow) * 144 + ks * 32 + bbyt;
                LDSM_X4(bfr[f2][0], bfr[f2][1], bfr[f2][2], bfr[f2][3], bd);
            }
            #pragma unroll
            for (int fm = 0; fm < 2; fm++)
                #pragma unroll
                for (int fn = 0; fn < 4; fn++)
                    mma_fp16(c1[fm][fn][0], c1[fm][fn][1], c1[fm][fn][2], c1[fm][fn][3],
                             af[fm][0], af[fm][1], af[fm][2], af[fm][3],
                             bfr[fn >> 1][(fn & 1) * 2], bfr[fn >> 1][(fn & 1) * 2 + 1]);
        }
        #pragma unroll
        for (int fm = 0; fm < 2; fm++) {
            int i0 = wm * 32 + fm * 16 + g;
            #pragma unroll
            for (int fn = 0; fn < 4; fn++) {
                int j0 = wn * 32 + fn * 8 + t4 * 2;
                if (j0 < 100) {
                    if (i0 < 112) {
                        sS[i0 * 105 + j0]     = c1[fm][fn][0] * 0.125f;
                        sS[i0 * 105 + j0 + 1] = c1[fm][fn][1] * 0.125f;
                    }
                    if (i0 + 8 < 112) {
                        sS[(i0 + 8) * 105 + j0]     = c1[fm][fn][2] * 0.125f;
                        sS[(i0 + 8) * 105 + j0 + 1] = c1[fm][fn][3] * 0.125f;
                    }
                }
            }
        }
    }
    __syncthreads();

    // ---- softmax (warp per column j), 3-pass, fp32 intermediates ----
    for (int j = wid; j < 100; j += 16) {
        float m = -1e30f;
        for (int i = lane; i < 100; i += 32) m = fmaxf(m, sS[i * 105 + j]);
        #pragma unroll
        for (int o = 16; o; o >>= 1) m = fmaxf(m, __shfl_xor_sync(~0u, m, o));
        float s = 0.f, mx = 0.f;
        for (int i = lane; i < 100; i += 32) {
            float e = __half2float(sGWh[i * 102 + j]) * __expf(sS[i * 105 + j] - m);
            sS[i * 105 + j] = e;
            s += e;
            mx = fmaxf(mx, e);
        }
        #pragma unroll
        for (int o = 16; o; o >>= 1) {
            s  += __shfl_xor_sync(~0u, s, o);
            mx  = fmaxf(mx, __shfl_xor_sync(~0u, mx, o));
        }
        const float inv_mx = 1.f / mx;
        for (int i = lane; i < 100; i += 32)
            sPT[j * 120 + i] = __float2half_rn(sS[i * 105 + j] * inv_mx);
        if (lane < 12) sPT[j * 120 + 100 + lane] = __float2half_rn(0.f);
        if (lane == 0) sInv[j] = mx / s;              // exact renormalization
    }
    // zero P^T pad rows 100..127
    for (int v = tid; v < 392; v += 512) {
        int r = 100 + v / 14, c = v % 14;
        *(uint4*)((char*)sPT + r * 240 + c * 16) = make_uint4(0, 0, 0, 0);
    }
    __syncthreads();

    // ---- Phase 2: out = P^T · V^T  (m=j, k=i 112, n=d 128; warp 32j x 32d) ----
    {
        float c2[2][4][4];
        #pragma unroll
        for (int i = 0; i < 2; i++)
            #pragma unroll
            for (int j = 0; j < 4; j++)
                #pragma unroll
                for (int k = 0; k < 4; k++) c2[i][j][k] = 0.f;
        const uint32_t sPb = smem_u32(sPT), sVb = smem_u32(sVT);
        #pragma unroll
        for (int ks = 0; ks < 7; ks++) {
            uint32_t af[2][4], bfr[2][4];
            #pragma unroll
            for (int fm = 0; fm < 2; fm++) {
                uint32_t ad = sPb + (wm * 32 + fm * 16 + arow) * 240 + ks * 32 + abyt;
                LDSM_X4(af[fm][0], af[fm][1], af[fm][2], af[fm][3], ad);
            }
            #pragma unroll
            for (int f2 = 0; f2 < 2; f2++) {
                uint32_t bd = sVb + (wn * 32 + f2 * 16 + brow) * 240 + ks * 32 + bbyt;
                LDSM_X4(bfr[f2][0], bfr[f2][1], bfr[f2][2], bfr[f2][3], bd);
            }
            #pragma unroll
            for (int fm = 0; fm < 2; fm++)
                #pragma unroll
                for (int fn = 0; fn < 4; fn++)
                    mma_fp16(c2[fm][fn][0], c2[fm][fn][1], c2[fm][fn][2], c2[fm][fn][3],
                             af[fm][0], af[fm][1], af[fm][2], af[fm][3],
                             bfr[fn >> 1][(fn & 1) * 2], bfr[fn >> 1][(fn & 1) * 2 + 1]);
        }
        const float wsc = *wsp, bsc = *bsp;
        #pragma unroll
        for (int fm = 0; fm < 2; fm++) {
            int j0 = wm * 32 + fm * 16 + g;
            #pragma unroll
            for (int fn = 0; fn < 4; fn++) {
                int d0 = wn * 32 + fn * 8 + t4 * 2;
                if (j0 < 100) {
                    float sc = sInv[j0] * wsc;
                    *(float2*)(out + (size_t)(b * 100 + j0) * 2048 + h * 128 + d0) =
                        make_float2(c2[fm][fn][0] * sc + bsc, c2[fm][fn][1] * sc + bsc);
                }
                if (j0 + 8 < 100) {
                    float sc = sInv[j0 + 8] * wsc;
                    *(float2*)(out + (size_t)(b * 100 + j0 + 8) * 2048 + h * 128 + d0) =
                        make_float2(c2[fm][fn][2] * sc + bsc, c2[fm][fn][3] * sc + bsc);
                }
            }
        }
    }
}

// ---------------------------------------------------------------------------
// Launch. Inputs: a_features, g_features, split, rel_pair_counts,
// W_g, b_g, W_K, b_K, W_Q, b_Q, w_s, b_s
// ---------------------------------------------------------------------------
extern "C" void kernel_launch(void* const* d_in, const int* in_sizes, int n_in,
                              void* d_out, int out_size)
{
    (void)in_sizes; (void)n_in; (void)out_size;
    const float* a  = (const float*)d_in[0];
    const float* gf = (const float*)d_in[1];
    const float* Wg = (const float*)d_in[4];
    const float* bg = (const float*)d_in[5];
    const float* Wk = (const float*)d_in[6];
    const float* bk = (const float*)d_in[7];
    const float* Wq = (const float*)d_in[8];
    const float* bq = (const float*)d_in[9];
    const float* ws = (const float*)d_in[10];
    const float* bs = (const float*)d_in[11];
    float* out = (float*)d_out;

    cudaFuncSetAttribute(gemm_kernel, cudaFuncAttributeMaxDynamicSharedMemorySize, GEMM_SMEM);
    cudaFuncSetAttribute(attn_kernel, cudaFuncAttributeMaxDynamicSharedMemorySize,
                         ATTN_SMEM_BYTES);

    prepA_kernel<<<PP * 2048 / 1024, 256>>>(a);
    prepW_kernel<<<dim3(64, 64), 256>>>(Wk, Wq);
    gate_kernel<<<640000 / GATE_ROWS, 256>>>(gf, Wg, bg);
    gemm_kernel<<<dim3(16, 50), 256, GEMM_SMEM>>>(bk, bq);
    attn_kernel<<<dim3(16, 64), 512, ATTN_SMEM_BYTES>>>(a, ws, bs, out);
}

// round 9
// speedup vs baseline: 3.1159x; 1.2943x over previous
#include <cuda_runtime.h>
#include <cuda_fp16.h>
#include <cstdint>

// Problem constants
#define BB   64
#define NN   100
#define DD   2048
#define NRH  16
#define PP   (BB*NN)        // 6400

#define GW_SCALE 1024.0f    // uniform gate scale; cancels exactly in softmax ratio

// ---------------------------------------------------------------------------
// Scratch (__device__ globals; no allocations allowed)
// ---------------------------------------------------------------------------
__device__ __half g_Ah[PP * 2048];               // 26.2 MB  A in fp16
__device__ __half g_Wh[2048 * 2048];             // 8.4 MB   W^T fused [n][k] (Wk|Wq)
__device__ __half g_Kh[PP * 1024];               // 13.1 MB  K fp16
__device__ __half g_Qh[PP * 1024];               // 13.1 MB  Q fp16
__device__ __half g_GW[BB * NRH * NN * NN];      // 20.5 MB  gw*1024 fp16, [b][h][j][i]

__device__ __forceinline__ uint32_t smem_u32(const void* p) {
    uint32_t a;
    asm("{ .reg .u64 t; cvta.to.shared.u64 t, %1; cvt.u32.u64 %0, t; }" : "=r"(a) : "l"(p));
    return a;
}

#define CP_ASYNC16(dst, src) \
    asm volatile("cp.async.cg.shared.global [%0], [%1], 16;" :: "r"(dst), "l"(src) : "memory")
#define CP_COMMIT() asm volatile("cp.async.commit_group;" ::: "memory")
#define CP_WAIT1()  asm volatile("cp.async.wait_group 1;" ::: "memory")
#define CP_WAIT0()  asm volatile("cp.async.wait_group 0;" ::: "memory")

#define LDSM_X4(r0, r1, r2, r3, addr) \
    asm volatile("ldmatrix.sync.aligned.m8n8.x4.shared.b16 {%0,%1,%2,%3}, [%4];" \
        : "=r"(r0), "=r"(r1), "=r"(r2), "=r"(r3) : "r"(addr))

#define LDSM_X4_TRANS(r0, r1, r2, r3, addr) \
    asm volatile("ldmatrix.sync.aligned.m8n8.x4.trans.shared.b16 {%0,%1,%2,%3}, [%4];" \
        : "=r"(r0), "=r"(r1), "=r"(r2), "=r"(r3) : "r"(addr))

__device__ __forceinline__ void mma_fp16(float& c0, float& c1, float& c2, float& c3,
                                         uint32_t a0, uint32_t a1, uint32_t a2, uint32_t a3,
                                         uint32_t b0, uint32_t b1)
{
    asm volatile(
        "mma.sync.aligned.m16n8k16.row.col.f32.f16.f16.f32 "
        "{%0,%1,%2,%3}, {%4,%5,%6,%7}, {%8,%9}, {%0,%1,%2,%3};"
        : "+f"(c0), "+f"(c1), "+f"(c2), "+f"(c3)
        : "r"(a0), "r"(a1), "r"(a2), "r"(a3), "r"(b0), "r"(b1));
}

// ---------------------------------------------------------------------------
// Prep A: fp32 -> fp16
// ---------------------------------------------------------------------------
__global__ __launch_bounds__(256)
void prepA_kernel(const float* __restrict__ A)
{
    int id = blockIdx.x * 256 + threadIdx.x;       // one float4 each
    float4 v = *(const float4*)(A + id * 4);
    __half h[4] = {__float2half_rn(v.x), __float2half_rn(v.y),
                   __float2half_rn(v.z), __float2half_rn(v.w)};
    *(uint2*)(g_Ah + id * 4) = *(uint2*)h;
}

// ---------------------------------------------------------------------------
// Prep W: Wh[n][k] = fp16(Wsrc[k][n']);  n<1024 -> Wk else Wq.  32x32 tiles.
// ---------------------------------------------------------------------------
__global__ __launch_bounds__(256)
void prepW_kernel(const float* __restrict__ Wk, const float* __restrict__ Wq)
{
    __shared__ float t[32][33];
    const int k0 = blockIdx.x * 32, n0 = blockIdx.y * 32;
    const float* src = (n0 < 1024) ? Wk : Wq;
    const int nc0 = (n0 < 1024) ? n0 : n0 - 1024;
    const int tx = threadIdx.x & 31, ty = threadIdx.x >> 5;
    for (int r = ty; r < 32; r += 8)
        t[r][tx] = src[(k0 + r) * 1024 + nc0 + tx];
    __syncthreads();
    for (int r = ty; r < 32; r += 8)
        g_Wh[(size_t)(n0 + r) * 2048 + k0 + tx] = __float2half_rn(t[tx][r]);
}

// ---------------------------------------------------------------------------
// fp16 GEMM: C[6400 x 2048] = Ah @ Wh^T (+bias)  ->  g_Kh | g_Qh (fp16)
// Tiles BM=128 BN=128 BK=64; 3-stage cp.async; 8 warps (2m x 4n), warp 64x32.
// ---------------------------------------------------------------------------
#define ROWH 72
#define ROWB 144
#define TILE_BYTES2 (128 * ROWB)                   // 18432 per operand
#define STAGE_BYTES2 (2 * TILE_BYTES2)             // 36864
#define NSTAGE 3
#define NITER  32                                  // 2048 / 64
#define GEMM_SMEM (NSTAGE * STAGE_BYTES2)          // 110592 B

__global__ __launch_bounds__(256, 2)
void gemm_kernel(const float* __restrict__ bk, const float* __restrict__ bq)
{
    extern __shared__ __align__(16) __half sm[];

    const int tid  = threadIdx.x;
    const int wid  = tid >> 5, lane = tid & 31;
    const int wm   = wid & 1,  wn   = wid >> 1;       // 2 x 4 warp grid
    const int g    = lane >> 2, t4  = lane & 3;
    const int mbase = blockIdx.y * 128;
    const int nbase = blockIdx.x * 128;

    const uint32_t sbase = smem_u32(sm);
    const __half* gA = g_Ah + (size_t)mbase * 2048;
    const __half* gB = g_Wh + (size_t)nbase * 2048;

    auto load_stage = [&](int it, int s) {
        const int k0 = it * 64;
        const uint32_t sA = sbase + s * STAGE_BYTES2;
        const uint32_t sB = sA + TILE_BYTES2;
        #pragma unroll
        for (int l = 0; l < 4; l++) {
            int q = tid + 256 * l;
            int r = q >> 3, c = q & 7;
            CP_ASYNC16(sA + r * ROWB + c * 16,
                       (const char*)(gA + (size_t)r * 2048 + k0 + c * 8));
            CP_ASYNC16(sB + r * ROWB + c * 16,
                       (const char*)(gB + (size_t)r * 2048 + k0 + c * 8));
        }
        CP_COMMIT();
    };

    float c[4][4][4];
    #pragma unroll
    for (int i = 0; i < 4; i++)
        #pragma unroll
        for (int j = 0; j < 4; j++)
            #pragma unroll
            for (int k = 0; k < 4; k++) c[i][j][k] = 0.f;

    load_stage(0, 0);
    load_stage(1, 1);

    const int arow = (lane & 15);
    const int abyt = (lane >> 4) << 4;
    const int brow = (lane & 7) + ((lane >> 4) << 3);
    const int bbyt = ((lane >> 3) & 1) << 4;

    for (int it = 0; it < NITER; ++it) {
        const int s = it % NSTAGE;
        if (it < NITER - 1) { CP_WAIT1(); } else { CP_WAIT0(); }
        __syncthreads();
        if (it + 2 < NITER) load_stage(it + 2, (it + 2) % NSTAGE);

        const uint32_t sA = sbase + s * STAGE_BYTES2;
        const uint32_t sB = sA + TILE_BYTES2;

        #pragma unroll
        for (int ks = 0; ks < 4; ks++) {
            uint32_t af[4][4], bfr[2][4];
            #pragma unroll
            for (int fm = 0; fm < 4; fm++) {
                uint32_t ad = sA + (wm * 64 + fm * 16 + arow) * ROWB + ks * 32 + abyt;
                LDSM_X4(af[fm][0], af[fm][1], af[fm][2], af[fm][3], ad);
            }
            #pragma unroll
            for (int f2 = 0; f2 < 2; f2++) {
                uint32_t bd = sB + (wn * 32 + f2 * 16 + brow) * ROWB + ks * 32 + bbyt;
                LDSM_X4(bfr[f2][0], bfr[f2][1], bfr[f2][2], bfr[f2][3], bd);
            }
            #pragma unroll
            for (int fm = 0; fm < 4; fm++)
                #pragma unroll
                for (int fn = 0; fn < 4; fn++) {
                    uint32_t b0 = bfr[fn >> 1][(fn & 1) * 2 + 0];
                    uint32_t b1 = bfr[fn >> 1][(fn & 1) * 2 + 1];
                    mma_fp16(c[fm][fn][0], c[fm][fn][1], c[fm][fn][2], c[fm][fn][3],
                             af[fm][0], af[fm][1], af[fm][2], af[fm][3], b0, b1);
                }
        }
    }

    const bool side = (nbase >= 1024);
    const float* bsrc = side ? bq : bk;
    __half* outh = side ? g_Qh : g_Kh;
    const int colb = side ? (nbase - 1024) : nbase;

    #pragma unroll
    for (int fm = 0; fm < 4; fm++) {
        int row = mbase + wm * 64 + fm * 16 + g;
        #pragma unroll
        for (int fn = 0; fn < 4; fn++) {
            int col = colb + wn * 32 + fn * 8 + t4 * 2;
            float b0 = bsrc[col], b1 = bsrc[col + 1];
            *(__half2*)(outh + (size_t)row * 1024 + col) =
                __floats2half2_rn(c[fm][fn][0] + b0, c[fm][fn][1] + b1);
            *(__half2*)(outh + (size_t)(row + 8) * 1024 + col) =
                __floats2half2_rn(c[fm][fn][2] + b0, c[fm][fn][3] + b1);
        }
    }
}

// ---------------------------------------------------------------------------
// Gate via fp16 mma, hi/lo split. Rows processed in (b, j, i)-PERMUTED order:
// slot r' = b*10000 + j*100 + i reads gf row b*10000 + i*100 + j, so the
// output scatter g_GW[b][h][j][i] keeps contiguous 16B runs per 8 lanes.
// ---------------------------------------------------------------------------
#define GATE_ROWS 256
#define GATE_RH   72
#define ROWB_GATE 144

__global__ __launch_bounds__(256)
void gate_kernel(const float* __restrict__ gf,
                 const float* __restrict__ Wg, const float* __restrict__ bg)
{
    __shared__ __align__(16) __half sGh[GATE_ROWS * GATE_RH];
    __shared__ __align__(16) __half sGl[GATE_ROWS * GATE_RH];

    const int tid = threadIdx.x, lane = tid & 31, wid = tid >> 5;
    const int g = lane >> 2, t4 = lane & 3;
    const int rowbase = blockIdx.x * GATE_ROWS;

    // stage permuted g rows fp32 -> (hi, lo) fp16; 4096 float4 / 256 thr
    for (int v = tid; v < 4096; v += 256) {
        int r = v >> 4, c4 = (v & 15) << 2;
        int rp = rowbase + r;
        int bb = rp / 10000;
        int remp = rp - bb * 10000;                // = j*100 + i
        int jj = remp / 100;
        int ii = remp - jj * 100;
        float4 x = *(const float4*)(gf + ((size_t)bb * 10000 + ii * 100 + jj) * 64 + c4);
        float xs[4] = {x.x, x.y, x.z, x.w};
        __half hi[4], lo[4];
        #pragma unroll
        for (int e = 0; e < 4; e++) {
            hi[e] = __float2half_rn(xs[e]);
            lo[e] = __float2half_rn(xs[e] - __half2float(hi[e]));
        }
        *(uint2*)(sGh + r * GATE_RH + c4) = *(uint2*)hi;
        *(uint2*)(sGl + r * GATE_RH + c4) = *(uint2*)lo;
    }

    // B fragments (col-major B = Wg^T[n][k])
    uint32_t bh[4][2][2], bl[4][2][2];
    #pragma unroll
    for (int ks = 0; ks < 4; ks++)
        #pragma unroll
        for (int nt = 0; nt < 2; nt++) {
            int n = nt * 8 + g;
            #pragma unroll
            for (int rg = 0; rg < 2; rg++) {
                int k0 = ks * 16 + t4 * 2 + rg * 8;
                float w0 = Wg[k0 * 16 + n], w1 = Wg[(k0 + 1) * 16 + n];
                __half h0 = __float2half_rn(w0), h1 = __float2half_rn(w1);
                __half l0 = __float2half_rn(w0 - __half2float(h0));
                __half l1 = __float2half_rn(w1 - __half2float(h1));
                __half hh[2] = {h0, h1}, ll[2] = {l0, l1};
                bh[ks][nt][rg] = *(uint32_t*)hh;
                bl[ks][nt][rg] = *(uint32_t*)ll;
            }
        }
    __syncthreads();

    const uint32_t sGhb = smem_u32(sGh), sGlb = smem_u32(sGl);
    const int arow = lane & 15, abyt = (lane >> 4) << 4;
    const int wrow = wid * 32;

    #pragma unroll
    for (int mt = 0; mt < 2; mt++) {
        float c[2][4];
        #pragma unroll
        for (int nt = 0; nt < 2; nt++)
            #pragma unroll
            for (int k = 0; k < 4; k++) c[nt][k] = 0.f;

        #pragma unroll
        for (int ks = 0; ks < 4; ks++) {
            uint32_t ah[4], al[4];
            uint32_t base_off = (wrow + mt * 16 + arow) * ROWB_GATE + ks * 32 + abyt;
            LDSM_X4(ah[0], ah[1], ah[2], ah[3], sGhb + base_off);
            LDSM_X4(al[0], al[1], al[2], al[3], sGlb + base_off);
            #pragma unroll
            for (int nt = 0; nt < 2; nt++) {
                mma_fp16(c[nt][0], c[nt][1], c[nt][2], c[nt][3],
                         ah[0], ah[1], ah[2], ah[3], bh[ks][nt][0], bh[ks][nt][1]);
                mma_fp16(c[nt][0], c[nt][1], c[nt][2], c[nt][3],
                         ah[0], ah[1], ah[2], ah[3], bl[ks][nt][0], bl[ks][nt][1]);
                mma_fp16(c[nt][0], c[nt][1], c[nt][2], c[nt][3],
                         al[0], al[1], al[2], al[3], bh[ks][nt][0], bh[ks][nt][1]);
            }
        }

        // epilogue: +bias, clamp, scale, scatter to [b][h][ (j*100+i) ]
        #pragma unroll
        for (int nt = 0; nt < 2; nt++) {
            int h0 = nt * 8 + t4 * 2;
            float bb0 = bg[h0], bb1 = bg[h0 + 1];
            #pragma unroll
            for (int p = 0; p < 2; p++) {
                int row = rowbase + wrow + mt * 16 + g + p * 8;   // = r'
                int bidx = row / 10000;
                int rem  = row - bidx * 10000;                    // = j*100+i
                __half* dst = g_GW + (size_t)bidx * 160000 + rem;
                float v0 = fmaxf(c[nt][p * 2 + 0] + bb0, 1e-6f) * GW_SCALE;
                float v1 = fmaxf(c[nt][p * 2 + 1] + bb1, 1e-6f) * GW_SCALE;
                dst[(size_t)h0 * 10000]       = __float2half_rn(v0);
                dst[(size_t)(h0 + 1) * 10000] = __float2half_rn(v1);
            }
        }
    }
}

// ---------------------------------------------------------------------------
// Attention per (b,h). 512 threads (16 warps, 4x4 grid), 2 CTAs/SM.
// SMEM (bytes, total 110096):
//   region0 @0       36864  : sKh[128][144B], sQh @18432 ; reused as sVT
//                             [112 rows][272B] ([i][d] fp16) after phase 1
//   sS      @36864   42000  : [100][105] fp32
//   sPT     @78864   30720  : [128 j][240B] fp16 (P^T, scaled to [0,1])
//   sInv    @109584    512
// Phase 2 B-operand loaded from sVT[i][d] via ldmatrix.trans.
// ---------------------------------------------------------------------------
#define ATTN_SMEM_BYTES 110096

__global__ __launch_bounds__(512, 2)
void attn_kernel(const float* __restrict__ a,
                 const float* __restrict__ wsp, const float* __restrict__ bsp,
                 float* __restrict__ out)
{
    extern __shared__ __align__(16) char smc[];
    __half* sKh  = (__half*)(smc);
    __half* sQh  = (__half*)(smc + 18432);
    __half* sVT  = (__half*)(smc);                 // overlays K/Q after phase 1
    float*  sS   = (float*) (smc + 36864);
    __half* sPT  = (__half*)(smc + 78864);
    float*  sInv = (float*) (smc + 109584);

    const int h = blockIdx.x, b = blockIdx.y;
    const int tid = threadIdx.x;
    const int wid = tid >> 5, lane = tid & 31;
    const int wm = wid & 3, wn = wid >> 2;            // 4 x 4 warp grid
    const int g = lane >> 2, t4 = lane & 3;

    // ---- initial loads: K, Q (+pad), sPT pad rows ----
    const __half* Kg = g_Kh + (size_t)(b * 100) * 1024 + h * 64;
    const __half* Qg = g_Qh + (size_t)(b * 100) * 1024 + h * 64;
    for (int v = tid; v < 800; v += 512) {            // 100 rows x 8 x 16B
        int r = v >> 3, c = v & 7;
        *(uint4*)(sKh + r * 72 + c * 8) = *(const uint4*)(Kg + (size_t)r * 1024 + c * 8);
        *(uint4*)(sQh + r * 72 + c * 8) = *(const uint4*)(Qg + (size_t)r * 1024 + c * 8);
    }
    for (int v = tid; v < 224; v += 512) {            // zero K/Q pad rows 100..127
        int r = 100 + (v >> 3), c = v & 7;
        *(uint4*)(sKh + r * 72 + c * 8) = make_uint4(0, 0, 0, 0);
        *(uint4*)(sQh + r * 72 + c * 8) = make_uint4(0, 0, 0, 0);
    }
    for (int v = tid; v < 420; v += 512)              // zero sPT rows j=100..127
        ((uint4*)((char*)sPT + 24000))[v] = make_uint4(0, 0, 0, 0);
    __syncthreads();

    const int arow = lane & 15,                abyt = (lane >> 4) << 4;
    const int brow = (lane & 7) + ((lane >> 4) << 3), bbyt = ((lane >> 3) & 1) << 4;

    // ---- Phase 1: S = K.Q^T * 0.125 (warp tile 32m x 32n) ----
    {
        float c1[2][4][4];
        #pragma unroll
        for (int i = 0; i < 2; i++)
            #pragma unroll
            for (int j = 0; j < 4; j++)
                #pragma unroll
                for (int k = 0; k < 4; k++) c1[i][j][k] = 0.f;
        const uint32_t sKb = smem_u32(sKh), sQb = smem_u32(sQh);
        #pragma unroll
        for (int ks = 0; ks < 4; ks++) {
            uint32_t af[2][4], bfr[2][4];
            #pragma unroll
            for (int fm = 0; fm < 2; fm++) {
                uint32_t ad = sKb + (wm * 32 + fm * 16 + arow) * 144 + ks * 32 + abyt;
                LDSM_X4(af[fm][0], af[fm][1], af[fm][2], af[fm][3], ad);
            }
            #pragma unroll
            for (int f2 = 0; f2 < 2; f2++) {
                uint32_t bd = sQb + (wn * 32 + f2 * 16 + brow) * 144 + ks * 32 + bbyt;
                LDSM_X4(bfr[f2][0], bfr[f2][1], bfr[f2][2], bfr[f2][3], bd);
            }
            #pragma unroll
            for (int fm = 0; fm < 2; fm++)
                #pragma unroll
                for (int fn = 0; fn < 4; fn++)
                    mma_fp16(c1[fm][fn][0], c1[fm][fn][1], c1[fm][fn][2], c1[fm][fn][3],
                             af[fm][0], af[fm][1], af[fm][2], af[fm][3],
                             bfr[fn >> 1][(fn & 1) * 2], bfr[fn >> 1][(fn & 1) * 2 + 1]);
        }
        #pragma unroll
        for (int fm = 0; fm < 2; fm++) {
            int i0 = wm * 32 + fm * 16 + g;
            #pragma unroll
            for (int fn = 0; fn < 4; fn++) {
                int j0 = wn * 32 + fn * 8 + t4 * 2;
                if (j0 < 100) {
                    if (i0 < 100) {
                        sS[i0 * 105 + j0]     = c1[fm][fn][0] * 0.125f;
                        sS[i0 * 105 + j0 + 1] = c1[fm][fn][1] * 0.125f;
                    }
                    if (i0 + 8 < 100) {
                        sS[(i0 + 8) * 105 + j0]     = c1[fm][fn][2] * 0.125f;
                        sS[(i0 + 8) * 105 + j0 + 1] = c1[fm][fn][3] * 0.125f;
                    }
                }
            }
        }
    }
    __syncthreads();   // K/Q dead from here; region0 becomes sVT

    // ---- V load into sVT[i][d] fp16, stride 136 halves (272B) ----
    for (int v = tid; v < 3200; v += 512) {
        int i = v >> 5, d0 = (v & 31) << 2;
        float4 x = *(const float4*)(a + (size_t)(b * 100 + i) * 2048 + h * 128 + d0);
        __half h4[4] = {__float2half_rn(x.x), __float2half_rn(x.y),
                        __float2half_rn(x.z), __float2half_rn(x.w)};
        *(uint2*)(sVT + i * 136 + d0) = *(uint2*)h4;
    }
    for (int v = tid; v < 204; v += 512)              // zero sVT rows i=100..111
        ((uint4*)((char*)sVT + 27200))[v] = make_uint4(0, 0, 0, 0);

    // ---- softmax (warp per column j), unrolled 4 i-slots ----
    const __half* GWT = g_GW + (size_t)(b * 16 + h) * 10000;   // [j][i]
    for (int j = wid; j < 100; j += 16) {
        // prefetch gw (coalesced: lane = i)
        float g0 = __half2float(GWT[j * 100 + lane]);
        float g1 = __half2float(GWT[j * 100 + lane + 32]);
        float g2 = __half2float(GWT[j * 100 + lane + 64]);
        float g3 = (lane < 4) ? __half2float(GWT[j * 100 + lane + 96]) : 0.f;

        float s0 = sS[lane * 105 + j];
        float s1 = sS[(lane + 32) * 105 + j];
        float s2 = sS[(lane + 64) * 105 + j];
        float s3 = (lane < 4) ? sS[(lane + 96) * 105 + j] : -1e30f;

        float m = fmaxf(fmaxf(s0, s1), fmaxf(s2, s3));
        #pragma unroll
        for (int o = 16; o; o >>= 1) m = fmaxf(m, __shfl_xor_sync(~0u, m, o));

        float e0 = g0 * __expf(s0 - m);
        float e1 = g1 * __expf(s1 - m);
        float e2 = g2 * __expf(s2 - m);
        float e3 = (lane < 4) ? g3 * __expf(s3 - m) : 0.f;

        float s  = e0 + e1 + e2 + e3;
        float mx = fmaxf(fmaxf(e0, e1), fmaxf(e2, e3));
        #pragma unroll
        for (int o = 16; o; o >>= 1) {
            s  += __shfl_xor_sync(~0u, s, o);
            mx  = fmaxf(mx, __shfl_xor_sync(~0u, mx, o));
        }
        const float inv_mx = 1.f / mx;
        sPT[j * 120 + lane]      = __float2half_rn(e0 * inv_mx);
        sPT[j * 120 + lane + 32] = __float2half_rn(e1 * inv_mx);
        sPT[j * 120 + lane + 64] = __float2half_rn(e2 * inv_mx);
        if (lane < 4)  sPT[j * 120 + lane + 96]  = __float2half_rn(e3 * inv_mx);
        if (lane < 12) sPT[j * 120 + 100 + lane] = __float2half_rn(0.f);
        if (lane == 0) sInv[j] = mx / s;              // exact renormalization
    }
    __syncthreads();

    // ---- Phase 2: out = P^T · V  (m=j, k=i 112, n=d 128; warp 32j x 32d) ----
    // B from sVT[i][d] via ldmatrix.trans (k rows, n-cols in 16B groups)
    {
        float c2[2][4][4];
        #pragma unroll
        for (int i = 0; i < 2; i++)
            #pragma unroll
            for (int j = 0; j < 4; j++)
                #pragma unroll
                for (int k = 0; k < 4; k++) c2[i][j][k] = 0.f;
        const uint32_t sPb = smem_u32(sPT), sVb = smem_u32(sVT);
        #pragma unroll
        for (int ks = 0; ks < 7; ks++) {
            uint32_t af[2][4], bfr[2][4];
            #pragma unroll
            for (int fm = 0; fm < 2; fm++) {
                uint32_t ad = sPb + (wm * 32 + fm * 16 + arow) * 240 + ks * 32 + abyt;
                LDSM_X4(af[fm][0], af[fm][1], af[fm][2], af[fm][3], ad);
            }
            #pragma unroll
            for (int f2 = 0; f2 < 2; f2++) {
                uint32_t bd = sVb + (ks * 16 + (lane & 15)) * 272
                            + (wn * 32 + f2 * 16) * 2 + ((lane >> 4) << 4);
                LDSM_X4_TRANS(bfr[f2][0], bfr[f2][1], bfr[f2][2], bfr[f2][3], bd);
            }
            #pragma unroll
            for (int fm = 0; fm < 2; fm++)
                #pragma unroll
                for (int fn = 0; fn < 4; fn++)
                    mma_fp16(c2[fm][fn][0], c2[fm][fn][1], c2[fm][fn][2], c2[fm][fn][3],
                             af[fm][0], af[fm][1], af[fm][2], af[fm][3],
                             bfr[fn >> 1][(fn & 1) * 2], bfr[fn >> 1][(fn & 1) * 2 + 1]);
        }
        const float wsc = *wsp, bsc = *bsp;
        #pragma unroll
        for (int fm = 0; fm < 2; fm++) {
            int j0 = wm * 32 + fm * 16 + g;
            #pragma unroll
            for (int fn = 0; fn < 4; fn++) {
                int d0 = wn * 32 + fn * 8 + t4 * 2;
                if (j0 < 100) {
                    float sc = sInv[j0] * wsc;
                    *(float2*)(out + (size_t)(b * 100 + j0) * 2048 + h * 128 + d0) =
                        make_float2(c2[fm][fn][0] * sc + bsc, c2[fm][fn][1] * sc + bsc);
                }
                if (j0 + 8 < 100) {
                    float sc = sInv[j0 + 8] * wsc;
                    *(float2*)(out + (size_t)(b * 100 + j0 + 8) * 2048 + h * 128 + d0) =
                        make_float2(c2[fm][fn][2] * sc + bsc, c2[fm][fn][3] * sc + bsc);
                }
            }
        }
    }
}

// ---------------------------------------------------------------------------
// Launch. Inputs: a_features, g_features, split, rel_pair_counts,
// W_g, b_g, W_K, b_K, W_Q, b_Q, w_s, b_s
// ---------------------------------------------------------------------------
extern "C" void kernel_launch(void* const* d_in, const int* in_sizes, int n_in,
                              void* d_out, int out_size)
{
    (void)in_sizes; (void)n_in; (void)out_size;
    const float* a  = (const float*)d_in[0];
    const float* gf = (const float*)d_in[1];
    const float* Wg = (const float*)d_in[4];
    const float* bg = (const float*)d_in[5];
    const float* Wk = (const float*)d_in[6];
    const float* bk = (const float*)d_in[7];
    const float* Wq = (const float*)d_in[8];
    const float* bq = (const float*)d_in[9];
    const float* ws = (const float*)d_in[10];
    const float* bs = (const float*)d_in[11];
    float* out = (float*)d_out;

    cudaFuncSetAttribute(gemm_kernel, cudaFuncAttributeMaxDynamicSharedMemorySize, GEMM_SMEM);
    cudaFuncSetAttribute(attn_kernel, cudaFuncAttributeMaxDynamicSharedMemorySize,
                         ATTN_SMEM_BYTES);

    prepA_kernel<<<PP * 2048 / 1024, 256>>>(a);
    prepW_kernel<<<dim3(64, 64), 256>>>(Wk, Wq);
    gate_kernel<<<640000 / GATE_ROWS, 256>>>(gf, Wg, bg);
    gemm_kernel<<<dim3(16, 50), 256, GEMM_SMEM>>>(bk, bq);
    attn_kernel<<<dim3(16, 64), 512, ATTN_SMEM_BYTES>>>(a, ws, bs, out);
}

// round 10
// speedup vs baseline: 3.1342x; 1.0059x over previous
#include <cuda_runtime.h>
#include <cuda_fp16.h>
#include <cstdint>

// Problem constants
#define BB   64
#define NN   100
#define DD   2048
#define NRH  16
#define PP   (BB*NN)        // 6400

#define GW_SCALE 1024.0f    // uniform gate scale; cancels exactly in softmax ratio

// ---------------------------------------------------------------------------
// Scratch (__device__ globals; no allocations allowed)
// ---------------------------------------------------------------------------
__device__ __half g_Ah[PP * 2048];               // 26.2 MB  A in fp16
__device__ __half g_Wh[2048 * 2048];             // 8.4 MB   W^T fused [n][k] (Wk|Wq)
__device__ __half g_Kh[PP * 1024];               // 13.1 MB  K fp16
__device__ __half g_Qh[PP * 1024];               // 13.1 MB  Q fp16
__device__ __half g_GW[BB * NRH * NN * NN];      // 20.5 MB  gw*1024 fp16, [b][h][j][i]

__device__ __forceinline__ uint32_t smem_u32(const void* p) {
    uint32_t a;
    asm("{ .reg .u64 t; cvta.to.shared.u64 t, %1; cvt.u32.u64 %0, t; }" : "=r"(a) : "l"(p));
    return a;
}

#define CP_ASYNC16(dst, src) \
    asm volatile("cp.async.cg.shared.global [%0], [%1], 16;" :: "r"(dst), "l"(src) : "memory")
#define CP_COMMIT() asm volatile("cp.async.commit_group;" ::: "memory")
#define CP_WAIT1()  asm volatile("cp.async.wait_group 1;" ::: "memory")
#define CP_WAIT0()  asm volatile("cp.async.wait_group 0;" ::: "memory")

#define LDSM_X4(r0, r1, r2, r3, addr) \
    asm volatile("ldmatrix.sync.aligned.m8n8.x4.shared.b16 {%0,%1,%2,%3}, [%4];" \
        : "=r"(r0), "=r"(r1), "=r"(r2), "=r"(r3) : "r"(addr))

#define LDSM_X4_TRANS(r0, r1, r2, r3, addr) \
    asm volatile("ldmatrix.sync.aligned.m8n8.x4.trans.shared.b16 {%0,%1,%2,%3}, [%4];" \
        : "=r"(r0), "=r"(r1), "=r"(r2), "=r"(r3) : "r"(addr))

__device__ __forceinline__ void mma_fp16(float& c0, float& c1, float& c2, float& c3,
                                         uint32_t a0, uint32_t a1, uint32_t a2, uint32_t a3,
                                         uint32_t b0, uint32_t b1)
{
    asm volatile(
        "mma.sync.aligned.m16n8k16.row.col.f32.f16.f16.f32 "
        "{%0,%1,%2,%3}, {%4,%5,%6,%7}, {%8,%9}, {%0,%1,%2,%3};"
        : "+f"(c0), "+f"(c1), "+f"(c2), "+f"(c3)
        : "r"(a0), "r"(a1), "r"(a2), "r"(a3), "r"(b0), "r"(b1));
}

// ---------------------------------------------------------------------------
// Fused prep: blocks [0, 12800) = A fp32->fp16; [12800, 16896) = W transpose.
// ---------------------------------------------------------------------------
#define PREP_A_BLOCKS 12800
#define PREP_BLOCKS   (PREP_A_BLOCKS + 4096)

__global__ __launch_bounds__(256)
void prep_kernel(const float* __restrict__ A,
                 const float* __restrict__ Wk, const float* __restrict__ Wq)
{
    __shared__ float t[32][33];
    if (blockIdx.x < PREP_A_BLOCKS) {
        int id = blockIdx.x * 256 + threadIdx.x;   // one float4 each
        float4 v = *(const float4*)(A + (size_t)id * 4);
        __half h[4] = {__float2half_rn(v.x), __float2half_rn(v.y),
                       __float2half_rn(v.z), __float2half_rn(v.w)};
        *(uint2*)(g_Ah + (size_t)id * 4) = *(uint2*)h;
    } else {
        int bid = blockIdx.x - PREP_A_BLOCKS;      // 4096 = 64 x 64
        const int k0 = (bid & 63) * 32, n0 = (bid >> 6) * 32;
        const float* src = (n0 < 1024) ? Wk : Wq;
        const int nc0 = (n0 < 1024) ? n0 : n0 - 1024;
        const int tx = threadIdx.x & 31, ty = threadIdx.x >> 5;
        for (int r = ty; r < 32; r += 8)
            t[r][tx] = src[(k0 + r) * 1024 + nc0 + tx];
        __syncthreads();
        for (int r = ty; r < 32; r += 8)
            g_Wh[(size_t)(n0 + r) * 2048 + k0 + tx] = __float2half_rn(t[tx][r]);
    }
}

// ---------------------------------------------------------------------------
// fp16 GEMM: C[6400 x 2048] = Ah @ Wh^T (+bias)  ->  g_Kh | g_Qh (fp16)
// Tiles BM=128 BN=128 BK=64; 3-stage cp.async; 8 warps (2m x 4n), warp 64x32.
// ---------------------------------------------------------------------------
#define ROWH 72
#define ROWB 144
#define TILE_BYTES2 (128 * ROWB)                   // 18432 per operand
#define STAGE_BYTES2 (2 * TILE_BYTES2)             // 36864
#define NSTAGE 3
#define NITER  32                                  // 2048 / 64
#define GEMM_SMEM (NSTAGE * STAGE_BYTES2)          // 110592 B

__global__ __launch_bounds__(256, 2)
void gemm_kernel(const float* __restrict__ bk, const float* __restrict__ bq)
{
    extern __shared__ __align__(16) __half sm[];

    const int tid  = threadIdx.x;
    const int wid  = tid >> 5, lane = tid & 31;
    const int wm   = wid & 1,  wn   = wid >> 1;       // 2 x 4 warp grid
    const int g    = lane >> 2, t4  = lane & 3;
    const int mbase = blockIdx.y * 128;
    const int nbase = blockIdx.x * 128;

    const uint32_t sbase = smem_u32(sm);
    const __half* gA = g_Ah + (size_t)mbase * 2048;
    const __half* gB = g_Wh + (size_t)nbase * 2048;

    auto load_stage = [&](int it, int s) {
        const int k0 = it * 64;
        const uint32_t sA = sbase + s * STAGE_BYTES2;
        const uint32_t sB = sA + TILE_BYTES2;
        #pragma unroll
        for (int l = 0; l < 4; l++) {
            int q = tid + 256 * l;
            int r = q >> 3, c = q & 7;
            CP_ASYNC16(sA + r * ROWB + c * 16,
                       (const char*)(gA + (size_t)r * 2048 + k0 + c * 8));
            CP_ASYNC16(sB + r * ROWB + c * 16,
                       (const char*)(gB + (size_t)r * 2048 + k0 + c * 8));
        }
        CP_COMMIT();
    };

    float c[4][4][4];
    #pragma unroll
    for (int i = 0; i < 4; i++)
        #pragma unroll
        for (int j = 0; j < 4; j++)
            #pragma unroll
            for (int k = 0; k < 4; k++) c[i][j][k] = 0.f;

    load_stage(0, 0);
    load_stage(1, 1);

    const int arow = (lane & 15);
    const int abyt = (lane >> 4) << 4;
    const int brow = (lane & 7) + ((lane >> 4) << 3);
    const int bbyt = ((lane >> 3) & 1) << 4;

    for (int it = 0; it < NITER; ++it) {
        const int s = it % NSTAGE;
        if (it < NITER - 1) { CP_WAIT1(); } else { CP_WAIT0(); }
        __syncthreads();
        if (it + 2 < NITER) load_stage(it + 2, (it + 2) % NSTAGE);

        const uint32_t sA = sbase + s * STAGE_BYTES2;
        const uint32_t sB = sA + TILE_BYTES2;

        #pragma unroll
        for (int ks = 0; ks < 4; ks++) {
            uint32_t af[4][4], bfr[2][4];
            #pragma unroll
            for (int fm = 0; fm < 4; fm++) {
                uint32_t ad = sA + (wm * 64 + fm * 16 + arow) * ROWB + ks * 32 + abyt;
                LDSM_X4(af[fm][0], af[fm][1], af[fm][2], af[fm][3], ad);
            }
            #pragma unroll
            for (int f2 = 0; f2 < 2; f2++) {
                uint32_t bd = sB + (wn * 32 + f2 * 16 + brow) * ROWB + ks * 32 + bbyt;
                LDSM_X4(bfr[f2][0], bfr[f2][1], bfr[f2][2], bfr[f2][3], bd);
            }
            #pragma unroll
            for (int fm = 0; fm < 4; fm++)
                #pragma unroll
                for (int fn = 0; fn < 4; fn++) {
                    uint32_t b0 = bfr[fn >> 1][(fn & 1) * 2 + 0];
                    uint32_t b1 = bfr[fn >> 1][(fn & 1) * 2 + 1];
                    mma_fp16(c[fm][fn][0], c[fm][fn][1], c[fm][fn][2], c[fm][fn][3],
                             af[fm][0], af[fm][1], af[fm][2], af[fm][3], b0, b1);
                }
        }
    }

    const bool side = (nbase >= 1024);
    const float* bsrc = side ? bq : bk;
    __half* outh = side ? g_Qh : g_Kh;
    const int colb = side ? (nbase - 1024) : nbase;

    #pragma unroll
    for (int fm = 0; fm < 4; fm++) {
        int row = mbase + wm * 64 + fm * 16 + g;
        #pragma unroll
        for (int fn = 0; fn < 4; fn++) {
            int col = colb + wn * 32 + fn * 8 + t4 * 2;
            float b0 = bsrc[col], b1 = bsrc[col + 1];
            *(__half2*)(outh + (size_t)row * 1024 + col) =
                __floats2half2_rn(c[fm][fn][0] + b0, c[fm][fn][1] + b1);
            *(__half2*)(outh + (size_t)(row + 8) * 1024 + col) =
                __floats2half2_rn(c[fm][fn][2] + b0, c[fm][fn][3] + b1);
        }
    }
}

// ---------------------------------------------------------------------------
// Gate via fp16 mma, hi/lo split. Rows in (b, j, i)-PERMUTED order so the
// output scatter g_GW[b][h][j][i] keeps contiguous 16B runs per 8 lanes.
// ---------------------------------------------------------------------------
#define GATE_ROWS 256
#define GATE_RH   72
#define ROWB_GATE 144

__global__ __launch_bounds__(256)
void gate_kernel(const float* __restrict__ gf,
                 const float* __restrict__ Wg, const float* __restrict__ bg)
{
    __shared__ __align__(16) __half sGh[GATE_ROWS * GATE_RH];
    __shared__ __align__(16) __half sGl[GATE_ROWS * GATE_RH];

    const int tid = threadIdx.x, lane = tid & 31, wid = tid >> 5;
    const int g = lane >> 2, t4 = lane & 3;
    const int rowbase = blockIdx.x * GATE_ROWS;

    for (int v = tid; v < 4096; v += 256) {
        int r = v >> 4, c4 = (v & 15) << 2;
        int rp = rowbase + r;
        int bb = rp / 10000;
        int remp = rp - bb * 10000;                // = j*100 + i
        int jj = remp / 100;
        int ii = remp - jj * 100;
        float4 x = *(const float4*)(gf + ((size_t)bb * 10000 + ii * 100 + jj) * 64 + c4);
        float xs[4] = {x.x, x.y, x.z, x.w};
        __half hi[4], lo[4];
        #pragma unroll
        for (int e = 0; e < 4; e++) {
            hi[e] = __float2half_rn(xs[e]);
            lo[e] = __float2half_rn(xs[e] - __half2float(hi[e]));
        }
        *(uint2*)(sGh + r * GATE_RH + c4) = *(uint2*)hi;
        *(uint2*)(sGl + r * GATE_RH + c4) = *(uint2*)lo;
    }

    uint32_t bh[4][2][2], bl[4][2][2];
    #pragma unroll
    for (int ks = 0; ks < 4; ks++)
        #pragma unroll
        for (int nt = 0; nt < 2; nt++) {
            int n = nt * 8 + g;
            #pragma unroll
            for (int rg = 0; rg < 2; rg++) {
                int k0 = ks * 16 + t4 * 2 + rg * 8;
                float w0 = Wg[k0 * 16 + n], w1 = Wg[(k0 + 1) * 16 + n];
                __half h0 = __float2half_rn(w0), h1 = __float2half_rn(w1);
                __half l0 = __float2half_rn(w0 - __half2float(h0));
                __half l1 = __float2half_rn(w1 - __half2float(h1));
                __half hh[2] = {h0, h1}, ll[2] = {l0, l1};
                bh[ks][nt][rg] = *(uint32_t*)hh;
                bl[ks][nt][rg] = *(uint32_t*)ll;
            }
        }
    __syncthreads();

    const uint32_t sGhb = smem_u32(sGh), sGlb = smem_u32(sGl);
    const int arow = lane & 15, abyt = (lane >> 4) << 4;
    const int wrow = wid * 32;

    #pragma unroll
    for (int mt = 0; mt < 2; mt++) {
        float c[2][4];
        #pragma unroll
        for (int nt = 0; nt < 2; nt++)
            #pragma unroll
            for (int k = 0; k < 4; k++) c[nt][k] = 0.f;

        #pragma unroll
        for (int ks = 0; ks < 4; ks++) {
            uint32_t ah[4], al[4];
            uint32_t base_off = (wrow + mt * 16 + arow) * ROWB_GATE + ks * 32 + abyt;
            LDSM_X4(ah[0], ah[1], ah[2], ah[3], sGhb + base_off);
            LDSM_X4(al[0], al[1], al[2], al[3], sGlb + base_off);
            #pragma unroll
            for (int nt = 0; nt < 2; nt++) {
                mma_fp16(c[nt][0], c[nt][1], c[nt][2], c[nt][3],
                         ah[0], ah[1], ah[2], ah[3], bh[ks][nt][0], bh[ks][nt][1]);
                mma_fp16(c[nt][0], c[nt][1], c[nt][2], c[nt][3],
                         ah[0], ah[1], ah[2], ah[3], bl[ks][nt][0], bl[ks][nt][1]);
                mma_fp16(c[nt][0], c[nt][1], c[nt][2], c[nt][3],
                         al[0], al[1], al[2], al[3], bh[ks][nt][0], bh[ks][nt][1]);
            }
        }

        #pragma unroll
        for (int nt = 0; nt < 2; nt++) {
            int h0 = nt * 8 + t4 * 2;
            float bb0 = bg[h0], bb1 = bg[h0 + 1];
            #pragma unroll
            for (int p = 0; p < 2; p++) {
                int row = rowbase + wrow + mt * 16 + g + p * 8;   // = r'
                int bidx = row / 10000;
                int rem  = row - bidx * 10000;                    // = j*100+i
                __half* dst = g_GW + (size_t)bidx * 160000 + rem;
                float v0 = fmaxf(c[nt][p * 2 + 0] + bb0, 1e-6f) * GW_SCALE;
                float v1 = fmaxf(c[nt][p * 2 + 1] + bb1, 1e-6f) * GW_SCALE;
                dst[(size_t)h0 * 10000]       = __float2half_rn(v0);
                dst[(size_t)(h0 + 1) * 10000] = __float2half_rn(v1);
            }
        }
    }
}

// ---------------------------------------------------------------------------
// Attention per (b,h). 512 threads (16 warps, 4x4 grid), 2 CTAs/SM.
// SMEM (bytes, total 110096):
//   region0 @0      36864 : sKh[128][144B], sQh @18432 ; AFTER phase 1 reused
//                           as sPT [128 j][240B] fp16 (P^T scaled to [0,1])
//   sS      @36864  42000 : [100][105] fp32
//   sVT     @78864  30464 : [112 i][272B] fp16 V[i][d] -- loaded AT START so
//                           its LDGs overlap phase-1 mma
//   sInv    @109584   512
// ---------------------------------------------------------------------------
#define ATTN_SMEM_BYTES 110096

__global__ __launch_bounds__(512, 2)
void attn_kernel(const float* __restrict__ a,
                 const float* __restrict__ wsp, const float* __restrict__ bsp,
                 float* __restrict__ out)
{
    extern __shared__ __align__(16) char smc[];
    __half* sKh  = (__half*)(smc);
    __half* sQh  = (__half*)(smc + 18432);
    __half* sPT  = (__half*)(smc);                 // overlays K/Q after phase 1
    float*  sS   = (float*) (smc + 36864);
    __half* sVT  = (__half*)(smc + 78864);
    float*  sInv = (float*) (smc + 109584);

    const int h = blockIdx.x, b = blockIdx.y;
    const int tid = threadIdx.x;
    const int wid = tid >> 5, lane = tid & 31;
    const int wm = wid & 3, wn = wid >> 2;            // 4 x 4 warp grid
    const int g = lane >> 2, t4 = lane & 3;

    // ---- initial loads: K, Q (+pad) AND V (overlaps phase-1 compute) ----
    const __half* Kg = g_Kh + (size_t)(b * 100) * 1024 + h * 64;
    const __half* Qg = g_Qh + (size_t)(b * 100) * 1024 + h * 64;
    for (int v = tid; v < 800; v += 512) {            // 100 rows x 8 x 16B
        int r = v >> 3, c = v & 7;
        *(uint4*)(sKh + r * 72 + c * 8) = *(const uint4*)(Kg + (size_t)r * 1024 + c * 8);
        *(uint4*)(sQh + r * 72 + c * 8) = *(const uint4*)(Qg + (size_t)r * 1024 + c * 8);
    }
    for (int v = tid; v < 224; v += 512) {            // zero K/Q pad rows 100..127
        int r = 100 + (v >> 3), c = v & 7;
        *(uint4*)(sKh + r * 72 + c * 8) = make_uint4(0, 0, 0, 0);
        *(uint4*)(sQh + r * 72 + c * 8) = make_uint4(0, 0, 0, 0);
    }
    // V into sVT[i][d] fp16, stride 136 halves (272B)
    for (int v = tid; v < 3200; v += 512) {
        int i = v >> 5, d0 = (v & 31) << 2;
        float4 x = *(const float4*)(a + (size_t)(b * 100 + i) * 2048 + h * 128 + d0);
        __half h4[4] = {__float2half_rn(x.x), __float2half_rn(x.y),
                        __float2half_rn(x.z), __float2half_rn(x.w)};
        *(uint2*)(sVT + i * 136 + d0) = *(uint2*)h4;
    }
    for (int v = tid; v < 204; v += 512)              // zero sVT rows i=100..111
        ((uint4*)((char*)sVT + 27200))[v] = make_uint4(0, 0, 0, 0);
    __syncthreads();

    const int arow = lane & 15, abyt = (lane >> 4) << 4;
    const int brow = (lane & 7) + ((lane >> 4) << 3), bbyt = ((lane >> 3) & 1) << 4;

    // ---- Phase 1: S = K.Q^T * 0.125 (warp tile 32m x 32n) ----
    {
        float c1[2][4][4];
        #pragma unroll
        for (int i = 0; i < 2; i++)
            #pragma unroll
            for (int j = 0; j < 4; j++)
                #pragma unroll
                for (int k = 0; k < 4; k++) c1[i][j][k] = 0.f;
        const uint32_t sKb = smem_u32(sKh), sQb = smem_u32(sQh);
        #pragma unroll
        for (int ks = 0; ks < 4; ks++) {
            uint32_t af[2][4], bfr[2][4];
            #pragma unroll
            for (int fm = 0; fm < 2; fm++) {
                uint32_t ad = sKb + (wm * 32 + fm * 16 + arow) * 144 + ks * 32 + abyt;
                LDSM_X4(af[fm][0], af[fm][1], af[fm][2], af[fm][3], ad);
            }
            #pragma unroll
            for (int f2 = 0; f2 < 2; f2++) {
                uint32_t bd = sQb + (wn * 32 + f2 * 16 + brow) * 144 + ks * 32 + bbyt;
                LDSM_X4(bfr[f2][0], bfr[f2][1], bfr[f2][2], bfr[f2][3], bd);
            }
            #pragma unroll
            for (int fm = 0; fm < 2; fm++)
                #pragma unroll
                for (int fn = 0; fn < 4; fn++)
                    mma_fp16(c1[fm][fn][0], c1[fm][fn][1], c1[fm][fn][2], c1[fm][fn][3],
                             af[fm][0], af[fm][1], af[fm][2], af[fm][3],
                             bfr[fn >> 1][(fn & 1) * 2], bfr[fn >> 1][(fn & 1) * 2 + 1]);
        }
        #pragma unroll
        for (int fm = 0; fm < 2; fm++) {
            int i0 = wm * 32 + fm * 16 + g;
            #pragma unroll
            for (int fn = 0; fn < 4; fn++) {
                int j0 = wn * 32 + fn * 8 + t4 * 2;
                if (j0 < 100) {
                    if (i0 < 100) {
                        sS[i0 * 105 + j0]     = c1[fm][fn][0] * 0.125f;
                        sS[i0 * 105 + j0 + 1] = c1[fm][fn][1] * 0.125f;
                    }
                    if (i0 + 8 < 100) {
                        sS[(i0 + 8) * 105 + j0]     = c1[fm][fn][2] * 0.125f;
                        sS[(i0 + 8) * 105 + j0 + 1] = c1[fm][fn][3] * 0.125f;
                    }
                }
            }
        }
    }
    __syncthreads();   // K/Q dead from here; region0 becomes sPT

    // ---- zero sPT pad rows j=100..127 (240B each) ----
    for (int v = tid; v < 420; v += 512)
        ((uint4*)((char*)sPT + 24000))[v] = make_uint4(0, 0, 0, 0);

    // ---- softmax (warp per column j), unrolled 4 i-slots ----
    const __half* GWT = g_GW + (size_t)(b * 16 + h) * 10000;   // [j][i]
    for (int j = wid; j < 100; j += 16) {
        float g0 = __half2float(GWT[j * 100 + lane]);
        float g1 = __half2float(GWT[j * 100 + lane + 32]);
        float g2 = __half2float(GWT[j * 100 + lane + 64]);
        float g3 = (lane < 4) ? __half2float(GWT[j * 100 + lane + 96]) : 0.f;

        float s0 = sS[lane * 105 + j];
        float s1 = sS[(lane + 32) * 105 + j];
        float s2 = sS[(lane + 64) * 105 + j];
        float s3 = (lane < 4) ? sS[(lane + 96) * 105 + j] : -1e30f;

        float m = fmaxf(fmaxf(s0, s1), fmaxf(s2, s3));
        #pragma unroll
        for (int o = 16; o; o >>= 1) m = fmaxf(m, __shfl_xor_sync(~0u, m, o));

        float e0 = g0 * __expf(s0 - m);
        float e1 = g1 * __expf(s1 - m);
        float e2 = g2 * __expf(s2 - m);
        float e3 = (lane < 4) ? g3 * __expf(s3 - m) : 0.f;

        float s  = e0 + e1 + e2 + e3;
        float mx = fmaxf(fmaxf(e0, e1), fmaxf(e2, e3));
        #pragma unroll
        for (int o = 16; o; o >>= 1) {
            s  += __shfl_xor_sync(~0u, s, o);
            mx  = fmaxf(mx, __shfl_xor_sync(~0u, mx, o));
        }
        const float inv_mx = 1.f / mx;
        sPT[j * 120 + lane]      = __float2half_rn(e0 * inv_mx);
        sPT[j * 120 + lane + 32] = __float2half_rn(e1 * inv_mx);
        sPT[j * 120 + lane + 64] = __float2half_rn(e2 * inv_mx);
        if (lane < 4)  sPT[j * 120 + lane + 96]  = __float2half_rn(e3 * inv_mx);
        if (lane < 12) sPT[j * 120 + 100 + lane] = __float2half_rn(0.f);
        if (lane == 0) sInv[j] = mx / s;              // exact renormalization
    }
    __syncthreads();

    // ---- Phase 2: out = P^T · V  (m=j, k=i 112, n=d 128; warp 32j x 32d) ----
    {
        float c2[2][4][4];
        #pragma unroll
        for (int i = 0; i < 2; i++)
            #pragma unroll
            for (int j = 0; j < 4; j++)
                #pragma unroll
                for (int k = 0; k < 4; k++) c2[i][j][k] = 0.f;
        const uint32_t sPb = smem_u32(sPT), sVb = smem_u32(sVT);
        #pragma unroll
        for (int ks = 0; ks < 7; ks++) {
            uint32_t af[2][4], bfr[2][4];
            #pragma unroll
            for (int fm = 0; fm < 2; fm++) {
                uint32_t ad = sPb + (wm * 32 + fm * 16 + arow) * 240 + ks * 32 + abyt;
                LDSM_X4(af[fm][0], af[fm][1], af[fm][2], af[fm][3], ad);
            }
            #pragma unroll
            for (int f2 = 0; f2 < 2; f2++) {
                uint32_t bd = sVb + (ks * 16 + (lane & 15)) * 272
                            + (wn * 32 + f2 * 16) * 2 + ((lane >> 4) << 4);
                LDSM_X4_TRANS(bfr[f2][0], bfr[f2][1], bfr[f2][2], bfr[f2][3], bd);
            }
            #pragma unroll
            for (int fm = 0; fm < 2; fm++)
                #pragma unroll
                for (int fn = 0; fn < 4; fn++)
                    mma_fp16(c2[fm][fn][0], c2[fm][fn][1], c2[fm][fn][2], c2[fm][fn][3],
                             af[fm][0], af[fm][1], af[fm][2], af[fm][3],
                             bfr[fn >> 1][(fn & 1) * 2], bfr[fn >> 1][(fn & 1) * 2 + 1]);
        }
        const float wsc = *wsp, bsc = *bsp;
        #pragma unroll
        for (int fm = 0; fm < 2; fm++) {
            int j0 = wm * 32 + fm * 16 + g;
            #pragma unroll
            for (int fn = 0; fn < 4; fn++) {
                int d0 = wn * 32 + fn * 8 + t4 * 2;
                if (j0 < 100) {
                    float sc = sInv[j0] * wsc;
                    *(float2*)(out + (size_t)(b * 100 + j0) * 2048 + h * 128 + d0) =
                        make_float2(c2[fm][fn][0] * sc + bsc, c2[fm][fn][1] * sc + bsc);
                }
                if (j0 + 8 < 100) {
                    float sc = sInv[j0 + 8] * wsc;
                    *(float2*)(out + (size_t)(b * 100 + j0 + 8) * 2048 + h * 128 + d0) =
                        make_float2(c2[fm][fn][2] * sc + bsc, c2[fm][fn][3] * sc + bsc);
                }
            }
        }
    }
}

// ---------------------------------------------------------------------------
// Launch. Inputs: a_features, g_features, split, rel_pair_counts,
// W_g, b_g, W_K, b_K, W_Q, b_Q, w_s, b_s
// ---------------------------------------------------------------------------
extern "C" void kernel_launch(void* const* d_in, const int* in_sizes, int n_in,
                              void* d_out, int out_size)
{
    (void)in_sizes; (void)n_in; (void)out_size;
    const float* a  = (const float*)d_in[0];
    const float* gf = (const float*)d_in[1];
    const float* Wg = (const float*)d_in[4];
    const float* bg = (const float*)d_in[5];
    const float* Wk = (const float*)d_in[6];
    const float* bk = (const float*)d_in[7];
    const float* Wq = (const float*)d_in[8];
    const float* bq = (const float*)d_in[9];
    const float* ws = (const float*)d_in[10];
    const float* bs = (const float*)d_in[11];
    float* out = (float*)d_out;

    cudaFuncSetAttribute(gemm_kernel, cudaFuncAttributeMaxDynamicSharedMemorySize, GEMM_SMEM);
    cudaFuncSetAttribute(attn_kernel, cudaFuncAttributeMaxDynamicSharedMemorySize,
                         ATTN_SMEM_BYTES);

    prep_kernel<<<PREP_BLOCKS, 256>>>(a, Wk, Wq);
    gate_kernel<<<640000 / GATE_ROWS, 256>>>(gf, Wg, bg);
    gemm_kernel<<<dim3(16, 50), 256, GEMM_SMEM>>>(bk, bq);
    attn_kernel<<<dim3(16, 64), 512, ATTN_SMEM_BYTES>>>(a, ws, bs, out);
}

// round 11
// speedup vs baseline: 3.1699x; 1.0114x over previous
#include <cuda_runtime.h>
#include <cuda_fp16.h>
#include <cstdint>

// Problem constants
#define BB   64
#define NN   100
#define DD   2048
#define NRH  16
#define PP   (BB*NN)        // 6400

#define GW_SCALE 1024.0f    // uniform gate scale; cancels exactly in softmax ratio

// ---------------------------------------------------------------------------
// Scratch (__device__ globals; no allocations allowed)
// ---------------------------------------------------------------------------
__device__ __half g_Ah[PP * 2048];               // 26.2 MB  A in fp16 (also V source)
__device__ __half g_Wh[2048 * 2048];             // 8.4 MB   W^T fused [n][k] (Wk|Wq)
__device__ __half g_Kh[PP * 1024];               // 13.1 MB  K fp16
__device__ __half g_Qh[PP * 1024];               // 13.1 MB  Q fp16
__device__ __half g_GW[BB * NRH * NN * NN];      // 20.5 MB  gw*1024 fp16, [b][h][j][i]

__device__ __forceinline__ uint32_t smem_u32(const void* p) {
    uint32_t a;
    asm("{ .reg .u64 t; cvta.to.shared.u64 t, %1; cvt.u32.u64 %0, t; }" : "=r"(a) : "l"(p));
    return a;
}

#define CP_ASYNC16(dst, src) \
    asm volatile("cp.async.cg.shared.global [%0], [%1], 16;" :: "r"(dst), "l"(src) : "memory")
#define CP_COMMIT() asm volatile("cp.async.commit_group;" ::: "memory")
#define CP_WAIT1()  asm volatile("cp.async.wait_group 1;" ::: "memory")
#define CP_WAIT0()  asm volatile("cp.async.wait_group 0;" ::: "memory")

#define LDSM_X4(r0, r1, r2, r3, addr) \
    asm volatile("ldmatrix.sync.aligned.m8n8.x4.shared.b16 {%0,%1,%2,%3}, [%4];" \
        : "=r"(r0), "=r"(r1), "=r"(r2), "=r"(r3) : "r"(addr))

#define LDSM_X4_TRANS(r0, r1, r2, r3, addr) \
    asm volatile("ldmatrix.sync.aligned.m8n8.x4.trans.shared.b16 {%0,%1,%2,%3}, [%4];" \
        : "=r"(r0), "=r"(r1), "=r"(r2), "=r"(r3) : "r"(addr))

__device__ __forceinline__ void mma_fp16(float& c0, float& c1, float& c2, float& c3,
                                         uint32_t a0, uint32_t a1, uint32_t a2, uint32_t a3,
                                         uint32_t b0, uint32_t b1)
{
    asm volatile(
        "mma.sync.aligned.m16n8k16.row.col.f32.f16.f16.f32 "
        "{%0,%1,%2,%3}, {%4,%5,%6,%7}, {%8,%9}, {%0,%1,%2,%3};"
        : "+f"(c0), "+f"(c1), "+f"(c2), "+f"(c3)
        : "r"(a0), "r"(a1), "r"(a2), "r"(a3), "r"(b0), "r"(b1));
}

// ---------------------------------------------------------------------------
// Fused prep: blocks [0, 12800) = A fp32->fp16; [12800, 16896) = W transpose.
// ---------------------------------------------------------------------------
#define PREP_A_BLOCKS 12800
#define PREP_BLOCKS   (PREP_A_BLOCKS + 4096)

__global__ __launch_bounds__(256)
void prep_kernel(const float* __restrict__ A,
                 const float* __restrict__ Wk, const float* __restrict__ Wq)
{
    __shared__ float t[32][33];
    if (blockIdx.x < PREP_A_BLOCKS) {
        int id = blockIdx.x * 256 + threadIdx.x;   // one float4 each
        float4 v = *(const float4*)(A + (size_t)id * 4);
        __half h[4] = {__float2half_rn(v.x), __float2half_rn(v.y),
                       __float2half_rn(v.z), __float2half_rn(v.w)};
        *(uint2*)(g_Ah + (size_t)id * 4) = *(uint2*)h;
    } else {
        int bid = blockIdx.x - PREP_A_BLOCKS;      // 4096 = 64 x 64
        const int k0 = (bid & 63) * 32, n0 = (bid >> 6) * 32;
        const float* src = (n0 < 1024) ? Wk : Wq;
        const int nc0 = (n0 < 1024) ? n0 : n0 - 1024;
        const int tx = threadIdx.x & 31, ty = threadIdx.x >> 5;
        for (int r = ty; r < 32; r += 8)
            t[r][tx] = src[(k0 + r) * 1024 + nc0 + tx];
        __syncthreads();
        for (int r = ty; r < 32; r += 8)
            g_Wh[(size_t)(n0 + r) * 2048 + k0 + tx] = __float2half_rn(t[tx][r]);
    }
}

// ---------------------------------------------------------------------------
// Fused GEMM + gate kernel.
//   Blocks [0, 800): fp16 GEMM tile (BM=128 BN=128 BK=64, 3-stage cp.async)
//   Blocks [800, 3300): gate chunk (256 rows, fp16 mma hi/lo split)
// Gate blocks backfill GEMM's tail wave; gate is DRAM-bound, GEMM tensor-bound.
// ---------------------------------------------------------------------------
#define ROWH 72
#define ROWB 144
#define TILE_BYTES2 (128 * ROWB)                   // 18432 per operand
#define STAGE_BYTES2 (2 * TILE_BYTES2)             // 36864
#define NSTAGE 3
#define NITER  32                                  // 2048 / 64
#define GEMM_SMEM (NSTAGE * STAGE_BYTES2)          // 110592 B

#define GEMM_BLOCKS 800
#define GATE_ROWS 256
#define GATE_RH   72
#define ROWB_GATE 144
#define GATE_BLOCKS (640000 / GATE_ROWS)           // 2500
#define GG_BLOCKS (GEMM_BLOCKS + GATE_BLOCKS)      // 3300

__device__ __forceinline__ void gemm_body(char* dynsm, int bid,
                                          const float* __restrict__ bk,
                                          const float* __restrict__ bq)
{
    const int tid  = threadIdx.x;
    const int wid  = tid >> 5, lane = tid & 31;
    const int wm   = wid & 1,  wn   = wid >> 1;       // 2 x 4 warp grid
    const int g    = lane >> 2, t4  = lane & 3;
    const int mbase = (bid >> 4) * 128;
    const int nbase = (bid & 15) * 128;

    const uint32_t sbase = smem_u32(dynsm);
    const __half* gA = g_Ah + (size_t)mbase * 2048;
    const __half* gB = g_Wh + (size_t)nbase * 2048;

    auto load_stage = [&](int it, int s) {
        const int k0 = it * 64;
        const uint32_t sA = sbase + s * STAGE_BYTES2;
        const uint32_t sB = sA + TILE_BYTES2;
        #pragma unroll
        for (int l = 0; l < 4; l++) {
            int q = tid + 256 * l;
            int r = q >> 3, c = q & 7;
            CP_ASYNC16(sA + r * ROWB + c * 16,
                       (const char*)(gA + (size_t)r * 2048 + k0 + c * 8));
            CP_ASYNC16(sB + r * ROWB + c * 16,
                       (const char*)(gB + (size_t)r * 2048 + k0 + c * 8));
        }
        CP_COMMIT();
    };

    float c[4][4][4];
    #pragma unroll
    for (int i = 0; i < 4; i++)
        #pragma unroll
        for (int j = 0; j < 4; j++)
            #pragma unroll
            for (int k = 0; k < 4; k++) c[i][j][k] = 0.f;

    load_stage(0, 0);
    load_stage(1, 1);

    const int arow = (lane & 15);
    const int abyt = (lane >> 4) << 4;
    const int brow = (lane & 7) + ((lane >> 4) << 3);
    const int bbyt = ((lane >> 3) & 1) << 4;

    for (int it = 0; it < NITER; ++it) {
        const int s = it % NSTAGE;
        if (it < NITER - 1) { CP_WAIT1(); } else { CP_WAIT0(); }
        __syncthreads();
        if (it + 2 < NITER) load_stage(it + 2, (it + 2) % NSTAGE);

        const uint32_t sA = sbase + s * STAGE_BYTES2;
        const uint32_t sB = sA + TILE_BYTES2;

        #pragma unroll
        for (int ks = 0; ks < 4; ks++) {
            uint32_t af[4][4], bfr[2][4];
            #pragma unroll
            for (int fm = 0; fm < 4; fm++) {
                uint32_t ad = sA + (wm * 64 + fm * 16 + arow) * ROWB + ks * 32 + abyt;
                LDSM_X4(af[fm][0], af[fm][1], af[fm][2], af[fm][3], ad);
            }
            #pragma unroll
            for (int f2 = 0; f2 < 2; f2++) {
                uint32_t bd = sB + (wn * 32 + f2 * 16 + brow) * ROWB + ks * 32 + bbyt;
                LDSM_X4(bfr[f2][0], bfr[f2][1], bfr[f2][2], bfr[f2][3], bd);
            }
            #pragma unroll
            for (int fm = 0; fm < 4; fm++)
                #pragma unroll
                for (int fn = 0; fn < 4; fn++) {
                    uint32_t b0 = bfr[fn >> 1][(fn & 1) * 2 + 0];
                    uint32_t b1 = bfr[fn >> 1][(fn & 1) * 2 + 1];
                    mma_fp16(c[fm][fn][0], c[fm][fn][1], c[fm][fn][2], c[fm][fn][3],
                             af[fm][0], af[fm][1], af[fm][2], af[fm][3], b0, b1);
                }
        }
    }

    const bool side = (nbase >= 1024);
    const float* bsrc = side ? bq : bk;
    __half* outh = side ? g_Qh : g_Kh;
    const int colb = side ? (nbase - 1024) : nbase;

    #pragma unroll
    for (int fm = 0; fm < 4; fm++) {
        int row = mbase + wm * 64 + fm * 16 + g;
        #pragma unroll
        for (int fn = 0; fn < 4; fn++) {
            int col = colb + wn * 32 + fn * 8 + t4 * 2;
            float b0 = bsrc[col], b1 = bsrc[col + 1];
            *(__half2*)(outh + (size_t)row * 1024 + col) =
                __floats2half2_rn(c[fm][fn][0] + b0, c[fm][fn][1] + b1);
            *(__half2*)(outh + (size_t)(row + 8) * 1024 + col) =
                __floats2half2_rn(c[fm][fn][2] + b0, c[fm][fn][3] + b1);
        }
    }
}

__device__ __forceinline__ void gate_body(char* dynsm, int bid,
                                          const float* __restrict__ gf,
                                          const float* __restrict__ Wg,
                                          const float* __restrict__ bg)
{
    __half* sGh = (__half*)dynsm;
    __half* sGl = sGh + GATE_ROWS * GATE_RH;       // 73728 B total < 110592

    const int tid = threadIdx.x, lane = tid & 31, wid = tid >> 5;
    const int g = lane >> 2, t4 = lane & 3;
    const int rowbase = bid * GATE_ROWS;

    // stage permuted g rows fp32 -> (hi, lo) fp16; slot r' = b,j,i order
    for (int v = tid; v < 4096; v += 256) {
        int r = v >> 4, c4 = (v & 15) << 2;
        int rp = rowbase + r;
        int bb = rp / 10000;
        int remp = rp - bb * 10000;                // = j*100 + i
        int jj = remp / 100;
        int ii = remp - jj * 100;
        float4 x = *(const float4*)(gf + ((size_t)bb * 10000 + ii * 100 + jj) * 64 + c4);
        float xs[4] = {x.x, x.y, x.z, x.w};
        __half hi[4], lo[4];
        #pragma unroll
        for (int e = 0; e < 4; e++) {
            hi[e] = __float2half_rn(xs[e]);
            lo[e] = __float2half_rn(xs[e] - __half2float(hi[e]));
        }
        *(uint2*)(sGh + r * GATE_RH + c4) = *(uint2*)hi;
        *(uint2*)(sGl + r * GATE_RH + c4) = *(uint2*)lo;
    }

    // B fragments (col-major B = Wg^T[n][k])
    uint32_t bh[4][2][2], bl[4][2][2];
    #pragma unroll
    for (int ks = 0; ks < 4; ks++)
        #pragma unroll
        for (int nt = 0; nt < 2; nt++) {
            int n = nt * 8 + g;
            #pragma unroll
            for (int rg = 0; rg < 2; rg++) {
                int k0 = ks * 16 + t4 * 2 + rg * 8;
                float w0 = Wg[k0 * 16 + n], w1 = Wg[(k0 + 1) * 16 + n];
                __half h0 = __float2half_rn(w0), h1 = __float2half_rn(w1);
                __half l0 = __float2half_rn(w0 - __half2float(h0));
                __half l1 = __float2half_rn(w1 - __half2float(h1));
                __half hh[2] = {h0, h1}, ll[2] = {l0, l1};
                bh[ks][nt][rg] = *(uint32_t*)hh;
                bl[ks][nt][rg] = *(uint32_t*)ll;
            }
        }
    __syncthreads();

    const uint32_t sGhb = smem_u32(sGh), sGlb = smem_u32(sGl);
    const int arow = lane & 15, abyt = (lane >> 4) << 4;
    const int wrow = wid * 32;

    #pragma unroll
    for (int mt = 0; mt < 2; mt++) {
        float c[2][4];
        #pragma unroll
        for (int nt = 0; nt < 2; nt++)
            #pragma unroll
            for (int k = 0; k < 4; k++) c[nt][k] = 0.f;

        #pragma unroll
        for (int ks = 0; ks < 4; ks++) {
            uint32_t ah[4], al[4];
            uint32_t base_off = (wrow + mt * 16 + arow) * ROWB_GATE + ks * 32 + abyt;
            LDSM_X4(ah[0], ah[1], ah[2], ah[3], sGhb + base_off);
            LDSM_X4(al[0], al[1], al[2], al[3], sGlb + base_off);
            #pragma unroll
            for (int nt = 0; nt < 2; nt++) {
                mma_fp16(c[nt][0], c[nt][1], c[nt][2], c[nt][3],
                         ah[0], ah[1], ah[2], ah[3], bh[ks][nt][0], bh[ks][nt][1]);
                mma_fp16(c[nt][0], c[nt][1], c[nt][2], c[nt][3],
                         ah[0], ah[1], ah[2], ah[3], bl[ks][nt][0], bl[ks][nt][1]);
                mma_fp16(c[nt][0], c[nt][1], c[nt][2], c[nt][3],
                         al[0], al[1], al[2], al[3], bh[ks][nt][0], bh[ks][nt][1]);
            }
        }

        #pragma unroll
        for (int nt = 0; nt < 2; nt++) {
            int h0 = nt * 8 + t4 * 2;
            float bb0 = bg[h0], bb1 = bg[h0 + 1];
            #pragma unroll
            for (int p = 0; p < 2; p++) {
                int row = rowbase + wrow + mt * 16 + g + p * 8;   // = r'
                int bidx = row / 10000;
                int rem  = row - bidx * 10000;                    // = j*100+i
                __half* dst = g_GW + (size_t)bidx * 160000 + rem;
                float v0 = fmaxf(c[nt][p * 2 + 0] + bb0, 1e-6f) * GW_SCALE;
                float v1 = fmaxf(c[nt][p * 2 + 1] + bb1, 1e-6f) * GW_SCALE;
                dst[(size_t)h0 * 10000]       = __float2half_rn(v0);
                dst[(size_t)(h0 + 1) * 10000] = __float2half_rn(v1);
            }
        }
    }
}

__global__ __launch_bounds__(256, 2)
void gg_kernel(const float* __restrict__ bk, const float* __restrict__ bq,
               const float* __restrict__ gf, const float* __restrict__ Wg,
               const float* __restrict__ bg)
{
    extern __shared__ __align__(16) char dynsm[];
    if (blockIdx.x < GEMM_BLOCKS) gemm_body(dynsm, blockIdx.x, bk, bq);
    else                          gate_body(dynsm, blockIdx.x - GEMM_BLOCKS, gf, Wg, bg);
}

// ---------------------------------------------------------------------------
// Attention per (b,h). 512 threads (16 warps, 4x4 grid), 2 CTAs/SM.
// V now read from g_Ah (fp16) -- identical values, half the DRAM traffic.
// SMEM (bytes, total 110096):
//   region0 @0      36864 : sKh[128][144B], sQh @18432 ; reused as sPT after
//                           phase 1 ([128 j][240B] fp16, P^T scaled to [0,1])
//   sS      @36864  42000 : [100][105] fp32
//   sVT     @78864  30464 : [112 i][272B] fp16 V[i][d], loaded at start
//   sInv    @109584   512
// ---------------------------------------------------------------------------
#define ATTN_SMEM_BYTES 110096

__global__ __launch_bounds__(512, 2)
void attn_kernel(const float* __restrict__ wsp, const float* __restrict__ bsp,
                 float* __restrict__ out)
{
    extern __shared__ __align__(16) char smc[];
    __half* sKh  = (__half*)(smc);
    __half* sQh  = (__half*)(smc + 18432);
    __half* sPT  = (__half*)(smc);                 // overlays K/Q after phase 1
    float*  sS   = (float*) (smc + 36864);
    __half* sVT  = (__half*)(smc + 78864);
    float*  sInv = (float*) (smc + 109584);

    const int h = blockIdx.x, b = blockIdx.y;
    const int tid = threadIdx.x;
    const int wid = tid >> 5, lane = tid & 31;
    const int wm = wid & 3, wn = wid >> 2;            // 4 x 4 warp grid
    const int g = lane >> 2, t4 = lane & 3;

    // ---- initial loads: K, Q (+pad) AND V (overlaps phase-1 compute) ----
    const __half* Kg = g_Kh + (size_t)(b * 100) * 1024 + h * 64;
    const __half* Qg = g_Qh + (size_t)(b * 100) * 1024 + h * 64;
    for (int v = tid; v < 800; v += 512) {            // 100 rows x 8 x 16B
        int r = v >> 3, c = v & 7;
        *(uint4*)(sKh + r * 72 + c * 8) = *(const uint4*)(Kg + (size_t)r * 1024 + c * 8);
        *(uint4*)(sQh + r * 72 + c * 8) = *(const uint4*)(Qg + (size_t)r * 1024 + c * 8);
    }
    for (int v = tid; v < 224; v += 512) {            // zero K/Q pad rows 100..127
        int r = 100 + (v >> 3), c = v & 7;
        *(uint4*)(sKh + r * 72 + c * 8) = make_uint4(0, 0, 0, 0);
        *(uint4*)(sQh + r * 72 + c * 8) = make_uint4(0, 0, 0, 0);
    }
    // V from g_Ah (fp16): 100 rows x 16 chunks of 8 halves (16B)
    const __half* Vg = g_Ah + (size_t)(b * 100) * 2048 + h * 128;
    for (int v = tid; v < 1600; v += 512) {
        int i = v >> 4, c = v & 15;
        *(uint4*)(sVT + i * 136 + c * 8) = *(const uint4*)(Vg + (size_t)i * 2048 + c * 8);
    }
    for (int v = tid; v < 204; v += 512)              // zero sVT rows i=100..111
        ((uint4*)((char*)sVT + 27200))[v] = make_uint4(0, 0, 0, 0);
    __syncthreads();

    const int arow = lane & 15, abyt = (lane >> 4) << 4;
    const int brow = (lane & 7) + ((lane >> 4) << 3), bbyt = ((lane >> 3) & 1) << 4;

    // ---- Phase 1: S = K.Q^T * 0.125 (warp tile 32m x 32n) ----
    {
        float c1[2][4][4];
        #pragma unroll
        for (int i = 0; i < 2; i++)
            #pragma unroll
            for (int j = 0; j < 4; j++)
                #pragma unroll
                for (int k = 0; k < 4; k++) c1[i][j][k] = 0.f;
        const uint32_t sKb = smem_u32(sKh), sQb = smem_u32(sQh);
        #pragma unroll
        for (int ks = 0; ks < 4; ks++) {
            uint32_t af[2][4], bfr[2][4];
            #pragma unroll
            for (int fm = 0; fm < 2; fm++) {
                uint32_t ad = sKb + (wm * 32 + fm * 16 + arow) * 144 + ks * 32 + abyt;
                LDSM_X4(af[fm][0], af[fm][1], af[fm][2], af[fm][3], ad);
            }
            #pragma unroll
            for (int f2 = 0; f2 < 2; f2++) {
                uint32_t bd = sQb + (wn * 32 + f2 * 16 + brow) * 144 + ks * 32 + bbyt;
                LDSM_X4(bfr[f2][0], bfr[f2][1], bfr[f2][2], bfr[f2][3], bd);
            }
            #pragma unroll
            for (int fm = 0; fm < 2; fm++)
                #pragma unroll
                for (int fn = 0; fn < 4; fn++)
                    mma_fp16(c1[fm][fn][0], c1[fm][fn][1], c1[fm][fn][2], c1[fm][fn][3],
                             af[fm][0], af[fm][1], af[fm][2], af[fm][3],
                             bfr[fn >> 1][(fn & 1) * 2], bfr[fn >> 1][(fn & 1) * 2 + 1]);
        }
        #pragma unroll
        for (int fm = 0; fm < 2; fm++) {
            int i0 = wm * 32 + fm * 16 + g;
            #pragma unroll
            for (int fn = 0; fn < 4; fn++) {
                int j0 = wn * 32 + fn * 8 + t4 * 2;
                if (j0 < 100) {
                    if (i0 < 100) {
                        sS[i0 * 105 + j0]     = c1[fm][fn][0] * 0.125f;
                        sS[i0 * 105 + j0 + 1] = c1[fm][fn][1] * 0.125f;
                    }
                    if (i0 + 8 < 100) {
                        sS[(i0 + 8) * 105 + j0]     = c1[fm][fn][2] * 0.125f;
                        sS[(i0 + 8) * 105 + j0 + 1] = c1[fm][fn][3] * 0.125f;
                    }
                }
            }
        }
    }
    __syncthreads();   // K/Q dead from here; region0 becomes sPT

    // ---- zero sPT pad rows j=100..127 (240B each) ----
    for (int v = tid; v < 420; v += 512)
        ((uint4*)((char*)sPT + 24000))[v] = make_uint4(0, 0, 0, 0);

    // ---- softmax (warp per column j), unrolled 4 i-slots ----
    const __half* GWT = g_GW + (size_t)(b * 16 + h) * 10000;   // [j][i]
    for (int j = wid; j < 100; j += 16) {
        float g0 = __half2float(GWT[j * 100 + lane]);
        float g1 = __half2float(GWT[j * 100 + lane + 32]);
        float g2 = __half2float(GWT[j * 100 + lane + 64]);
        float g3 = (lane < 4) ? __half2float(GWT[j * 100 + lane + 96]) : 0.f;

        float s0 = sS[lane * 105 + j];
        float s1 = sS[(lane + 32) * 105 + j];
        float s2 = sS[(lane + 64) * 105 + j];
        float s3 = (lane < 4) ? sS[(lane + 96) * 105 + j] : -1e30f;

        float m = fmaxf(fmaxf(s0, s1), fmaxf(s2, s3));
        #pragma unroll
        for (int o = 16; o; o >>= 1) m = fmaxf(m, __shfl_xor_sync(~0u, m, o));

        float e0 = g0 * __expf(s0 - m);
        float e1 = g1 * __expf(s1 - m);
        float e2 = g2 * __expf(s2 - m);
        float e3 = (lane < 4) ? g3 * __expf(s3 - m) : 0.f;

        float s  = e0 + e1 + e2 + e3;
        float mx = fmaxf(fmaxf(e0, e1), fmaxf(e2, e3));
        #pragma unroll
        for (int o = 16; o; o >>= 1) {
            s  += __shfl_xor_sync(~0u, s, o);
            mx  = fmaxf(mx, __shfl_xor_sync(~0u, mx, o));
        }
        const float inv_mx = 1.f / mx;
        sPT[j * 120 + lane]      = __float2half_rn(e0 * inv_mx);
        sPT[j * 120 + lane + 32] = __float2half_rn(e1 * inv_mx);
        sPT[j * 120 + lane + 64] = __float2half_rn(e2 * inv_mx);
        if (lane < 4)  sPT[j * 120 + lane + 96]  = __float2half_rn(e3 * inv_mx);
        if (lane < 12) sPT[j * 120 + 100 + lane] = __float2half_rn(0.f);
        if (lane == 0) sInv[j] = mx / s;              // exact renormalization
    }
    __syncthreads();

    // ---- Phase 2: out = P^T · V  (m=j, k=i 112, n=d 128; warp 32j x 32d) ----
    {
        float c2[2][4][4];
        #pragma unroll
        for (int i = 0; i < 2; i++)
            #pragma unroll
            for (int j = 0; j < 4; j++)
                #pragma unroll
                for (int k = 0; k < 4; k++) c2[i][j][k] = 0.f;
        const uint32_t sPb = smem_u32(sPT), sVb = smem_u32(sVT);
        #pragma unroll
        for (int ks = 0; ks < 7; ks++) {
            uint32_t af[2][4], bfr[2][4];
            #pragma unroll
            for (int fm = 0; fm < 2; fm++) {
                uint32_t ad = sPb + (wm * 32 + fm * 16 + arow) * 240 + ks * 32 + abyt;
                LDSM_X4(af[fm][0], af[fm][1], af[fm][2], af[fm][3], ad);
            }
            #pragma unroll
            for (int f2 = 0; f2 < 2; f2++) {
                uint32_t bd = sVb + (ks * 16 + (lane & 15)) * 272
                            + (wn * 32 + f2 * 16) * 2 + ((lane >> 4) << 4);
                LDSM_X4_TRANS(bfr[f2][0], bfr[f2][1], bfr[f2][2], bfr[f2][3], bd);
            }
            #pragma unroll
            for (int fm = 0; fm < 2; fm++)
                #pragma unroll
                for (int fn = 0; fn < 4; fn++)
                    mma_fp16(c2[fm][fn][0], c2[fm][fn][1], c2[fm][fn][2], c2[fm][fn][3],
                             af[fm][0], af[fm][1], af[fm][2], af[fm][3],
                             bfr[fn >> 1][(fn & 1) * 2], bfr[fn >> 1][(fn & 1) * 2 + 1]);
        }
        const float wsc = *wsp, bsc = *bsp;
        #pragma unroll
        for (int fm = 0; fm < 2; fm++) {
            int j0 = wm * 32 + fm * 16 + g;
            #pragma unroll
            for (int fn = 0; fn < 4; fn++) {
                int d0 = wn * 32 + fn * 8 + t4 * 2;
                if (j0 < 100) {
                    float sc = sInv[j0] * wsc;
                    *(float2*)(out + (size_t)(b * 100 + j0) * 2048 + h * 128 + d0) =
                        make_float2(c2[fm][fn][0] * sc + bsc, c2[fm][fn][1] * sc + bsc);
                }
                if (j0 + 8 < 100) {
                    float sc = sInv[j0 + 8] * wsc;
                    *(float2*)(out + (size_t)(b * 100 + j0 + 8) * 2048 + h * 128 + d0) =
                        make_float2(c2[fm][fn][2] * sc + bsc, c2[fm][fn][3] * sc + bsc);
                }
            }
        }
    }
}

// ---------------------------------------------------------------------------
// Launch. Inputs: a_features, g_features, split, rel_pair_counts,
// W_g, b_g, W_K, b_K, W_Q, b_Q, w_s, b_s
// ---------------------------------------------------------------------------
extern "C" void kernel_launch(void* const* d_in, const int* in_sizes, int n_in,
                              void* d_out, int out_size)
{
    (void)in_sizes; (void)n_in; (void)out_size;
    const float* a  = (const float*)d_in[0];
    const float* gf = (const float*)d_in[1];
    const float* Wg = (const float*)d_in[4];
    const float* bg = (const float*)d_in[5];
    const float* Wk = (const float*)d_in[6];
    const float* bk = (const float*)d_in[7];
    const float* Wq = (const float*)d_in[8];
    const float* bq = (const float*)d_in[9];
    const float* ws = (const float*)d_in[10];
    const float* bs = (const float*)d_in[11];
    float* out = (float*)d_out;

    cudaFuncSetAttribute(gg_kernel, cudaFuncAttributeMaxDynamicSharedMemorySize, GEMM_SMEM);
    cudaFuncSetAttribute(attn_kernel, cudaFuncAttributeMaxDynamicSharedMemorySize,
                         ATTN_SMEM_BYTES);

    prep_kernel<<<PREP_BLOCKS, 256>>>(a, Wk, Wq);
    gg_kernel<<<GG_BLOCKS, 256, GEMM_SMEM>>>(bk, bq, gf, Wg, bg);
    attn_kernel<<<dim3(16, 64), 512, ATTN_SMEM_BYTES>>>(ws, bs, out);
}

// round 12
// speedup vs baseline: 3.6211x; 1.1423x over previous
#include <cuda_runtime.h>
#include <cuda_fp16.h>
#include <cstdint>

// Problem constants
#define BB   64
#define NN   100
#define DD   2048
#define NRH  16
#define PP   (BB*NN)        // 6400

#define GW_SCALE 1024.0f    // uniform gate scale; cancels exactly in softmax ratio

// ---------------------------------------------------------------------------
// Scratch (__device__ globals; no allocations allowed)
// ---------------------------------------------------------------------------
__device__ __half g_Ah[PP * 2048];               // 26.2 MB  A in fp16 (also V source)
__device__ __half g_Wh[2048 * 2048];             // 8.4 MB   W^T fused [n][k] (Wk|Wq)
__device__ __half g_Kh[PP * 1024];               // 13.1 MB  K fp16
__device__ __half g_Qh[PP * 1024];               // 13.1 MB  Q fp16
__device__ __half g_GW[BB * NRH * NN * NN];      // 20.5 MB  gw*1024 fp16, [b][h][j][i]

__device__ __forceinline__ uint32_t smem_u32(const void* p) {
    uint32_t a;
    asm("{ .reg .u64 t; cvta.to.shared.u64 t, %1; cvt.u32.u64 %0, t; }" : "=r"(a) : "l"(p));
    return a;
}

#define CP_ASYNC16(dst, src) \
    asm volatile("cp.async.cg.shared.global [%0], [%1], 16;" :: "r"(dst), "l"(src) : "memory")
#define CP_COMMIT() asm volatile("cp.async.commit_group;" ::: "memory")
#define CP_WAIT1()  asm volatile("cp.async.wait_group 1;" ::: "memory")
#define CP_WAIT0()  asm volatile("cp.async.wait_group 0;" ::: "memory")

// Non-volatile: barriers fence smem ordering; lets ptxas interleave with mma.
#define LDSM_X4(r0, r1, r2, r3, addr) \
    asm("ldmatrix.sync.aligned.m8n8.x4.shared.b16 {%0,%1,%2,%3}, [%4];" \
        : "=r"(r0), "=r"(r1), "=r"(r2), "=r"(r3) : "r"(addr))

#define LDSM_X4_TRANS(r0, r1, r2, r3, addr) \
    asm("ldmatrix.sync.aligned.m8n8.x4.trans.shared.b16 {%0,%1,%2,%3}, [%4];" \
        : "=r"(r0), "=r"(r1), "=r"(r2), "=r"(r3) : "r"(addr))

__device__ __forceinline__ void mma_fp16(float& c0, float& c1, float& c2, float& c3,
                                         uint32_t a0, uint32_t a1, uint32_t a2, uint32_t a3,
                                         uint32_t b0, uint32_t b1)
{
    asm("mma.sync.aligned.m16n8k16.row.col.f32.f16.f16.f32 "
        "{%0,%1,%2,%3}, {%4,%5,%6,%7}, {%8,%9}, {%0,%1,%2,%3};"
        : "+f"(c0), "+f"(c1), "+f"(c2), "+f"(c3)
        : "r"(a0), "r"(a1), "r"(a2), "r"(a3), "r"(b0), "r"(b1));
}

// ---------------------------------------------------------------------------
// Fused prep: blocks [0, 12800) = A fp32->fp16; [12800, 16896) = W transpose.
// ---------------------------------------------------------------------------
#define PREP_A_BLOCKS 12800
#define PREP_BLOCKS   (PREP_A_BLOCKS + 4096)

__global__ __launch_bounds__(256)
void prep_kernel(const float* __restrict__ A,
                 const float* __restrict__ Wk, const float* __restrict__ Wq)
{
    __shared__ float t[32][33];
    if (blockIdx.x < PREP_A_BLOCKS) {
        int id = blockIdx.x * 256 + threadIdx.x;   // one float4 each
        float4 v = *(const float4*)(A + (size_t)id * 4);
        __half h[4] = {__float2half_rn(v.x), __float2half_rn(v.y),
                       __float2half_rn(v.z), __float2half_rn(v.w)};
        *(uint2*)(g_Ah + (size_t)id * 4) = *(uint2*)h;
    } else {
        int bid = blockIdx.x - PREP_A_BLOCKS;      // 4096 = 64 x 64
        const int k0 = (bid & 63) * 32, n0 = (bid >> 6) * 32;
        const float* src = (n0 < 1024) ? Wk : Wq;
        const int nc0 = (n0 < 1024) ? n0 : n0 - 1024;
        const int tx = threadIdx.x & 31, ty = threadIdx.x >> 5;
        for (int r = ty; r < 32; r += 8)
            t[r][tx] = src[(k0 + r) * 1024 + nc0 + tx];
        __syncthreads();
        for (int r = ty; r < 32; r += 8)
            g_Wh[(size_t)(n0 + r) * 2048 + k0 + tx] = __float2half_rn(t[tx][r]);
    }
}

// ---------------------------------------------------------------------------
// fp16 GEMM: C[6400 x 2048] = Ah @ Wh^T (+bias)  ->  g_Kh | g_Qh (fp16)
// Tiles BM=128 BN=128 BK=64; 3-stage cp.async; 8 warps (2m x 4n), warp 64x32.
// ---------------------------------------------------------------------------
#define ROWH 72
#define ROWB 144
#define TILE_BYTES2 (128 * ROWB)                   // 18432 per operand
#define STAGE_BYTES2 (2 * TILE_BYTES2)             // 36864
#define NSTAGE 3
#define NITER  32                                  // 2048 / 64
#define GEMM_SMEM (NSTAGE * STAGE_BYTES2)          // 110592 B

__global__ __launch_bounds__(256, 2)
void gemm_kernel(const float* __restrict__ bk, const float* __restrict__ bq)
{
    extern __shared__ __align__(16) __half sm[];

    const int tid  = threadIdx.x;
    const int wid  = tid >> 5, lane = tid & 31;
    const int wm   = wid & 1,  wn   = wid >> 1;       // 2 x 4 warp grid
    const int g    = lane >> 2, t4  = lane & 3;
    const int mbase = blockIdx.y * 128;
    const int nbase = blockIdx.x * 128;

    const uint32_t sbase = smem_u32(sm);
    const __half* gA = g_Ah + (size_t)mbase * 2048;
    const __half* gB = g_Wh + (size_t)nbase * 2048;

    auto load_stage = [&](int it, int s) {
        const int k0 = it * 64;
        const uint32_t sA = sbase + s * STAGE_BYTES2;
        const uint32_t sB = sA + TILE_BYTES2;
        #pragma unroll
        for (int l = 0; l < 4; l++) {
            int q = tid + 256 * l;
            int r = q >> 3, c = q & 7;
            CP_ASYNC16(sA + r * ROWB + c * 16,
                       (const char*)(gA + (size_t)r * 2048 + k0 + c * 8));
            CP_ASYNC16(sB + r * ROWB + c * 16,
                       (const char*)(gB + (size_t)r * 2048 + k0 + c * 8));
        }
        CP_COMMIT();
    };

    float c[4][4][4];
    #pragma unroll
    for (int i = 0; i < 4; i++)
        #pragma unroll
        for (int j = 0; j < 4; j++)
            #pragma unroll
            for (int k = 0; k < 4; k++) c[i][j][k] = 0.f;

    load_stage(0, 0);
    load_stage(1, 1);

    const int arow = (lane & 15);
    const int abyt = (lane >> 4) << 4;
    const int brow = (lane & 7) + ((lane >> 4) << 3);
    const int bbyt = ((lane >> 3) & 1) << 4;

    for (int it = 0; it < NITER; ++it) {
        const int s = it % NSTAGE;
        if (it < NITER - 1) { CP_WAIT1(); } else { CP_WAIT0(); }
        __syncthreads();
        if (it + 2 < NITER) load_stage(it + 2, (it + 2) % NSTAGE);

        const uint32_t sA = sbase + s * STAGE_BYTES2;
        const uint32_t sB = sA + TILE_BYTES2;

        #pragma unroll
        for (int ks = 0; ks < 4; ks++) {
            uint32_t af[4][4], bfr[2][4];
            #pragma unroll
            for (int fm = 0; fm < 4; fm++) {
                uint32_t ad = sA + (wm * 64 + fm * 16 + arow) * ROWB + ks * 32 + abyt;
                LDSM_X4(af[fm][0], af[fm][1], af[fm][2], af[fm][3], ad);
            }
            #pragma unroll
            for (int f2 = 0; f2 < 2; f2++) {
                uint32_t bd = sB + (wn * 32 + f2 * 16 + brow) * ROWB + ks * 32 + bbyt;
                LDSM_X4(bfr[f2][0], bfr[f2][1], bfr[f2][2], bfr[f2][3], bd);
            }
            #pragma unroll
            for (int fm = 0; fm < 4; fm++)
                #pragma unroll
                for (int fn = 0; fn < 4; fn++) {
                    uint32_t b0 = bfr[fn >> 1][(fn & 1) * 2 + 0];
                    uint32_t b1 = bfr[fn >> 1][(fn & 1) * 2 + 1];
                    mma_fp16(c[fm][fn][0], c[fm][fn][1], c[fm][fn][2], c[fm][fn][3],
                             af[fm][0], af[fm][1], af[fm][2], af[fm][3], b0, b1);
                }
        }
    }

    const bool side = (nbase >= 1024);
    const float* bsrc = side ? bq : bk;
    __half* outh = side ? g_Qh : g_Kh;
    const int colb = side ? (nbase - 1024) : nbase;

    #pragma unroll
    for (int fm = 0; fm < 4; fm++) {
        int row = mbase + wm * 64 + fm * 16 + g;
        #pragma unroll
        for (int fn = 0; fn < 4; fn++) {
            int col = colb + wn * 32 + fn * 8 + t4 * 2;
            float b0 = bsrc[col], b1 = bsrc[col + 1];
            *(__half2*)(outh + (size_t)row * 1024 + col) =
                __floats2half2_rn(c[fm][fn][0] + b0, c[fm][fn][1] + b1);
            *(__half2*)(outh + (size_t)(row + 8) * 1024 + col) =
                __floats2half2_rn(c[fm][fn][2] + b0, c[fm][fn][3] + b1);
        }
    }
}

// ---------------------------------------------------------------------------
// Gate via fp16 mma, hi/lo split. Rows in (b, j, i)-PERMUTED order so the
// output scatter g_GW[b][h][j][i] keeps contiguous 16B runs per 8 lanes.
// Staging loop FULLY UNROLLED with hoisted index math -> MLP ~16.
// Each block: 256 rows; one block handles rows within a single (b) slab and
// a fixed j-range? No -- GATE_ROWS=256 < 10000, so bb/jj constant-ish per
// block except at slab borders; computed per-iteration but with cheap math.
// ---------------------------------------------------------------------------
#define GATE_ROWS 256
#define GATE_RH   72
#define ROWB_GATE 144

__global__ __launch_bounds__(256, 2)
void gate_kernel(const float* __restrict__ gf,
                 const float* __restrict__ Wg, const float* __restrict__ bg)
{
    __shared__ __align__(16) __half sGh[GATE_ROWS * GATE_RH];
    __shared__ __align__(16) __half sGl[GATE_ROWS * GATE_RH];

    const int tid = threadIdx.x, lane = tid & 31, wid = tid >> 5;
    const int g = lane >> 2, t4 = lane & 3;
    const int rowbase = blockIdx.x * GATE_ROWS;

    // stage permuted g rows fp32 -> (hi, lo) fp16; 16 fully-unrolled chains
    {
        const int r0 = tid >> 4;          // base row for this thread (l=0)
        const int c4 = (tid & 15) << 2;   // column (constant across l)
        #pragma unroll
        for (int l = 0; l < 16; l++) {
            int r  = r0 + l * 16;
            int rp = rowbase + r;
            int bb = rp / 10000;
            int remp = rp - bb * 10000;            // = j*100 + i
            int jj = remp / 100;
            int ii = remp - jj * 100;
            float4 x = *(const float4*)(gf + ((size_t)bb * 10000 + ii * 100 + jj) * 64 + c4);
            float xs[4] = {x.x, x.y, x.z, x.w};
            __half hi[4], lo[4];
            #pragma unroll
            for (int e = 0; e < 4; e++) {
                hi[e] = __float2half_rn(xs[e]);
                lo[e] = __float2half_rn(xs[e] - __half2float(hi[e]));
            }
            *(uint2*)(sGh + r * GATE_RH + c4) = *(uint2*)hi;
            *(uint2*)(sGl + r * GATE_RH + c4) = *(uint2*)lo;
        }
    }

    // B fragments (col-major B = Wg^T[n][k])
    uint32_t bh[4][2][2], bl[4][2][2];
    #pragma unroll
    for (int ks = 0; ks < 4; ks++)
        #pragma unroll
        for (int nt = 0; nt < 2; nt++) {
            int n = nt * 8 + g;
            #pragma unroll
            for (int rg = 0; rg < 2; rg++) {
                int k0 = ks * 16 + t4 * 2 + rg * 8;
                float w0 = Wg[k0 * 16 + n], w1 = Wg[(k0 + 1) * 16 + n];
                __half h0 = __float2half_rn(w0), h1 = __float2half_rn(w1);
                __half l0 = __float2half_rn(w0 - __half2float(h0));
                __half l1 = __float2half_rn(w1 - __half2float(h1));
                __half hh[2] = {h0, h1}, ll[2] = {l0, l1};
                bh[ks][nt][rg] = *(uint32_t*)hh;
                bl[ks][nt][rg] = *(uint32_t*)ll;
            }
        }
    __syncthreads();

    const uint32_t sGhb = smem_u32(sGh), sGlb = smem_u32(sGl);
    const int arow = lane & 15, abyt = (lane >> 4) << 4;
    const int wrow = wid * 32;

    #pragma unroll
    for (int mt = 0; mt < 2; mt++) {
        float c[2][4];
        #pragma unroll
        for (int nt = 0; nt < 2; nt++)
            #pragma unroll
            for (int k = 0; k < 4; k++) c[nt][k] = 0.f;

        #pragma unroll
        for (int ks = 0; ks < 4; ks++) {
            uint32_t ah[4], al[4];
            uint32_t base_off = (wrow + mt * 16 + arow) * ROWB_GATE + ks * 32 + abyt;
            LDSM_X4(ah[0], ah[1], ah[2], ah[3], sGhb + base_off);
            LDSM_X4(al[0], al[1], al[2], al[3], sGlb + base_off);
            #pragma unroll
            for (int nt = 0; nt < 2; nt++) {
                mma_fp16(c[nt][0], c[nt][1], c[nt][2], c[nt][3],
                         ah[0], ah[1], ah[2], ah[3], bh[ks][nt][0], bh[ks][nt][1]);
                mma_fp16(c[nt][0], c[nt][1], c[nt][2], c[nt][3],
                         ah[0], ah[1], ah[2], ah[3], bl[ks][nt][0], bl[ks][nt][1]);
                mma_fp16(c[nt][0], c[nt][1], c[nt][2], c[nt][3],
                         al[0], al[1], al[2], al[3], bh[ks][nt][0], bh[ks][nt][1]);
            }
        }

        #pragma unroll
        for (int nt = 0; nt < 2; nt++) {
            int h0 = nt * 8 + t4 * 2;
            float bb0 = bg[h0], bb1 = bg[h0 + 1];
            #pragma unroll
            for (int p = 0; p < 2; p++) {
                int row = rowbase + wrow + mt * 16 + g + p * 8;   // = r'
                int bidx = row / 10000;
                int rem  = row - bidx * 10000;                    // = j*100+i
                __half* dst = g_GW + (size_t)bidx * 160000 + rem;
                float v0 = fmaxf(c[nt][p * 2 + 0] + bb0, 1e-6f) * GW_SCALE;
                float v1 = fmaxf(c[nt][p * 2 + 1] + bb1, 1e-6f) * GW_SCALE;
                dst[(size_t)h0 * 10000]       = __float2half_rn(v0);
                dst[(size_t)(h0 + 1) * 10000] = __float2half_rn(v1);
            }
        }
    }
}

// ---------------------------------------------------------------------------
// Attention per (b,h). 512 threads (16 warps, 4x4 grid), 2 CTAs/SM.
// V read from g_Ah (fp16). SMEM total 110096 bytes (layout per R10).
// ---------------------------------------------------------------------------
#define ATTN_SMEM_BYTES 110096

__global__ __launch_bounds__(512, 2)
void attn_kernel(const float* __restrict__ wsp, const float* __restrict__ bsp,
                 float* __restrict__ out)
{
    extern __shared__ __align__(16) char smc[];
    __half* sKh  = (__half*)(smc);
    __half* sQh  = (__half*)(smc + 18432);
    __half* sPT  = (__half*)(smc);                 // overlays K/Q after phase 1
    float*  sS   = (float*) (smc + 36864);
    __half* sVT  = (__half*)(smc + 78864);
    float*  sInv = (float*) (smc + 109584);

    const int h = blockIdx.x, b = blockIdx.y;
    const int tid = threadIdx.x;
    const int wid = tid >> 5, lane = tid & 31;
    const int wm = wid & 3, wn = wid >> 2;            // 4 x 4 warp grid
    const int g = lane >> 2, t4 = lane & 3;

    // ---- initial loads: K, Q (+pad) AND V (overlaps phase-1 compute) ----
    const __half* Kg = g_Kh + (size_t)(b * 100) * 1024 + h * 64;
    const __half* Qg = g_Qh + (size_t)(b * 100) * 1024 + h * 64;
    for (int v = tid; v < 800; v += 512) {            // 100 rows x 8 x 16B
        int r = v >> 3, c = v & 7;
        *(uint4*)(sKh + r * 72 + c * 8) = *(const uint4*)(Kg + (size_t)r * 1024 + c * 8);
        *(uint4*)(sQh + r * 72 + c * 8) = *(const uint4*)(Qg + (size_t)r * 1024 + c * 8);
    }
    for (int v = tid; v < 224; v += 512) {            // zero K/Q pad rows 100..127
        int r = 100 + (v >> 3), c = v & 7;
        *(uint4*)(sKh + r * 72 + c * 8) = make_uint4(0, 0, 0, 0);
        *(uint4*)(sQh + r * 72 + c * 8) = make_uint4(0, 0, 0, 0);
    }
    // V from g_Ah (fp16): 100 rows x 16 chunks of 8 halves (16B)
    const __half* Vg = g_Ah + (size_t)(b * 100) * 2048 + h * 128;
    for (int v = tid; v < 1600; v += 512) {
        int i = v >> 4, c = v & 15;
        *(uint4*)(sVT + i * 136 + c * 8) = *(const uint4*)(Vg + (size_t)i * 2048 + c * 8);
    }
    for (int v = tid; v < 204; v += 512)              // zero sVT rows i=100..111
        ((uint4*)((char*)sVT + 27200))[v] = make_uint4(0, 0, 0, 0);
    __syncthreads();

    const int arow = lane & 15, abyt = (lane >> 4) << 4;
    const int brow = (lane & 7) + ((lane >> 4) << 3), bbyt = ((lane >> 3) & 1) << 4;

    // ---- Phase 1: S = K.Q^T * 0.125 (warp tile 32m x 32n) ----
    {
        float c1[2][4][4];
        #pragma unroll
        for (int i = 0; i < 2; i++)
            #pragma unroll
            for (int j = 0; j < 4; j++)
                #pragma unroll
                for (int k = 0; k < 4; k++) c1[i][j][k] = 0.f;
        const uint32_t sKb = smem_u32(sKh), sQb = smem_u32(sQh);
        #pragma unroll
        for (int ks = 0; ks < 4; ks++) {
            uint32_t af[2][4], bfr[2][4];
            #pragma unroll
            for (int fm = 0; fm < 2; fm++) {
                uint32_t ad = sKb + (wm * 32 + fm * 16 + arow) * 144 + ks * 32 + abyt;
                LDSM_X4(af[fm][0], af[fm][1], af[fm][2], af[fm][3], ad);
            }
            #pragma unroll
            for (int f2 = 0; f2 < 2; f2++) {
                uint32_t bd = sQb + (wn * 32 + f2 * 16 + brow) * 144 + ks * 32 + bbyt;
                LDSM_X4(bfr[f2][0], bfr[f2][1], bfr[f2][2], bfr[f2][3], bd);
            }
            #pragma unroll
            for (int fm = 0; fm < 2; fm++)
                #pragma unroll
                for (int fn = 0; fn < 4; fn++)
                    mma_fp16(c1[fm][fn][0], c1[fm][fn][1], c1[fm][fn][2], c1[fm][fn][3],
                             af[fm][0], af[fm][1], af[fm][2], af[fm][3],
                             bfr[fn >> 1][(fn & 1) * 2], bfr[fn >> 1][(fn & 1) * 2 + 1]);
        }
        #pragma unroll
        for (int fm = 0; fm < 2; fm++) {
            int i0 = wm * 32 + fm * 16 + g;
            #pragma unroll
            for (int fn = 0; fn < 4; fn++) {
                int j0 = wn * 32 + fn * 8 + t4 * 2;
                if (j0 < 100) {
                    if (i0 < 100) {
                        sS[i0 * 105 + j0]     = c1[fm][fn][0] * 0.125f;
                        sS[i0 * 105 + j0 + 1] = c1[fm][fn][1] * 0.125f;
                    }
                    if (i0 + 8 < 100) {
                        sS[(i0 + 8) * 105 + j0]     = c1[fm][fn][2] * 0.125f;
                        sS[(i0 + 8) * 105 + j0 + 1] = c1[fm][fn][3] * 0.125f;
                    }
                }
            }
        }
    }
    __syncthreads();   // K/Q dead from here; region0 becomes sPT

    // ---- zero sPT pad rows j=100..127 (240B each) ----
    for (int v = tid; v < 420; v += 512)
        ((uint4*)((char*)sPT + 24000))[v] = make_uint4(0, 0, 0, 0);

    // ---- softmax (warp per column j), unrolled 4 i-slots ----
    const __half* GWT = g_GW + (size_t)(b * 16 + h) * 10000;   // [j][i]
    for (int j = wid; j < 100; j += 16) {
        float g0 = __half2float(GWT[j * 100 + lane]);
        float g1 = __half2float(GWT[j * 100 + lane + 32]);
        float g2 = __half2float(GWT[j * 100 + lane + 64]);
        float g3 = (lane < 4) ? __half2float(GWT[j * 100 + lane + 96]) : 0.f;

        float s0 = sS[lane * 105 + j];
        float s1 = sS[(lane + 32) * 105 + j];
        float s2 = sS[(lane + 64) * 105 + j];
        float s3 = (lane < 4) ? sS[(lane + 96) * 105 + j] : -1e30f;

        float m = fmaxf(fmaxf(s0, s1), fmaxf(s2, s3));
        #pragma unroll
        for (int o = 16; o; o >>= 1) m = fmaxf(m, __shfl_xor_sync(~0u, m, o));

        float e0 = g0 * __expf(s0 - m);
        float e1 = g1 * __expf(s1 - m);
        float e2 = g2 * __expf(s2 - m);
        float e3 = (lane < 4) ? g3 * __expf(s3 - m) : 0.f;

        float s  = e0 + e1 + e2 + e3;
        float mx = fmaxf(fmaxf(e0, e1), fmaxf(e2, e3));
        #pragma unroll
        for (int o = 16; o; o >>= 1) {
            s  += __shfl_xor_sync(~0u, s, o);
            mx  = fmaxf(mx, __shfl_xor_sync(~0u, mx, o));
        }
        const float inv_mx = 1.f / mx;
        sPT[j * 120 + lane]      = __float2half_rn(e0 * inv_mx);
        sPT[j * 120 + lane + 32] = __float2half_rn(e1 * inv_mx);
        sPT[j * 120 + lane + 64] = __float2half_rn(e2 * inv_mx);
        if (lane < 4)  sPT[j * 120 + lane + 96]  = __float2half_rn(e3 * inv_mx);
        if (lane < 12) sPT[j * 120 + 100 + lane] = __float2half_rn(0.f);
        if (lane == 0) sInv[j] = mx / s;              // exact renormalization
    }
    __syncthreads();

    // ---- Phase 2: out = P^T · V  (m=j, k=i 112, n=d 128; warp 32j x 32d) ----
    {
        float c2[2][4][4];
        #pragma unroll
        for (int i = 0; i < 2; i++)
            #pragma unroll
            for (int j = 0; j < 4; j++)
                #pragma unroll
                for (int k = 0; k < 4; k++) c2[i][j][k] = 0.f;
        const uint32_t sPb = smem_u32(sPT), sVb = smem_u32(sVT);
        #pragma unroll
        for (int ks = 0; ks < 7; ks++) {
            uint32_t af[2][4], bfr[2][4];
            #pragma unroll
            for (int fm = 0; fm < 2; fm++) {
                uint32_t ad = sPb + (wm * 32 + fm * 16 + arow) * 240 + ks * 32 + abyt;
                LDSM_X4(af[fm][0], af[fm][1], af[fm][2], af[fm][3], ad);
            }
            #pragma unroll
            for (int f2 = 0; f2 < 2; f2++) {
                uint32_t bd = sVb + (ks * 16 + (lane & 15)) * 272
                            + (wn * 32 + f2 * 16) * 2 + ((lane >> 4) << 4);
                LDSM_X4_TRANS(bfr[f2][0], bfr[f2][1], bfr[f2][2], bfr[f2][3], bd);
            }
            #pragma unroll
            for (int fm = 0; fm < 2; fm++)
                #pragma unroll
                for (int fn = 0; fn < 4; fn++)
                    mma_fp16(c2[fm][fn][0], c2[fm][fn][1], c2[fm][fn][2], c2[fm][fn][3],
                             af[fm][0], af[fm][1], af[fm][2], af[fm][3],
                             bfr[fn >> 1][(fn & 1) * 2], bfr[fn >> 1][(fn & 1) * 2 + 1]);
        }
        const float wsc = *wsp, bsc = *bsp;
        #pragma unroll
        for (int fm = 0; fm < 2; fm++) {
            int j0 = wm * 32 + fm * 16 + g;
            #pragma unroll
            for (int fn = 0; fn < 4; fn++) {
                int d0 = wn * 32 + fn * 8 + t4 * 2;
                if (j0 < 100) {
                    float sc = sInv[j0] * wsc;
                    *(float2*)(out + (size_t)(b * 100 + j0) * 2048 + h * 128 + d0) =
                        make_float2(c2[fm][fn][0] * sc + bsc, c2[fm][fn][1] * sc + bsc);
                }
                if (j0 + 8 < 100) {
                    float sc = sInv[j0 + 8] * wsc;
                    *(float2*)(out + (size_t)(b * 100 + j0 + 8) * 2048 + h * 128 + d0) =
                        make_float2(c2[fm][fn][2] * sc + bsc, c2[fm][fn][3] * sc + bsc);
                }
            }
        }
    }
}

// ---------------------------------------------------------------------------
// Launch. Inputs: a_features, g_features, split, rel_pair_counts,
// W_g, b_g, W_K, b_K, W_Q, b_Q, w_s, b_s
// ---------------------------------------------------------------------------
extern "C" void kernel_launch(void* const* d_in, const int* in_sizes, int n_in,
                              void* d_out, int out_size)
{
    (void)in_sizes; (void)n_in; (void)out_size;
    const float* a  = (const float*)d_in[0];
    const float* gf = (const float*)d_in[1];
    const float* Wg = (const float*)d_in[4];
    const float* bg = (const float*)d_in[5];
    const float* Wk = (const float*)d_in[6];
    const float* bk = (const float*)d_in[7];
    const float* Wq = (const float*)d_in[8];
    const float* bq = (const float*)d_in[9];
    const float* ws = (const float*)d_in[10];
    const float* bs = (const float*)d_in[11];
    float* out = (float*)d_out;

    cudaFuncSetAttribute(gemm_kernel, cudaFuncAttributeMaxDynamicSharedMemorySize, GEMM_SMEM);
    cudaFuncSetAttribute(attn_kernel, cudaFuncAttributeMaxDynamicSharedMemorySize,
                         ATTN_SMEM_BYTES);

    prep_kernel<<<PREP_BLOCKS, 256>>>(a, Wk, Wq);
    gate_kernel<<<640000 / GATE_ROWS, 256>>>(gf, Wg, bg);
    gemm_kernel<<<dim3(16, 50), 256, GEMM_SMEM>>>(bk, bq);
    attn_kernel<<<dim3(16, 64), 512, ATTN_SMEM_BYTES>>>(ws, bs, out);
}

// round 13
// speedup vs baseline: 3.6442x; 1.0064x over previous
#include <cuda_runtime.h>
#include <cuda_fp16.h>
#include <cstdint>

// Problem constants
#define BB   64
#define NN   100
#define DD   2048
#define NRH  16
#define PP   (BB*NN)        // 6400

#define GW_SCALE 1024.0f    // uniform gate scale; cancels exactly in softmax ratio

// ---------------------------------------------------------------------------
// Scratch (__device__ globals; no allocations allowed)
// ---------------------------------------------------------------------------
__device__ __half g_Ah[PP * 2048];               // 26.2 MB  A in fp16 (also V source)
__device__ __half g_Wh[2048 * 2048];             // 8.4 MB   W^T fused [n][k] (Wk|Wq)
__device__ __half g_Kh[PP * 1024];               // 13.1 MB  K fp16
__device__ __half g_Qh[PP * 1024];               // 13.1 MB  Q fp16
__device__ __half g_GW[BB * NRH * NN * NN];      // 20.5 MB  gw*1024 fp16, [b][h][j][i]

__device__ __forceinline__ uint32_t smem_u32(const void* p) {
    uint32_t a;
    asm("{ .reg .u64 t; cvta.to.shared.u64 t, %1; cvt.u32.u64 %0, t; }" : "=r"(a) : "l"(p));
    return a;
}

#define CP_ASYNC16(dst, src) \
    asm volatile("cp.async.cg.shared.global [%0], [%1], 16;" :: "r"(dst), "l"(src) : "memory")
#define CP_COMMIT() asm volatile("cp.async.commit_group;" ::: "memory")
#define CP_WAIT1()  asm volatile("cp.async.wait_group 1;" ::: "memory")
#define CP_WAIT0()  asm volatile("cp.async.wait_group 0;" ::: "memory")

// Non-volatile: barriers fence smem ordering; lets ptxas interleave with mma.
#define LDSM_X4(r0, r1, r2, r3, addr) \
    asm("ldmatrix.sync.aligned.m8n8.x4.shared.b16 {%0,%1,%2,%3}, [%4];" \
        : "=r"(r0), "=r"(r1), "=r"(r2), "=r"(r3) : "r"(addr))

#define LDSM_X4_TRANS(r0, r1, r2, r3, addr) \
    asm("ldmatrix.sync.aligned.m8n8.x4.trans.shared.b16 {%0,%1,%2,%3}, [%4];" \
        : "=r"(r0), "=r"(r1), "=r"(r2), "=r"(r3) : "r"(addr))

__device__ __forceinline__ void mma_fp16(float& c0, float& c1, float& c2, float& c3,
                                         uint32_t a0, uint32_t a1, uint32_t a2, uint32_t a3,
                                         uint32_t b0, uint32_t b1)
{
    asm("mma.sync.aligned.m16n8k16.row.col.f32.f16.f16.f32 "
        "{%0,%1,%2,%3}, {%4,%5,%6,%7}, {%8,%9}, {%0,%1,%2,%3};"
        : "+f"(c0), "+f"(c1), "+f"(c2), "+f"(c3)
        : "r"(a0), "r"(a1), "r"(a2), "r"(a3), "r"(b0), "r"(b1));
}

// ---------------------------------------------------------------------------
// Fused prep: blocks [0, 12800) = A fp32->fp16; [12800, 16896) = W transpose.
// ---------------------------------------------------------------------------
#define PREP_A_BLOCKS 12800
#define PREP_BLOCKS   (PREP_A_BLOCKS + 4096)

__global__ __launch_bounds__(256)
void prep_kernel(const float* __restrict__ A,
                 const float* __restrict__ Wk, const float* __restrict__ Wq)
{
    __shared__ float t[32][33];
    if (blockIdx.x < PREP_A_BLOCKS) {
        int id = blockIdx.x * 256 + threadIdx.x;   // one float4 each
        float4 v = *(const float4*)(A + (size_t)id * 4);
        __half h[4] = {__float2half_rn(v.x), __float2half_rn(v.y),
                       __float2half_rn(v.z), __float2half_rn(v.w)};
        *(uint2*)(g_Ah + (size_t)id * 4) = *(uint2*)h;
    } else {
        int bid = blockIdx.x - PREP_A_BLOCKS;      // 4096 = 64 x 64
        const int k0 = (bid & 63) * 32, n0 = (bid >> 6) * 32;
        const float* src = (n0 < 1024) ? Wk : Wq;
        const int nc0 = (n0 < 1024) ? n0 : n0 - 1024;
        const int tx = threadIdx.x & 31, ty = threadIdx.x >> 5;
        for (int r = ty; r < 32; r += 8)
            t[r][tx] = src[(k0 + r) * 1024 + nc0 + tx];
        __syncthreads();
        for (int r = ty; r < 32; r += 8)
            g_Wh[(size_t)(n0 + r) * 2048 + k0 + tx] = __float2half_rn(t[tx][r]);
    }
}

// ---------------------------------------------------------------------------
// fp16 GEMM: C[6400 x 2048] = Ah @ Wh^T (+bias)  ->  g_Kh | g_Qh (fp16)
// Tiles BM=128 BN=128 BK=64; 3-stage cp.async; 8 warps (2m x 4n), warp 64x32.
// ---------------------------------------------------------------------------
#define ROWH 72
#define ROWB 144
#define TILE_BYTES2 (128 * ROWB)                   // 18432 per operand
#define STAGE_BYTES2 (2 * TILE_BYTES2)             // 36864
#define NSTAGE 3
#define NITER  32                                  // 2048 / 64
#define GEMM_SMEM (NSTAGE * STAGE_BYTES2)          // 110592 B

__global__ __launch_bounds__(256, 2)
void gemm_kernel(const float* __restrict__ bk, const float* __restrict__ bq)
{
    extern __shared__ __align__(16) __half sm[];

    const int tid  = threadIdx.x;
    const int wid  = tid >> 5, lane = tid & 31;
    const int wm   = wid & 1,  wn   = wid >> 1;       // 2 x 4 warp grid
    const int g    = lane >> 2, t4  = lane & 3;
    const int mbase = blockIdx.y * 128;
    const int nbase = blockIdx.x * 128;

    const uint32_t sbase = smem_u32(sm);
    const __half* gA = g_Ah + (size_t)mbase * 2048;
    const __half* gB = g_Wh + (size_t)nbase * 2048;

    auto load_stage = [&](int it, int s) {
        const int k0 = it * 64;
        const uint32_t sA = sbase + s * STAGE_BYTES2;
        const uint32_t sB = sA + TILE_BYTES2;
        #pragma unroll
        for (int l = 0; l < 4; l++) {
            int q = tid + 256 * l;
            int r = q >> 3, c = q & 7;
            CP_ASYNC16(sA + r * ROWB + c * 16,
                       (const char*)(gA + (size_t)r * 2048 + k0 + c * 8));
            CP_ASYNC16(sB + r * ROWB + c * 16,
                       (const char*)(gB + (size_t)r * 2048 + k0 + c * 8));
        }
        CP_COMMIT();
    };

    float c[4][4][4];
    #pragma unroll
    for (int i = 0; i < 4; i++)
        #pragma unroll
        for (int j = 0; j < 4; j++)
            #pragma unroll
            for (int k = 0; k < 4; k++) c[i][j][k] = 0.f;

    load_stage(0, 0);
    load_stage(1, 1);

    const int arow = (lane & 15);
    const int abyt = (lane >> 4) << 4;
    const int brow = (lane & 7) + ((lane >> 4) << 3);
    const int bbyt = ((lane >> 3) & 1) << 4;

    for (int it = 0; it < NITER; ++it) {
        const int s = it % NSTAGE;
        if (it < NITER - 1) { CP_WAIT1(); } else { CP_WAIT0(); }
        __syncthreads();
        if (it + 2 < NITER) load_stage(it + 2, (it + 2) % NSTAGE);

        const uint32_t sA = sbase + s * STAGE_BYTES2;
        const uint32_t sB = sA + TILE_BYTES2;

        #pragma unroll
        for (int ks = 0; ks < 4; ks++) {
            uint32_t af[4][4], bfr[2][4];
            #pragma unroll
            for (int fm = 0; fm < 4; fm++) {
                uint32_t ad = sA + (wm * 64 + fm * 16 + arow) * ROWB + ks * 32 + abyt;
                LDSM_X4(af[fm][0], af[fm][1], af[fm][2], af[fm][3], ad);
            }
            #pragma unroll
            for (int f2 = 0; f2 < 2; f2++) {
                uint32_t bd = sB + (wn * 32 + f2 * 16 + brow) * ROWB + ks * 32 + bbyt;
                LDSM_X4(bfr[f2][0], bfr[f2][1], bfr[f2][2], bfr[f2][3], bd);
            }
            #pragma unroll
            for (int fm = 0; fm < 4; fm++)
                #pragma unroll
                for (int fn = 0; fn < 4; fn++) {
                    uint32_t b0 = bfr[fn >> 1][(fn & 1) * 2 + 0];
                    uint32_t b1 = bfr[fn >> 1][(fn & 1) * 2 + 1];
                    mma_fp16(c[fm][fn][0], c[fm][fn][1], c[fm][fn][2], c[fm][fn][3],
                             af[fm][0], af[fm][1], af[fm][2], af[fm][3], b0, b1);
                }
        }
    }

    const bool side = (nbase >= 1024);
    const float* bsrc = side ? bq : bk;
    __half* outh = side ? g_Qh : g_Kh;
    const int colb = side ? (nbase - 1024) : nbase;

    #pragma unroll
    for (int fm = 0; fm < 4; fm++) {
        int row = mbase + wm * 64 + fm * 16 + g;
        #pragma unroll
        for (int fn = 0; fn < 4; fn++) {
            int col = colb + wn * 32 + fn * 8 + t4 * 2;
            float b0 = bsrc[col], b1 = bsrc[col + 1];
            *(__half2*)(outh + (size_t)row * 1024 + col) =
                __floats2half2_rn(c[fm][fn][0] + b0, c[fm][fn][1] + b1);
            *(__half2*)(outh + (size_t)(row + 8) * 1024 + col) =
                __floats2half2_rn(c[fm][fn][2] + b0, c[fm][fn][3] + b1);
        }
    }
}

// ---------------------------------------------------------------------------
// Gate via fp16 mma, hi/lo split. Rows in (b, j, i)-PERMUTED order so the
// output scatter g_GW[b][h][j][i] keeps contiguous 16B runs per 8 lanes.
// Staging loop fully unrolled (MLP ~16).
// ---------------------------------------------------------------------------
#define GATE_ROWS 256
#define GATE_RH   72
#define ROWB_GATE 144

__global__ __launch_bounds__(256, 2)
void gate_kernel(const float* __restrict__ gf,
                 const float* __restrict__ Wg, const float* __restrict__ bg)
{
    __shared__ __align__(16) __half sGh[GATE_ROWS * GATE_RH];
    __shared__ __align__(16) __half sGl[GATE_ROWS * GATE_RH];

    const int tid = threadIdx.x, lane = tid & 31, wid = tid >> 5;
    const int g = lane >> 2, t4 = lane & 3;
    const int rowbase = blockIdx.x * GATE_ROWS;

    {
        const int r0 = tid >> 4;
        const int c4 = (tid & 15) << 2;
        #pragma unroll
        for (int l = 0; l < 16; l++) {
            int r  = r0 + l * 16;
            int rp = rowbase + r;
            int bb = rp / 10000;
            int remp = rp - bb * 10000;            // = j*100 + i
            int jj = remp / 100;
            int ii = remp - jj * 100;
            float4 x = *(const float4*)(gf + ((size_t)bb * 10000 + ii * 100 + jj) * 64 + c4);
            float xs[4] = {x.x, x.y, x.z, x.w};
            __half hi[4], lo[4];
            #pragma unroll
            for (int e = 0; e < 4; e++) {
                hi[e] = __float2half_rn(xs[e]);
                lo[e] = __float2half_rn(xs[e] - __half2float(hi[e]));
            }
            *(uint2*)(sGh + r * GATE_RH + c4) = *(uint2*)hi;
            *(uint2*)(sGl + r * GATE_RH + c4) = *(uint2*)lo;
        }
    }

    uint32_t bh[4][2][2], bl[4][2][2];
    #pragma unroll
    for (int ks = 0; ks < 4; ks++)
        #pragma unroll
        for (int nt = 0; nt < 2; nt++) {
            int n = nt * 8 + g;
            #pragma unroll
            for (int rg = 0; rg < 2; rg++) {
                int k0 = ks * 16 + t4 * 2 + rg * 8;
                float w0 = Wg[k0 * 16 + n], w1 = Wg[(k0 + 1) * 16 + n];
                __half h0 = __float2half_rn(w0), h1 = __float2half_rn(w1);
                __half l0 = __float2half_rn(w0 - __half2float(h0));
                __half l1 = __float2half_rn(w1 - __half2float(h1));
                __half hh[2] = {h0, h1}, ll[2] = {l0, l1};
                bh[ks][nt][rg] = *(uint32_t*)hh;
                bl[ks][nt][rg] = *(uint32_t*)ll;
            }
        }
    __syncthreads();

    const uint32_t sGhb = smem_u32(sGh), sGlb = smem_u32(sGl);
    const int arow = lane & 15, abyt = (lane >> 4) << 4;
    const int wrow = wid * 32;

    #pragma unroll
    for (int mt = 0; mt < 2; mt++) {
        float c[2][4];
        #pragma unroll
        for (int nt = 0; nt < 2; nt++)
            #pragma unroll
            for (int k = 0; k < 4; k++) c[nt][k] = 0.f;

        #pragma unroll
        for (int ks = 0; ks < 4; ks++) {
            uint32_t ah[4], al[4];
            uint32_t base_off = (wrow + mt * 16 + arow) * ROWB_GATE + ks * 32 + abyt;
            LDSM_X4(ah[0], ah[1], ah[2], ah[3], sGhb + base_off);
            LDSM_X4(al[0], al[1], al[2], al[3], sGlb + base_off);
            #pragma unroll
            for (int nt = 0; nt < 2; nt++) {
                mma_fp16(c[nt][0], c[nt][1], c[nt][2], c[nt][3],
                         ah[0], ah[1], ah[2], ah[3], bh[ks][nt][0], bh[ks][nt][1]);
                mma_fp16(c[nt][0], c[nt][1], c[nt][2], c[nt][3],
                         ah[0], ah[1], ah[2], ah[3], bl[ks][nt][0], bl[ks][nt][1]);
                mma_fp16(c[nt][0], c[nt][1], c[nt][2], c[nt][3],
                         al[0], al[1], al[2], al[3], bh[ks][nt][0], bh[ks][nt][1]);
            }
        }

        #pragma unroll
        for (int nt = 0; nt < 2; nt++) {
            int h0 = nt * 8 + t4 * 2;
            float bb0 = bg[h0], bb1 = bg[h0 + 1];
            #pragma unroll
            for (int p = 0; p < 2; p++) {
                int row = rowbase + wrow + mt * 16 + g + p * 8;   // = r'
                int bidx = row / 10000;
                int rem  = row - bidx * 10000;                    // = j*100+i
                __half* dst = g_GW + (size_t)bidx * 160000 + rem;
                float v0 = fmaxf(c[nt][p * 2 + 0] + bb0, 1e-6f) * GW_SCALE;
                float v1 = fmaxf(c[nt][p * 2 + 1] + bb1, 1e-6f) * GW_SCALE;
                dst[(size_t)h0 * 10000]       = __float2half_rn(v0);
                dst[(size_t)(h0 + 1) * 10000] = __float2half_rn(v1);
            }
        }
    }
}

// ---------------------------------------------------------------------------
// Attention per (b,h). 512 threads (16 warps, 4x4 grid), 2 CTAs/SM.
// V read from g_Ah (fp16). SMEM total 110096 bytes (layout per R10).
// ---------------------------------------------------------------------------
#define ATTN_SMEM_BYTES 110096

__global__ __launch_bounds__(512, 2)
void attn_kernel(const float* __restrict__ wsp, const float* __restrict__ bsp,
                 float* __restrict__ out)
{
    extern __shared__ __align__(16) char smc[];
    __half* sKh  = (__half*)(smc);
    __half* sQh  = (__half*)(smc + 18432);
    __half* sPT  = (__half*)(smc);                 // overlays K/Q after phase 1
    float*  sS   = (float*) (smc + 36864);
    __half* sVT  = (__half*)(smc + 78864);
    float*  sInv = (float*) (smc + 109584);

    const int h = blockIdx.x, b = blockIdx.y;
    const int tid = threadIdx.x;
    const int wid = tid >> 5, lane = tid & 31;
    const int wm = wid & 3, wn = wid >> 2;            // 4 x 4 warp grid
    const int g = lane >> 2, t4 = lane & 3;

    // ---- initial loads: K, Q (+pad) AND V (overlaps phase-1 compute) ----
    const __half* Kg = g_Kh + (size_t)(b * 100) * 1024 + h * 64;
    const __half* Qg = g_Qh + (size_t)(b * 100) * 1024 + h * 64;
    for (int v = tid; v < 800; v += 512) {            // 100 rows x 8 x 16B
        int r = v >> 3, c = v & 7;
        *(uint4*)(sKh + r * 72 + c * 8) = *(const uint4*)(Kg + (size_t)r * 1024 + c * 8);
        *(uint4*)(sQh + r * 72 + c * 8) = *(const uint4*)(Qg + (size_t)r * 1024 + c * 8);
    }
    for (int v = tid; v < 224; v += 512) {            // zero K/Q pad rows 100..127
        int r = 100 + (v >> 3), c = v & 7;
        *(uint4*)(sKh + r * 72 + c * 8) = make_uint4(0, 0, 0, 0);
        *(uint4*)(sQh + r * 72 + c * 8) = make_uint4(0, 0, 0, 0);
    }
    // V from g_Ah (fp16): 100 rows x 16 chunks of 8 halves (16B)
    const __half* Vg = g_Ah + (size_t)(b * 100) * 2048 + h * 128;
    for (int v = tid; v < 1600; v += 512) {
        int i = v >> 4, c = v & 15;
        *(uint4*)(sVT + i * 136 + c * 8) = *(const uint4*)(Vg + (size_t)i * 2048 + c * 8);
    }
    for (int v = tid; v < 204; v += 512)              // zero sVT rows i=100..111
        ((uint4*)((char*)sVT + 27200))[v] = make_uint4(0, 0, 0, 0);
    __syncthreads();

    const int arow = lane & 15, abyt = (lane >> 4) << 4;
    const int brow = (lane & 7) + ((lane >> 4) << 3), bbyt = ((lane >> 3) & 1) << 4;

    // ---- Phase 1: S = K.Q^T * 0.125 (warp tile 32m x 32n) ----
    {
        float c1[2][4][4];
        #pragma unroll
        for (int i = 0; i < 2; i++)
            #pragma unroll
            for (int j = 0; j < 4; j++)
                #pragma unroll
                for (int k = 0; k < 4; k++) c1[i][j][k] = 0.f;
        const uint32_t sKb = smem_u32(sKh), sQb = smem_u32(sQh);
        #pragma unroll
        for (int ks = 0; ks < 4; ks++) {
            uint32_t af[2][4], bfr[2][4];
            #pragma unroll
            for (int fm = 0; fm < 2; fm++) {
                uint32_t ad = sKb + (wm * 32 + fm * 16 + arow) * 144 + ks * 32 + abyt;
                LDSM_X4(af[fm][0], af[fm][1], af[fm][2], af[fm][3], ad);
            }
            #pragma unroll
            for (int f2 = 0; f2 < 2; f2++) {
                uint32_t bd = sQb + (wn * 32 + f2 * 16 + brow) * 144 + ks * 32 + bbyt;
                LDSM_X4(bfr[f2][0], bfr[f2][1], bfr[f2][2], bfr[f2][3], bd);
            }
            #pragma unroll
            for (int fm = 0; fm < 2; fm++)
                #pragma unroll
                for (int fn = 0; fn < 4; fn++)
                    mma_fp16(c1[fm][fn][0], c1[fm][fn][1], c1[fm][fn][2], c1[fm][fn][3],
                             af[fm][0], af[fm][1], af[fm][2], af[fm][3],
                             bfr[fn >> 1][(fn & 1) * 2], bfr[fn >> 1][(fn & 1) * 2 + 1]);
        }
        #pragma unroll
        for (int fm = 0; fm < 2; fm++) {
            int i0 = wm * 32 + fm * 16 + g;
            #pragma unroll
            for (int fn = 0; fn < 4; fn++) {
                int j0 = wn * 32 + fn * 8 + t4 * 2;
                if (j0 < 100) {
                    if (i0 < 100) {
                        sS[i0 * 105 + j0]     = c1[fm][fn][0] * 0.125f;
                        sS[i0 * 105 + j0 + 1] = c1[fm][fn][1] * 0.125f;
                    }
                    if (i0 + 8 < 100) {
                        sS[(i0 + 8) * 105 + j0]     = c1[fm][fn][2] * 0.125f;
                        sS[(i0 + 8) * 105 + j0 + 1] = c1[fm][fn][3] * 0.125f;
                    }
                }
            }
        }
    }
    __syncthreads();   // K/Q dead from here; region0 becomes sPT

    // ---- zero sPT pad rows j=100..127 (240B each) ----
    for (int v = tid; v < 420; v += 512)
        ((uint4*)((char*)sPT + 24000))[v] = make_uint4(0, 0, 0, 0);

    // ---- softmax (warp per column j), unrolled 4 i-slots ----
    const __half* GWT = g_GW + (size_t)(b * 16 + h) * 10000;   // [j][i]
    for (int j = wid; j < 100; j += 16) {
        float g0 = __half2float(GWT[j * 100 + lane]);
        float g1 = __half2float(GWT[j * 100 + lane + 32]);
        float g2 = __half2float(GWT[j * 100 + lane + 64]);
        float g3 = (lane < 4) ? __half2float(GWT[j * 100 + lane + 96]) : 0.f;

        float s0 = sS[lane * 105 + j];
        float s1 = sS[(lane + 32) * 105 + j];
        float s2 = sS[(lane + 64) * 105 + j];
        float s3 = (lane < 4) ? sS[(lane + 96) * 105 + j] : -1e30f;

        float m = fmaxf(fmaxf(s0, s1), fmaxf(s2, s3));
        #pragma unroll
        for (int o = 16; o; o >>= 1) m = fmaxf(m, __shfl_xor_sync(~0u, m, o));

        float e0 = g0 * __expf(s0 - m);
        float e1 = g1 * __expf(s1 - m);
        float e2 = g2 * __expf(s2 - m);
        float e3 = (lane < 4) ? g3 * __expf(s3 - m) : 0.f;

        float s  = e0 + e1 + e2 + e3;
        float mx = fmaxf(fmaxf(e0, e1), fmaxf(e2, e3));
        #pragma unroll
        for (int o = 16; o; o >>= 1) {
            s  += __shfl_xor_sync(~0u, s, o);
            mx  = fmaxf(mx, __shfl_xor_sync(~0u, mx, o));
        }
        const float inv_mx = 1.f / mx;
        sPT[j * 120 + lane]      = __float2half_rn(e0 * inv_mx);
        sPT[j * 120 + lane + 32] = __float2half_rn(e1 * inv_mx);
        sPT[j * 120 + lane + 64] = __float2half_rn(e2 * inv_mx);
        if (lane < 4)  sPT[j * 120 + lane + 96]  = __float2half_rn(e3 * inv_mx);
        if (lane < 12) sPT[j * 120 + 100 + lane] = __float2half_rn(0.f);
        if (lane == 0) sInv[j] = mx / s;              // exact renormalization
    }
    __syncthreads();

    // ---- Phase 2: out = P^T · V  (m=j, k=i 112, n=d 128; warp 32j x 32d) ----
    {
        float c2[2][4][4];
        #pragma unroll
        for (int i = 0; i < 2; i++)
            #pragma unroll
            for (int j = 0; j < 4; j++)
                #pragma unroll
                for (int k = 0; k < 4; k++) c2[i][j][k] = 0.f;
        const uint32_t sPb = smem_u32(sPT), sVb = smem_u32(sVT);
        #pragma unroll
        for (int ks = 0; ks < 7; ks++) {
            uint32_t af[2][4], bfr[2][4];
            #pragma unroll
            for (int fm = 0; fm < 2; fm++) {
                uint32_t ad = sPb + (wm * 32 + fm * 16 + arow) * 240 + ks * 32 + abyt;
                LDSM_X4(af[fm][0], af[fm][1], af[fm][2], af[fm][3], ad);
            }
            #pragma unroll
            for (int f2 = 0; f2 < 2; f2++) {
                uint32_t bd = sVb + (ks * 16 + (lane & 15)) * 272
                            + (wn * 32 + f2 * 16) * 2 + ((lane >> 4) << 4);
                LDSM_X4_TRANS(bfr[f2][0], bfr[f2][1], bfr[f2][2], bfr[f2][3], bd);
            }
            #pragma unroll
            for (int fm = 0; fm < 2; fm++)
                #pragma unroll
                for (int fn = 0; fn < 4; fn++)
                    mma_fp16(c2[fm][fn][0], c2[fm][fn][1], c2[fm][fn][2], c2[fm][fn][3],
                             af[fm][0], af[fm][1], af[fm][2], af[fm][3],
                             bfr[fn >> 1][(fn & 1) * 2], bfr[fn >> 1][(fn & 1) * 2 + 1]);
        }
        const float wsc = *wsp, bsc = *bsp;
        #pragma unroll
        for (int fm = 0; fm < 2; fm++) {
            int j0 = wm * 32 + fm * 16 + g;
            #pragma unroll
            for (int fn = 0; fn < 4; fn++) {
                int d0 = wn * 32 + fn * 8 + t4 * 2;
                if (j0 < 100) {
                    float sc = sInv[j0] * wsc;
                    *(float2*)(out + (size_t)(b * 100 + j0) * 2048 + h * 128 + d0) =
                        make_float2(c2[fm][fn][0] * sc + bsc, c2[fm][fn][1] * sc + bsc);
                }
                if (j0 + 8 < 100) {
                    float sc = sInv[j0 + 8] * wsc;
                    *(float2*)(out + (size_t)(b * 100 + j0 + 8) * 2048 + h * 128 + d0) =
                        make_float2(c2[fm][fn][2] * sc + bsc, c2[fm][fn][3] * sc + bsc);
                }
            }
        }
    }
}

// ---------------------------------------------------------------------------
// Launch. DAG: { prep || gate } -> gemm -> attn, via stream-forked capture.
// prep (18 regs, 4KB smem) and gate (74KB smem) co-reside on SMs; both are
// DRAM-bound and data-independent -> true overlap. Stream/event create+destroy
// are host ops (not captured) so graph replay carries zero extra cost.
// Inputs: a_features, g_features, split, rel_pair_counts,
// W_g, b_g, W_K, b_K, W_Q, b_Q, w_s, b_s
// ---------------------------------------------------------------------------
extern "C" void kernel_launch(void* const* d_in, const int* in_sizes, int n_in,
                              void* d_out, int out_size)
{
    (void)in_sizes; (void)n_in; (void)out_size;
    const float* a  = (const float*)d_in[0];
    const float* gf = (const float*)d_in[1];
    const float* Wg = (const float*)d_in[4];
    const float* bg = (const float*)d_in[5];
    const float* Wk = (const float*)d_in[6];
    const float* bk = (const float*)d_in[7];
    const float* Wq = (const float*)d_in[8];
    const float* bq = (const float*)d_in[9];
    const float* ws = (const float*)d_in[10];
    const float* bs = (const float*)d_in[11];
    float* out = (float*)d_out;

    cudaFuncSetAttribute(gemm_kernel, cudaFuncAttributeMaxDynamicSharedMemorySize, GEMM_SMEM);
    cudaFuncSetAttribute(attn_kernel, cudaFuncAttributeMaxDynamicSharedMemorySize,
                         ATTN_SMEM_BYTES);

    cudaStream_t s2;
    cudaStreamCreateWithFlags(&s2, cudaStreamNonBlocking);
    cudaEvent_t evFork, evJoin;
    cudaEventCreateWithFlags(&evFork, cudaEventDisableTiming);
    cudaEventCreateWithFlags(&evJoin, cudaEventDisableTiming);

    // fork: s2 branches off the (possibly captured) default stream
    cudaEventRecord(evFork, 0);
    cudaStreamWaitEvent(s2, evFork, 0);

    prep_kernel<<<PREP_BLOCKS, 256>>>(a, Wk, Wq);                   // default stream
    gate_kernel<<<640000 / GATE_ROWS, 256, 0, s2>>>(gf, Wg, bg);    // parallel branch

    // join: default stream waits for gate before attn (gemm doesn't need gate,
    // but joining before gemm keeps the DAG simple; gate << gemm in duration)
    cudaEventRecord(evJoin, s2);
    cudaStreamWaitEvent(0, evJoin, 0);

    gemm_kernel<<<dim3(16, 50), 256, GEMM_SMEM>>>(bk, bq);
    attn_kernel<<<dim3(16, 64), 512, ATTN_SMEM_BYTES>>>(ws, bs, out);

    cudaStreamDestroy(s2);
    cudaEventDestroy(evFork);
    cudaEventDestroy(evJoin);
}

// round 14
// speedup vs baseline: 3.6702x; 1.0071x over previous
#include <cuda_runtime.h>
#include <cuda_fp16.h>
#include <cstdint>

// Problem constants
#define BB   64
#define NN   100
#define DD   2048
#define NRH  16
#define PP   (BB*NN)        // 6400

#define GW_SCALE 1024.0f    // uniform gate scale; cancels exactly in softmax ratio

// ---------------------------------------------------------------------------
// Scratch (__device__ globals; no allocations allowed)
// ---------------------------------------------------------------------------
__device__ __half g_Ah[PP * 2048];               // 26.2 MB  A in fp16 (also V source)
__device__ __half g_Wh[2048 * 2048];             // 8.4 MB   W^T fused [n][k] (Wk|Wq)
__device__ __half g_Kh[PP * 1024];               // 13.1 MB  K fp16
__device__ __half g_Qh[PP * 1024];               // 13.1 MB  Q fp16
__device__ __half g_GW[BB * NRH * NN * NN];      // 20.5 MB  gw*1024 fp16, [b][h][j][i]

__device__ __forceinline__ uint32_t smem_u32(const void* p) {
    uint32_t a;
    asm("{ .reg .u64 t; cvta.to.shared.u64 t, %1; cvt.u32.u64 %0, t; }" : "=r"(a) : "l"(p));
    return a;
}

#define CP_ASYNC16(dst, src) \
    asm volatile("cp.async.cg.shared.global [%0], [%1], 16;" :: "r"(dst), "l"(src) : "memory")
#define CP_COMMIT() asm volatile("cp.async.commit_group;" ::: "memory")
#define CP_WAIT1()  asm volatile("cp.async.wait_group 1;" ::: "memory")
#define CP_WAIT0()  asm volatile("cp.async.wait_group 0;" ::: "memory")

// Non-volatile: barriers fence smem ordering; lets ptxas interleave with mma.
#define LDSM_X4(r0, r1, r2, r3, addr) \
    asm("ldmatrix.sync.aligned.m8n8.x4.shared.b16 {%0,%1,%2,%3}, [%4];" \
        : "=r"(r0), "=r"(r1), "=r"(r2), "=r"(r3) : "r"(addr))

#define LDSM_X4_TRANS(r0, r1, r2, r3, addr) \
    asm("ldmatrix.sync.aligned.m8n8.x4.trans.shared.b16 {%0,%1,%2,%3}, [%4];" \
        : "=r"(r0), "=r"(r1), "=r"(r2), "=r"(r3) : "r"(addr))

__device__ __forceinline__ void mma_fp16(float& c0, float& c1, float& c2, float& c3,
                                         uint32_t a0, uint32_t a1, uint32_t a2, uint32_t a3,
                                         uint32_t b0, uint32_t b1)
{
    asm("mma.sync.aligned.m16n8k16.row.col.f32.f16.f16.f32 "
        "{%0,%1,%2,%3}, {%4,%5,%6,%7}, {%8,%9}, {%0,%1,%2,%3};"
        : "+f"(c0), "+f"(c1), "+f"(c2), "+f"(c3)
        : "r"(a0), "r"(a1), "r"(a2), "r"(a3), "r"(b0), "r"(b1));
}

// ---------------------------------------------------------------------------
// Fused prep: blocks [0, 12800) = A fp32->fp16; [12800, 16896) = W transpose.
// ---------------------------------------------------------------------------
#define PREP_A_BLOCKS 12800
#define PREP_BLOCKS   (PREP_A_BLOCKS + 4096)

__global__ __launch_bounds__(256)
void prep_kernel(const float* __restrict__ A,
                 const float* __restrict__ Wk, const float* __restrict__ Wq)
{
    __shared__ float t[32][33];
    if (blockIdx.x < PREP_A_BLOCKS) {
        int id = blockIdx.x * 256 + threadIdx.x;   // one float4 each
        float4 v = *(const float4*)(A + (size_t)id * 4);
        __half h[4] = {__float2half_rn(v.x), __float2half_rn(v.y),
                       __float2half_rn(v.z), __float2half_rn(v.w)};
        *(uint2*)(g_Ah + (size_t)id * 4) = *(uint2*)h;
    } else {
        int bid = blockIdx.x - PREP_A_BLOCKS;      // 4096 = 64 x 64
        const int k0 = (bid & 63) * 32, n0 = (bid >> 6) * 32;
        const float* src = (n0 < 1024) ? Wk : Wq;
        const int nc0 = (n0 < 1024) ? n0 : n0 - 1024;
        const int tx = threadIdx.x & 31, ty = threadIdx.x >> 5;
        for (int r = ty; r < 32; r += 8)
            t[r][tx] = src[(k0 + r) * 1024 + nc0 + tx];
        __syncthreads();
        for (int r = ty; r < 32; r += 8)
            g_Wh[(size_t)(n0 + r) * 2048 + k0 + tx] = __float2half_rn(t[tx][r]);
    }
}

// ---------------------------------------------------------------------------
// fp16 GEMM: C[6400 x 2048] = Ah @ Wh^T (+bias)  ->  g_Kh | g_Qh (fp16)
// Tiles BM=128 BN=128 BK=64; 3-stage cp.async; 8 warps (2m x 4n), warp 64x32.
// ---------------------------------------------------------------------------
#define ROWH 72
#define ROWB 144
#define TILE_BYTES2 (128 * ROWB)                   // 18432 per operand
#define STAGE_BYTES2 (2 * TILE_BYTES2)             // 36864
#define NSTAGE 3
#define NITER  32                                  // 2048 / 64
#define GEMM_SMEM (NSTAGE * STAGE_BYTES2)          // 110592 B

__global__ __launch_bounds__(256, 2)
void gemm_kernel(const float* __restrict__ bk, const float* __restrict__ bq)
{
    extern __shared__ __align__(16) __half sm[];

    const int tid  = threadIdx.x;
    const int wid  = tid >> 5, lane = tid & 31;
    const int wm   = wid & 1,  wn   = wid >> 1;       // 2 x 4 warp grid
    const int g    = lane >> 2, t4  = lane & 3;
    const int mbase = blockIdx.y * 128;
    const int nbase = blockIdx.x * 128;

    const uint32_t sbase = smem_u32(sm);
    const __half* gA = g_Ah + (size_t)mbase * 2048;
    const __half* gB = g_Wh + (size_t)nbase * 2048;

    auto load_stage = [&](int it, int s) {
        const int k0 = it * 64;
        const uint32_t sA = sbase + s * STAGE_BYTES2;
        const uint32_t sB = sA + TILE_BYTES2;
        #pragma unroll
        for (int l = 0; l < 4; l++) {
            int q = tid + 256 * l;
            int r = q >> 3, c = q & 7;
            CP_ASYNC16(sA + r * ROWB + c * 16,
                       (const char*)(gA + (size_t)r * 2048 + k0 + c * 8));
            CP_ASYNC16(sB + r * ROWB + c * 16,
                       (const char*)(gB + (size_t)r * 2048 + k0 + c * 8));
        }
        CP_COMMIT();
    };

    float c[4][4][4];
    #pragma unroll
    for (int i = 0; i < 4; i++)
        #pragma unroll
        for (int j = 0; j < 4; j++)
            #pragma unroll
            for (int k = 0; k < 4; k++) c[i][j][k] = 0.f;

    load_stage(0, 0);
    load_stage(1, 1);

    const int arow = (lane & 15);
    const int abyt = (lane >> 4) << 4;
    const int brow = (lane & 7) + ((lane >> 4) << 3);
    const int bbyt = ((lane >> 3) & 1) << 4;

    for (int it = 0; it < NITER; ++it) {
        const int s = it % NSTAGE;
        if (it < NITER - 1) { CP_WAIT1(); } else { CP_WAIT0(); }
        __syncthreads();
        if (it + 2 < NITER) load_stage(it + 2, (it + 2) % NSTAGE);

        const uint32_t sA = sbase + s * STAGE_BYTES2;
        const uint32_t sB = sA + TILE_BYTES2;

        #pragma unroll
        for (int ks = 0; ks < 4; ks++) {
            uint32_t af[4][4], bfr[2][4];
            #pragma unroll
            for (int fm = 0; fm < 4; fm++) {
                uint32_t ad = sA + (wm * 64 + fm * 16 + arow) * ROWB + ks * 32 + abyt;
                LDSM_X4(af[fm][0], af[fm][1], af[fm][2], af[fm][3], ad);
            }
            #pragma unroll
            for (int f2 = 0; f2 < 2; f2++) {
                uint32_t bd = sB + (wn * 32 + f2 * 16 + brow) * ROWB + ks * 32 + bbyt;
                LDSM_X4(bfr[f2][0], bfr[f2][1], bfr[f2][2], bfr[f2][3], bd);
            }
            #pragma unroll
            for (int fm = 0; fm < 4; fm++)
                #pragma unroll
                for (int fn = 0; fn < 4; fn++) {
                    uint32_t b0 = bfr[fn >> 1][(fn & 1) * 2 + 0];
                    uint32_t b1 = bfr[fn >> 1][(fn & 1) * 2 + 1];
                    mma_fp16(c[fm][fn][0], c[fm][fn][1], c[fm][fn][2], c[fm][fn][3],
                             af[fm][0], af[fm][1], af[fm][2], af[fm][3], b0, b1);
                }
        }
    }

    const bool side = (nbase >= 1024);
    const float* bsrc = side ? bq : bk;
    __half* outh = side ? g_Qh : g_Kh;
    const int colb = side ? (nbase - 1024) : nbase;

    #pragma unroll
    for (int fm = 0; fm < 4; fm++) {
        int row = mbase + wm * 64 + fm * 16 + g;
        #pragma unroll
        for (int fn = 0; fn < 4; fn++) {
            int col = colb + wn * 32 + fn * 8 + t4 * 2;
            float b0 = bsrc[col], b1 = bsrc[col + 1];
            *(__half2*)(outh + (size_t)row * 1024 + col) =
                __floats2half2_rn(c[fm][fn][0] + b0, c[fm][fn][1] + b1);
            *(__half2*)(outh + (size_t)(row + 8) * 1024 + col) =
                __floats2half2_rn(c[fm][fn][2] + b0, c[fm][fn][3] + b1);
        }
    }
}

// ---------------------------------------------------------------------------
// Gate via fp16 mma, hi/lo split. Rows in (b, j, i)-PERMUTED order so the
// output scatter g_GW[b][h][j][i] keeps contiguous 16B runs per 8 lanes.
// Fully independent of prep/gemm -> runs on a low-priority stream, filling
// gemm's idle DRAM bandwidth and tail-wave SM slack.
// ---------------------------------------------------------------------------
#define GATE_ROWS 256
#define GATE_RH   72
#define ROWB_GATE 144

__global__ __launch_bounds__(256, 2)
void gate_kernel(const float* __restrict__ gf,
                 const float* __restrict__ Wg, const float* __restrict__ bg)
{
    __shared__ __align__(16) __half sGh[GATE_ROWS * GATE_RH];
    __shared__ __align__(16) __half sGl[GATE_ROWS * GATE_RH];

    const int tid = threadIdx.x, lane = tid & 31, wid = tid >> 5;
    const int g = lane >> 2, t4 = lane & 3;
    const int rowbase = blockIdx.x * GATE_ROWS;

    {
        const int r0 = tid >> 4;
        const int c4 = (tid & 15) << 2;
        #pragma unroll
        for (int l = 0; l < 16; l++) {
            int r  = r0 + l * 16;
            int rp = rowbase + r;
            int bb = rp / 10000;
            int remp = rp - bb * 10000;            // = j*100 + i
            int jj = remp / 100;
            int ii = remp - jj * 100;
            float4 x = *(const float4*)(gf + ((size_t)bb * 10000 + ii * 100 + jj) * 64 + c4);
            float xs[4] = {x.x, x.y, x.z, x.w};
            __half hi[4], lo[4];
            #pragma unroll
            for (int e = 0; e < 4; e++) {
                hi[e] = __float2half_rn(xs[e]);
                lo[e] = __float2half_rn(xs[e] - __half2float(hi[e]));
            }
            *(uint2*)(sGh + r * GATE_RH + c4) = *(uint2*)hi;
            *(uint2*)(sGl + r * GATE_RH + c4) = *(uint2*)lo;
        }
    }

    uint32_t bh[4][2][2], bl[4][2][2];
    #pragma unroll
    for (int ks = 0; ks < 4; ks++)
        #pragma unroll
        for (int nt = 0; nt < 2; nt++) {
            int n = nt * 8 + g;
            #pragma unroll
            for (int rg = 0; rg < 2; rg++) {
                int k0 = ks * 16 + t4 * 2 + rg * 8;
                float w0 = Wg[k0 * 16 + n], w1 = Wg[(k0 + 1) * 16 + n];
                __half h0 = __float2half_rn(w0), h1 = __float2half_rn(w1);
                __half l0 = __float2half_rn(w0 - __half2float(h0));
                __half l1 = __float2half_rn(w1 - __half2float(h1));
                __half hh[2] = {h0, h1}, ll[2] = {l0, l1};
                bh[ks][nt][rg] = *(uint32_t*)hh;
                bl[ks][nt][rg] = *(uint32_t*)ll;
            }
        }
    __syncthreads();

    const uint32_t sGhb = smem_u32(sGh), sGlb = smem_u32(sGl);
    const int arow = lane & 15, abyt = (lane >> 4) << 4;
    const int wrow = wid * 32;

    #pragma unroll
    for (int mt = 0; mt < 2; mt++) {
        float c[2][4];
        #pragma unroll
        for (int nt = 0; nt < 2; nt++)
            #pragma unroll
            for (int k = 0; k < 4; k++) c[nt][k] = 0.f;

        #pragma unroll
        for (int ks = 0; ks < 4; ks++) {
            uint32_t ah[4], al[4];
            uint32_t base_off = (wrow + mt * 16 + arow) * ROWB_GATE + ks * 32 + abyt;
            LDSM_X4(ah[0], ah[1], ah[2], ah[3], sGhb + base_off);
            LDSM_X4(al[0], al[1], al[2], al[3], sGlb + base_off);
            #pragma unroll
            for (int nt = 0; nt < 2; nt++) {
                mma_fp16(c[nt][0], c[nt][1], c[nt][2], c[nt][3],
                         ah[0], ah[1], ah[2], ah[3], bh[ks][nt][0], bh[ks][nt][1]);
                mma_fp16(c[nt][0], c[nt][1], c[nt][2], c[nt][3],
                         ah[0], ah[1], ah[2], ah[3], bl[ks][nt][0], bl[ks][nt][1]);
                mma_fp16(c[nt][0], c[nt][1], c[nt][2], c[nt][3],
                         al[0], al[1], al[2], al[3], bh[ks][nt][0], bh[ks][nt][1]);
            }
        }

        #pragma unroll
        for (int nt = 0; nt < 2; nt++) {
            int h0 = nt * 8 + t4 * 2;
            float bb0 = bg[h0], bb1 = bg[h0 + 1];
            #pragma unroll
            for (int p = 0; p < 2; p++) {
                int row = rowbase + wrow + mt * 16 + g + p * 8;   // = r'
                int bidx = row / 10000;
                int rem  = row - bidx * 10000;                    // = j*100+i
                __half* dst = g_GW + (size_t)bidx * 160000 + rem;
                float v0 = fmaxf(c[nt][p * 2 + 0] + bb0, 1e-6f) * GW_SCALE;
                float v1 = fmaxf(c[nt][p * 2 + 1] + bb1, 1e-6f) * GW_SCALE;
                dst[(size_t)h0 * 10000]       = __float2half_rn(v0);
                dst[(size_t)(h0 + 1) * 10000] = __float2half_rn(v1);
            }
        }
    }
}

// ---------------------------------------------------------------------------
// Attention per (b,h). 512 threads (16 warps, 4x4 grid), 2 CTAs/SM.
// V read from g_Ah (fp16). SMEM total 110096 bytes (layout per R10).
// ---------------------------------------------------------------------------
#define ATTN_SMEM_BYTES 110096

__global__ __launch_bounds__(512, 2)
void attn_kernel(const float* __restrict__ wsp, const float* __restrict__ bsp,
                 float* __restrict__ out)
{
    extern __shared__ __align__(16) char smc[];
    __half* sKh  = (__half*)(smc);
    __half* sQh  = (__half*)(smc + 18432);
    __half* sPT  = (__half*)(smc);                 // overlays K/Q after phase 1
    float*  sS   = (float*) (smc + 36864);
    __half* sVT  = (__half*)(smc + 78864);
    float*  sInv = (float*) (smc + 109584);

    const int h = blockIdx.x, b = blockIdx.y;
    const int tid = threadIdx.x;
    const int wid = tid >> 5, lane = tid & 31;
    const int wm = wid & 3, wn = wid >> 2;            // 4 x 4 warp grid
    const int g = lane >> 2, t4 = lane & 3;

    // ---- initial loads: K, Q (+pad) AND V (overlaps phase-1 compute) ----
    const __half* Kg = g_Kh + (size_t)(b * 100) * 1024 + h * 64;
    const __half* Qg = g_Qh + (size_t)(b * 100) * 1024 + h * 64;
    for (int v = tid; v < 800; v += 512) {            // 100 rows x 8 x 16B
        int r = v >> 3, c = v & 7;
        *(uint4*)(sKh + r * 72 + c * 8) = *(const uint4*)(Kg + (size_t)r * 1024 + c * 8);
        *(uint4*)(sQh + r * 72 + c * 8) = *(const uint4*)(Qg + (size_t)r * 1024 + c * 8);
    }
    for (int v = tid; v < 224; v += 512) {            // zero K/Q pad rows 100..127
        int r = 100 + (v >> 3), c = v & 7;
        *(uint4*)(sKh + r * 72 + c * 8) = make_uint4(0, 0, 0, 0);
        *(uint4*)(sQh + r * 72 + c * 8) = make_uint4(0, 0, 0, 0);
    }
    // V from g_Ah (fp16): 100 rows x 16 chunks of 8 halves (16B)
    const __half* Vg = g_Ah + (size_t)(b * 100) * 2048 + h * 128;
    for (int v = tid; v < 1600; v += 512) {
        int i = v >> 4, c = v & 15;
        *(uint4*)(sVT + i * 136 + c * 8) = *(const uint4*)(Vg + (size_t)i * 2048 + c * 8);
    }
    for (int v = tid; v < 204; v += 512)              // zero sVT rows i=100..111
        ((uint4*)((char*)sVT + 27200))[v] = make_uint4(0, 0, 0, 0);
    __syncthreads();

    const int arow = lane & 15, abyt = (lane >> 4) << 4;
    const int brow = (lane & 7) + ((lane >> 4) << 3), bbyt = ((lane >> 3) & 1) << 4;

    // ---- Phase 1: S = K.Q^T * 0.125 (warp tile 32m x 32n) ----
    {
        float c1[2][4][4];
        #pragma unroll
        for (int i = 0; i < 2; i++)
            #pragma unroll
            for (int j = 0; j < 4; j++)
                #pragma unroll
                for (int k = 0; k < 4; k++) c1[i][j][k] = 0.f;
        const uint32_t sKb = smem_u32(sKh), sQb = smem_u32(sQh);
        #pragma unroll
        for (int ks = 0; ks < 4; ks++) {
            uint32_t af[2][4], bfr[2][4];
            #pragma unroll
            for (int fm = 0; fm < 2; fm++) {
                uint32_t ad = sKb + (wm * 32 + fm * 16 + arow) * 144 + ks * 32 + abyt;
                LDSM_X4(af[fm][0], af[fm][1], af[fm][2], af[fm][3], ad);
            }
            #pragma unroll
            for (int f2 = 0; f2 < 2; f2++) {
                uint32_t bd = sQb + (wn * 32 + f2 * 16 + brow) * 144 + ks * 32 + bbyt;
                LDSM_X4(bfr[f2][0], bfr[f2][1], bfr[f2][2], bfr[f2][3], bd);
            }
            #pragma unroll
            for (int fm = 0; fm < 2; fm++)
                #pragma unroll
                for (int fn = 0; fn < 4; fn++)
                    mma_fp16(c1[fm][fn][0], c1[fm][fn][1], c1[fm][fn][2], c1[fm][fn][3],
                             af[fm][0], af[fm][1], af[fm][2], af[fm][3],
                             bfr[fn >> 1][(fn & 1) * 2], bfr[fn >> 1][(fn & 1) * 2 + 1]);
        }
        #pragma unroll
        for (int fm = 0; fm < 2; fm++) {
            int i0 = wm * 32 + fm * 16 + g;
            #pragma unroll
            for (int fn = 0; fn < 4; fn++) {
                int j0 = wn * 32 + fn * 8 + t4 * 2;
                if (j0 < 100) {
                    if (i0 < 100) {
                        sS[i0 * 105 + j0]     = c1[fm][fn][0] * 0.125f;
                        sS[i0 * 105 + j0 + 1] = c1[fm][fn][1] * 0.125f;
                    }
                    if (i0 + 8 < 100) {
                        sS[(i0 + 8) * 105 + j0]     = c1[fm][fn][2] * 0.125f;
                        sS[(i0 + 8) * 105 + j0 + 1] = c1[fm][fn][3] * 0.125f;
                    }
                }
            }
        }
    }
    __syncthreads();   // K/Q dead from here; region0 becomes sPT

    // ---- zero sPT pad rows j=100..127 (240B each) ----
    for (int v = tid; v < 420; v += 512)
        ((uint4*)((char*)sPT + 24000))[v] = make_uint4(0, 0, 0, 0);

    // ---- softmax (warp per column j), unrolled 4 i-slots ----
    const __half* GWT = g_GW + (size_t)(b * 16 + h) * 10000;   // [j][i]
    for (int j = wid; j < 100; j += 16) {
        float g0 = __half2float(GWT[j * 100 + lane]);
        float g1 = __half2float(GWT[j * 100 + lane + 32]);
        float g2 = __half2float(GWT[j * 100 + lane + 64]);
        float g3 = (lane < 4) ? __half2float(GWT[j * 100 + lane + 96]) : 0.f;

        float s0 = sS[lane * 105 + j];
        float s1 = sS[(lane + 32) * 105 + j];
        float s2 = sS[(lane + 64) * 105 + j];
        float s3 = (lane < 4) ? sS[(lane + 96) * 105 + j] : -1e30f;

        float m = fmaxf(fmaxf(s0, s1), fmaxf(s2, s3));
        #pragma unroll
        for (int o = 16; o; o >>= 1) m = fmaxf(m, __shfl_xor_sync(~0u, m, o));

        float e0 = g0 * __expf(s0 - m);
        float e1 = g1 * __expf(s1 - m);
        float e2 = g2 * __expf(s2 - m);
        float e3 = (lane < 4) ? g3 * __expf(s3 - m) : 0.f;

        float s  = e0 + e1 + e2 + e3;
        float mx = fmaxf(fmaxf(e0, e1), fmaxf(e2, e3));
        #pragma unroll
        for (int o = 16; o; o >>= 1) {
            s  += __shfl_xor_sync(~0u, s, o);
            mx  = fmaxf(mx, __shfl_xor_sync(~0u, mx, o));
        }
        const float inv_mx = 1.f / mx;
        sPT[j * 120 + lane]      = __float2half_rn(e0 * inv_mx);
        sPT[j * 120 + lane + 32] = __float2half_rn(e1 * inv_mx);
        sPT[j * 120 + lane + 64] = __float2half_rn(e2 * inv_mx);
        if (lane < 4)  sPT[j * 120 + lane + 96]  = __float2half_rn(e3 * inv_mx);
        if (lane < 12) sPT[j * 120 + 100 + lane] = __float2half_rn(0.f);
        if (lane == 0) sInv[j] = mx / s;              // exact renormalization
    }
    __syncthreads();

    // ---- Phase 2: out = P^T · V  (m=j, k=i 112, n=d 128; warp 32j x 32d) ----
    {
        float c2[2][4][4];
        #pragma unroll
        for (int i = 0; i < 2; i++)
            #pragma unroll
            for (int j = 0; j < 4; j++)
                #pragma unroll
                for (int k = 0; k < 4; k++) c2[i][j][k] = 0.f;
        const uint32_t sPb = smem_u32(sPT), sVb = smem_u32(sVT);
        #pragma unroll
        for (int ks = 0; ks < 7; ks++) {
            uint32_t af[2][4], bfr[2][4];
            #pragma unroll
            for (int fm = 0; fm < 2; fm++) {
                uint32_t ad = sPb + (wm * 32 + fm * 16 + arow) * 240 + ks * 32 + abyt;
                LDSM_X4(af[fm][0], af[fm][1], af[fm][2], af[fm][3], ad);
            }
            #pragma unroll
            for (int f2 = 0; f2 < 2; f2++) {
                uint32_t bd = sVb + (ks * 16 + (lane & 15)) * 272
                            + (wn * 32 + f2 * 16) * 2 + ((lane >> 4) << 4);
                LDSM_X4_TRANS(bfr[f2][0], bfr[f2][1], bfr[f2][2], bfr[f2][3], bd);
            }
            #pragma unroll
            for (int fm = 0; fm < 2; fm++)
                #pragma unroll
                for (int fn = 0; fn < 4; fn++)
                    mma_fp16(c2[fm][fn][0], c2[fm][fn][1], c2[fm][fn][2], c2[fm][fn][3],
                             af[fm][0], af[fm][1], af[fm][2], af[fm][3],
                             bfr[fn >> 1][(fn & 1) * 2], bfr[fn >> 1][(fn & 1) * 2 + 1]);
        }
        const float wsc = *wsp, bsc = *bsp;
        #pragma unroll
        for (int fm = 0; fm < 2; fm++) {
            int j0 = wm * 32 + fm * 16 + g;
            #pragma unroll
            for (int fn = 0; fn < 4; fn++) {
                int d0 = wn * 32 + fn * 8 + t4 * 2;
                if (j0 < 100) {
                    float sc = sInv[j0] * wsc;
                    *(float2*)(out + (size_t)(b * 100 + j0) * 2048 + h * 128 + d0) =
                        make_float2(c2[fm][fn][0] * sc + bsc, c2[fm][fn][1] * sc + bsc);
                }
                if (j0 + 8 < 100) {
                    float sc = sInv[j0 + 8] * wsc;
                    *(float2*)(out + (size_t)(b * 100 + j0 + 8) * 2048 + h * 128 + d0) =
                        make_float2(c2[fm][fn][2] * sc + bsc, c2[fm][fn][3] * sc + bsc);
                }
            }
        }
    }
}

// ---------------------------------------------------------------------------
// Launch. DAG: gate (low-priority, forked at t=0) || (prep -> gemm) -> attn.
// gemm is tensor-bound with DRAM at 2.7% -- gate's DRAM traffic and tail-wave
// SM usage hide under it. Low priority keeps gate from delaying prep/gemm CTAs.
// Inputs: a_features, g_features, split, rel_pair_counts,
// W_g, b_g, W_K, b_K, W_Q, b_Q, w_s, b_s
// ---------------------------------------------------------------------------
extern "C" void kernel_launch(void* const* d_in, const int* in_sizes, int n_in,
                              void* d_out, int out_size)
{
    (void)in_sizes; (void)n_in; (void)out_size;
    const float* a  = (const float*)d_in[0];
    const float* gf = (const float*)d_in[1];
    const float* Wg = (const float*)d_in[4];
    const float* bg = (const float*)d_in[5];
    const float* Wk = (const float*)d_in[6];
    const float* bk = (const float*)d_in[7];
    const float* Wq = (const float*)d_in[8];
    const float* bq = (const float*)d_in[9];
    const float* ws = (const float*)d_in[10];
    const float* bs = (const float*)d_in[11];
    float* out = (float*)d_out;

    cudaFuncSetAttribute(gemm_kernel, cudaFuncAttributeMaxDynamicSharedMemorySize, GEMM_SMEM);
    cudaFuncSetAttribute(attn_kernel, cudaFuncAttributeMaxDynamicSharedMemorySize,
                         ATTN_SMEM_BYTES);

    int prLow = 0, prHigh = 0;
    cudaDeviceGetStreamPriorityRange(&prLow, &prHigh);   // prLow = numerically lowest priority

    cudaStream_t s2;
    cudaStreamCreateWithPriority(&s2, cudaStreamNonBlocking, prLow);
    cudaEvent_t evFork, evJoin;
    cudaEventCreateWithFlags(&evFork, cudaEventDisableTiming);
    cudaEventCreateWithFlags(&evJoin, cudaEventDisableTiming);

    // fork: s2 branches off the capture stream
    cudaEventRecord(evFork, 0);
    cudaStreamWaitEvent(s2, evFork, 0);

    gate_kernel<<<640000 / GATE_ROWS, 256, 0, s2>>>(gf, Wg, bg);    // low-prio branch

    prep_kernel<<<PREP_BLOCKS, 256>>>(a, Wk, Wq);                   // critical path
    gemm_kernel<<<dim3(16, 50), 256, GEMM_SMEM>>>(bk, bq);

    // join: attn needs gate's output
    cudaEventRecord(evJoin, s2);
    cudaStreamWaitEvent(0, evJoin, 0);

    attn_kernel<<<dim3(16, 64), 512, ATTN_SMEM_BYTES>>>(ws, bs, out);

    cudaStreamDestroy(s2);
    cudaEventDestroy(evFork);
    cudaEventDestroy(evJoin);
}